// round 6
// baseline (speedup 1.0000x reference)
#include <cuda_runtime.h>
#include <cuda_bf16.h>
#include <cstdint>

// Problem constants
#define NN     50000
#define EE     800000
#define EP     (EE + NN)      // edges + self loops = 850000
#define FIN    128
#define HID    128
#define OUTF   128
#define HEADS  4

// ---------------------------------------------------------------------------
// Scratch (static device globals; no runtime allocation)
// ---------------------------------------------------------------------------
__device__ __align__(16) float g_xp[(size_t)NN * 512];   // GEMM output (max H*OUT=512)
__device__ __align__(16) float g_h [(size_t)NN * 128];   // layer activations
__device__ __align__(16) float g_ob[(size_t)NN * 128];   // pre-BN aggregation output
__device__ __align__(16) float g_as[NN * 4];             // a_src per (node, head)
__device__ __align__(16) float g_ad[NN * 4];             // a_dst per (node, head)
__device__ int g_rowptr[NN + 1];
__device__ int g_cursor[NN];
__device__ int g_deg[NN];
__device__ int g_csrc[EP];
__device__ int g_src[EP];
__device__ int g_dst[EP];
__device__ int g_is64;
__device__ float g_bnsum[128];
__device__ float g_bnsq[128];

__device__ __forceinline__ float lrelu(float x) { return x > 0.f ? x : 0.2f * x; }

// ---------------------------------------------------------------------------
// Edge-index dtype detection + decode.
// JAX without x64 silently emits int32 even though the reference says int64.
// Interpreting int32 pairs as int64 gives values >= 2^32 almost surely, so a
// 64-entry scan distinguishes the layouts with certainty.
// ---------------------------------------------------------------------------
__global__ void detect_kernel(const void* ei) {
    const long long* p = (const long long*)ei;   // 64*8 = 512B: safe either way
    int ok = 1;
    for (int j = 0; j < 64; j++) {
        long long v = p[j];
        if (v < 0 || v >= NN) { ok = 0; break; }
    }
    g_is64 = ok;
}

__global__ void decode_kernel(const void* ei) {
    int i = blockIdx.x * blockDim.x + threadIdx.x;
    if (i >= EP) return;
    int src, dst;
    if (i >= EE) {
        src = i - EE; dst = i - EE;               // self loops
    } else if (g_is64) {
        const long long* p = (const long long*)ei;
        src = (int)p[i]; dst = (int)p[EE + i];
    } else {
        const int* p = (const int*)ei;
        src = p[i]; dst = p[EE + i];
    }
    g_src[i] = src; g_dst[i] = dst;
    if (i < NN) g_deg[i] = 0;                    // fused zero_deg (NN < EP)
}

// ---------------------------------------------------------------------------
// CSR build: histogram -> exclusive scan -> scatter (by destination node)
// ---------------------------------------------------------------------------
__global__ void hist_kernel() {
    int i = blockIdx.x * blockDim.x + threadIdx.x;
    if (i >= EP) return;
    atomicAdd(&g_deg[g_dst[i]], 1);
}

__global__ void scan_kernel() {
    __shared__ int sh[1024];
    __shared__ int carry;
    if (threadIdx.x == 0) carry = 0;
    __syncthreads();
    for (int base = 0; base < NN; base += 1024) {
        int i = base + threadIdx.x;
        int v = (i < NN) ? g_deg[i] : 0;
        sh[threadIdx.x] = v;
        __syncthreads();
        #pragma unroll
        for (int off = 1; off < 1024; off <<= 1) {
            int t = (threadIdx.x >= off) ? sh[threadIdx.x - off] : 0;
            __syncthreads();
            sh[threadIdx.x] += t;
            __syncthreads();
        }
        if (i < NN) {
            g_rowptr[i] = carry + sh[threadIdx.x] - v;  // exclusive
            g_cursor[i] = carry + sh[threadIdx.x] - v;
        }
        __syncthreads();
        if (threadIdx.x == 0) carry += sh[1023];
        __syncthreads();
    }
    if (threadIdx.x == 0) g_rowptr[NN] = carry;
}

__global__ void scatter_kernel() {
    int i = blockIdx.x * blockDim.x + threadIdx.x;
    if (i >= EP) return;
    int pos = atomicAdd(&g_cursor[g_dst[i]], 1);
    g_csrc[pos] = g_src[i];
}

// ---------------------------------------------------------------------------
// SGEMM: Y[M, Nd] = X[M, 128] @ W[128, Nd], fp32, 128x128 tile, 8x8/thread
// ---------------------------------------------------------------------------
__global__ __launch_bounds__(256)
void sgemm_kernel(const float* __restrict__ X, const float* __restrict__ W,
                  float* __restrict__ Y, int M, int Nd) {
    __shared__ __align__(16) float As[16][128];
    __shared__ __align__(16) float Bs[16][128];
    const int bm = blockIdx.x * 128;
    const int bn = blockIdx.y * 128;
    const int tid = threadIdx.x;
    const int tx = tid & 15, ty = tid >> 4;

    float acc[8][8];
    #pragma unroll
    for (int i = 0; i < 8; i++)
        #pragma unroll
        for (int j = 0; j < 8; j++) acc[i][j] = 0.f;

    for (int kt = 0; kt < 8; kt++) {
        const int k0 = kt * 16;
        // A tile: 128 rows x 16 cols, stored transposed As[k][m]
        #pragma unroll
        for (int p = 0; p < 2; p++) {
            int r = (tid >> 2) + p * 64;
            int c = (tid & 3) * 4;
            int gr = bm + r;
            float4 v = make_float4(0.f, 0.f, 0.f, 0.f);
            if (gr < M) v = *(const float4*)(X + (size_t)gr * 128 + k0 + c);
            As[c + 0][r] = v.x; As[c + 1][r] = v.y;
            As[c + 2][r] = v.z; As[c + 3][r] = v.w;
        }
        // B tile: 16 rows x 128 cols
        #pragma unroll
        for (int p = 0; p < 2; p++) {
            int r = (tid >> 5) + p * 8;
            int c = (tid & 31) * 4;
            float4 v = *(const float4*)(W + (size_t)(k0 + r) * Nd + bn + c);
            *(float4*)&Bs[r][c] = v;
        }
        __syncthreads();
        #pragma unroll
        for (int k = 0; k < 16; k++) {
            float a[8], b[8];
            *(float4*)(a)     = *(const float4*)&As[k][ty * 8];
            *(float4*)(a + 4) = *(const float4*)&As[k][ty * 8 + 4];
            *(float4*)(b)     = *(const float4*)&Bs[k][tx * 8];
            *(float4*)(b + 4) = *(const float4*)&Bs[k][tx * 8 + 4];
            #pragma unroll
            for (int i = 0; i < 8; i++)
                #pragma unroll
                for (int j = 0; j < 8; j++) acc[i][j] += a[i] * b[j];
        }
        __syncthreads();
    }
    #pragma unroll
    for (int i = 0; i < 8; i++) {
        int gr = bm + ty * 8 + i;
        if (gr >= M) continue;
        *(float4*)(Y + (size_t)gr * Nd + bn + tx * 8)     = *(float4*)&acc[i][0];
        *(float4*)(Y + (size_t)gr * Nd + bn + tx * 8 + 4) = *(float4*)&acc[i][4];
    }
}

// ---------------------------------------------------------------------------
// Per-(node, head) attention dots: a_s = <xp[n,h,:], att_src[h,:]>, a_d likewise
// One warp per (n, h). C = per-head channels (32 or 128).
// ---------------------------------------------------------------------------
__global__ __launch_bounds__(256)
void att_kernel(const float* __restrict__ xp, const float* __restrict__ asw,
                const float* __restrict__ adw, int C) {
    int gw = (blockIdx.x * blockDim.x + threadIdx.x) >> 5;
    int lane = threadIdx.x & 31;
    if (gw >= NN * HEADS) return;
    int n = gw >> 2, h = gw & 3;
    const float* row = xp + (size_t)n * (HEADS * C) + h * C;
    float s = 0.f, d = 0.f;
    for (int t = lane; t < C; t += 32) {
        float v = row[t];
        s += v * asw[h * C + t];
        d += v * adw[h * C + t];
    }
    #pragma unroll
    for (int o = 16; o; o >>= 1) {
        s += __shfl_xor_sync(0xffffffffu, s, o);
        d += __shfl_xor_sync(0xffffffffu, d, o);
    }
    if (lane == 0) { g_as[n * 4 + h] = s; g_ad[n * 4 + h] = d; }
}

// ---------------------------------------------------------------------------
// Aggregation: per destination node (one warp): segment softmax in registers,
// then weighted gather-accumulate of xp[src]. MEAN=true averages heads.
// ---------------------------------------------------------------------------
template <bool MEAN>
__global__ __launch_bounds__(256)
void aggregate_kernel(const float* __restrict__ xp, const float* __restrict__ bias,
                      float* __restrict__ ob) {
    int n = (blockIdx.x * blockDim.x + threadIdx.x) >> 5;
    int lane = threadIdx.x & 31;
    if (n >= NN) return;
    const int rs = g_rowptr[n], re = g_rowptr[n + 1];
    const float4 adv = *(const float4*)(g_ad + 4 * n);

    // pass 1: per-head max of leaky_relu(a_s[src] + a_d[n])
    float m0 = -1e30f, m1 = -1e30f, m2 = -1e30f, m3 = -1e30f;
    for (int idx = rs + lane; idx < re; idx += 32) {
        int s = g_csrc[idx];
        float4 a = __ldg((const float4*)(g_as + 4 * s));
        m0 = fmaxf(m0, lrelu(a.x + adv.x));
        m1 = fmaxf(m1, lrelu(a.y + adv.y));
        m2 = fmaxf(m2, lrelu(a.z + adv.z));
        m3 = fmaxf(m3, lrelu(a.w + adv.w));
    }
    #pragma unroll
    for (int o = 16; o; o >>= 1) {
        m0 = fmaxf(m0, __shfl_xor_sync(0xffffffffu, m0, o));
        m1 = fmaxf(m1, __shfl_xor_sync(0xffffffffu, m1, o));
        m2 = fmaxf(m2, __shfl_xor_sync(0xffffffffu, m2, o));
        m3 = fmaxf(m3, __shfl_xor_sync(0xffffffffu, m3, o));
    }

    // pass 2: per-head sum of exp(e - m)
    float s0 = 0.f, s1 = 0.f, s2 = 0.f, s3 = 0.f;
    for (int idx = rs + lane; idx < re; idx += 32) {
        int s = g_csrc[idx];
        float4 a = __ldg((const float4*)(g_as + 4 * s));
        s0 += __expf(lrelu(a.x + adv.x) - m0);
        s1 += __expf(lrelu(a.y + adv.y) - m1);
        s2 += __expf(lrelu(a.z + adv.z) - m2);
        s3 += __expf(lrelu(a.w + adv.w) - m3);
    }
    #pragma unroll
    for (int o = 16; o; o >>= 1) {
        s0 += __shfl_xor_sync(0xffffffffu, s0, o);
        s1 += __shfl_xor_sync(0xffffffffu, s1, o);
        s2 += __shfl_xor_sync(0xffffffffu, s2, o);
        s3 += __shfl_xor_sync(0xffffffffu, s3, o);
    }
    const float i0 = 1.f / (s0 + 1e-16f), i1 = 1.f / (s1 + 1e-16f);
    const float i2 = 1.f / (s2 + 1e-16f), i3 = 1.f / (s3 + 1e-16f);

    // pass 3: weighted aggregation. Each lane owns output features [4*lane, 4*lane+4).
    float acc0 = 0.f, acc1 = 0.f, acc2 = 0.f, acc3 = 0.f;
    for (int idx = rs; idx < re; idx += 32) {
        int myi = idx + lane;
        int s = 0;
        float w0 = 0.f, w1 = 0.f, w2 = 0.f, w3 = 0.f;
        if (myi < re) {
            s = g_csrc[myi];
            float4 a = __ldg((const float4*)(g_as + 4 * s));
            w0 = __expf(lrelu(a.x + adv.x) - m0) * i0;
            w1 = __expf(lrelu(a.y + adv.y) - m1) * i1;
            w2 = __expf(lrelu(a.z + adv.z) - m2) * i2;
            w3 = __expf(lrelu(a.w + adv.w) - m3) * i3;
        }
        int cnt = min(32, re - idx);
        for (int j = 0; j < cnt; j++) {
            int sj   = __shfl_sync(0xffffffffu, s,  j);
            float b0 = __shfl_sync(0xffffffffu, w0, j);
            float b1 = __shfl_sync(0xffffffffu, w1, j);
            float b2 = __shfl_sync(0xffffffffu, w2, j);
            float b3 = __shfl_sync(0xffffffffu, w3, j);
            if (MEAN) {
                const float* base = xp + (size_t)sj * 512 + lane * 4;
                float4 v0 = __ldg((const float4*)(base));
                float4 v1 = __ldg((const float4*)(base + 128));
                float4 v2 = __ldg((const float4*)(base + 256));
                float4 v3 = __ldg((const float4*)(base + 384));
                acc0 += 0.25f * (b0 * v0.x + b1 * v1.x + b2 * v2.x + b3 * v3.x);
                acc1 += 0.25f * (b0 * v0.y + b1 * v1.y + b2 * v2.y + b3 * v3.y);
                acc2 += 0.25f * (b0 * v0.z + b1 * v1.z + b2 * v2.z + b3 * v3.z);
                acc3 += 0.25f * (b0 * v0.w + b1 * v1.w + b2 * v2.w + b3 * v3.w);
            } else {
                float w = (lane < 16) ? (lane < 8 ? b0 : b1) : (lane < 24 ? b2 : b3);
                float4 v = __ldg((const float4*)(xp + (size_t)sj * 128 + lane * 4));
                acc0 += w * v.x; acc1 += w * v.y; acc2 += w * v.z; acc3 += w * v.w;
            }
        }
    }
    int o = lane * 4;
    float* dst = ob + (size_t)n * 128 + o;
    dst[0] = acc0 + bias[o + 0];
    dst[1] = acc1 + bias[o + 1];
    dst[2] = acc2 + bias[o + 2];
    dst[3] = acc3 + bias[o + 3];
}

// ---------------------------------------------------------------------------
// BatchNorm (training-style: batch mean/var) + optional ELU
// ---------------------------------------------------------------------------
__global__ void bn_zero_kernel() {
    if (threadIdx.x < 128) { g_bnsum[threadIdx.x] = 0.f; g_bnsq[threadIdx.x] = 0.f; }
}

__global__ __launch_bounds__(128)
void bn_stats_kernel(const float* __restrict__ v) {
    int col = threadIdx.x;
    float s = 0.f, q = 0.f;
    for (int r = blockIdx.x; r < NN; r += gridDim.x) {
        float x = v[(size_t)r * 128 + col];
        s += x; q += x * x;
    }
    atomicAdd(&g_bnsum[col], s);
    atomicAdd(&g_bnsq[col], q);
}

template <bool ELU>
__global__ __launch_bounds__(256)
void bn_apply_kernel(const float* __restrict__ in, const float* __restrict__ gamma,
                     const float* __restrict__ beta, float* __restrict__ out) {
    int i = blockIdx.x * blockDim.x + threadIdx.x;
    if (i >= NN * 128) return;
    int col = i & 127;
    const float invN = 1.f / (float)NN;
    float mu  = g_bnsum[col] * invN;
    float var = g_bnsq[col] * invN - mu * mu;
    float sc  = gamma[col] * rsqrtf(var + 1e-5f);
    float y   = (in[i] - mu) * sc + beta[col];
    if (ELU) y = (y > 0.f) ? y : expm1f(y);
    out[i] = y;
}

// ---------------------------------------------------------------------------
// Launch
// ---------------------------------------------------------------------------
extern "C" void kernel_launch(void* const* d_in, const int* in_sizes, int n_in,
                              void* d_out, int out_size) {
    const float* x   = (const float*)d_in[0];
    const void*  ei  = d_in[1];                 // int32 or int64; detected on device
    const float* W0  = (const float*)d_in[2];
    const float* as0 = (const float*)d_in[3];
    const float* ad0 = (const float*)d_in[4];
    const float* b0  = (const float*)d_in[5];
    const float* g0  = (const float*)d_in[6];
    const float* be0 = (const float*)d_in[7];
    const float* W1  = (const float*)d_in[8];
    const float* as1 = (const float*)d_in[9];
    const float* ad1 = (const float*)d_in[10];
    const float* b1  = (const float*)d_in[11];
    const float* g1  = (const float*)d_in[12];
    const float* be1 = (const float*)d_in[13];
    const float* W2  = (const float*)d_in[14];
    const float* as2 = (const float*)d_in[15];
    const float* ad2 = (const float*)d_in[16];
    const float* b2  = (const float*)d_in[17];
    const float* g2  = (const float*)d_in[18];
    const float* be2 = (const float*)d_in[19];
    float* out = (float*)d_out;

    float* xp; cudaGetSymbolAddress((void**)&xp, g_xp);
    float* hb; cudaGetSymbolAddress((void**)&hb, g_h);
    float* ob; cudaGetSymbolAddress((void**)&ob, g_ob);

    const int nb_e  = (EP + 255) / 256;
    const int nb_aw = (NN * HEADS + 7) / 8;   // att: 8 warps/block
    const int nb_ag = (NN + 7) / 8;           // agg: 8 warps/block
    const int nb_el = (NN * 128 + 255) / 256;
    const dim3 gemm128((NN + 127) / 128, 1);
    const dim3 gemm512((NN + 127) / 128, 4);

    // CSR build (once, reused by all 3 layers)
    detect_kernel<<<1, 1>>>(ei);
    decode_kernel<<<nb_e, 256>>>(ei);
    hist_kernel<<<nb_e, 256>>>();
    scan_kernel<<<1, 1024>>>();
    scatter_kernel<<<nb_e, 256>>>();

    // ---- Layer 0: 128 -> 4x32 concat ----
    sgemm_kernel<<<gemm128, 256>>>(x, W0, xp, NN, 128);
    att_kernel<<<nb_aw, 256>>>(xp, as0, ad0, 32);
    aggregate_kernel<false><<<nb_ag, 256>>>(xp, b0, ob);
    bn_zero_kernel<<<1, 128>>>();
    bn_stats_kernel<<<512, 128>>>(ob);
    bn_apply_kernel<true><<<nb_el, 256>>>(ob, g0, be0, hb);

    // ---- Layer 1: 128 -> 4x32 concat ----
    sgemm_kernel<<<gemm128, 256>>>(hb, W1, xp, NN, 128);
    att_kernel<<<nb_aw, 256>>>(xp, as1, ad1, 32);
    aggregate_kernel<false><<<nb_ag, 256>>>(xp, b1, ob);
    bn_zero_kernel<<<1, 128>>>();
    bn_stats_kernel<<<512, 128>>>(ob);
    bn_apply_kernel<true><<<nb_el, 256>>>(ob, g1, be1, hb);

    // ---- Layer 2: 128 -> 4x128 mean ----
    sgemm_kernel<<<gemm512, 256>>>(hb, W2, xp, NN, 512);
    att_kernel<<<nb_aw, 256>>>(xp, as2, ad2, 128);
    aggregate_kernel<true><<<nb_ag, 256>>>(xp, b2, ob);
    bn_zero_kernel<<<1, 128>>>();
    bn_stats_kernel<<<512, 128>>>(ob);
    bn_apply_kernel<false><<<nb_el, 256>>>(ob, g2, be2, out);

    (void)in_sizes; (void)n_in; (void)out_size;
}

// round 7
// speedup vs baseline: 1.0661x; 1.0661x over previous
#include <cuda_runtime.h>
#include <cuda_bf16.h>
#include <cstdint>

// Problem constants
#define NN     50000
#define EE     800000
#define EP     (EE + NN)      // edges + self loops = 850000
#define HEADS  4

// ---------------------------------------------------------------------------
// Scratch (static device globals; no runtime allocation)
// ---------------------------------------------------------------------------
__device__ __align__(16) float g_xp[(size_t)NN * 512];   // GEMM out / L2 agg buffer
__device__ __align__(16) float g_h [(size_t)NN * 128];   // layer activations
__device__ __align__(16) float g_ob[(size_t)NN * 128];   // pre-BN buffer
__device__ __align__(16) float g_as[NN * 4];             // a_src per (node, head)
__device__ __align__(16) float g_ad[NN * 4];             // a_dst per (node, head)
__device__ __align__(16) float g_w2r[512 * 128];         // repacked W2: [h*128+c][o]
__device__ __align__(16) float g_us[512];                // u_src[h*128+c]
__device__ __align__(16) float g_ud[512];                // u_dst[h*128+c]
__device__ int g_rowptr[NN + 1];
__device__ int g_cursor[NN];
__device__ int g_deg[NN];
__device__ int g_csrc[EP];
__device__ int g_src[EP];
__device__ int g_dst[EP];
__device__ int g_is64;
__device__ float g_bnsum[128];
__device__ float g_bnsq[128];

__device__ __forceinline__ float lrelu(float x) { return x > 0.f ? x : 0.2f * x; }

// ---------------------------------------------------------------------------
// Edge-index dtype detection (JAX may emit int32 despite int64 in reference)
// ---------------------------------------------------------------------------
__global__ void detect_kernel(const void* ei) {
    const long long* p = (const long long*)ei;   // 512B read: safe either way
    int ok = 1;
    for (int j = 0; j < 64; j++) {
        long long v = p[j];
        if (v < 0 || v >= NN) { ok = 0; break; }
    }
    g_is64 = ok;
}

__global__ void zero_deg_kernel() {
    int i = blockIdx.x * blockDim.x + threadIdx.x;
    if (i < NN) g_deg[i] = 0;
}

// decode edges (+self loops) and build degree histogram in one pass
__global__ void decode_kernel(const void* ei) {
    int i = blockIdx.x * blockDim.x + threadIdx.x;
    if (i >= EP) return;
    int src, dst;
    if (i >= EE) {
        src = i - EE; dst = i - EE;
    } else if (g_is64) {
        const long long* p = (const long long*)ei;
        src = (int)p[i]; dst = (int)p[EE + i];
    } else {
        const int* p = (const int*)ei;
        src = p[i]; dst = p[EE + i];
    }
    g_src[i] = src; g_dst[i] = dst;
    atomicAdd(&g_deg[dst], 1);
}

// Fast single-block exclusive scan: serial-per-thread + warp shuffles, 2 barriers
__global__ void scan_kernel() {
    const int CH = 49;                       // 1024*49 >= 50000
    int t = threadIdx.x, lane = t & 31, wid = t >> 5;
    int base = t * CH;
    int sum = 0;
    #pragma unroll 7
    for (int i = 0; i < CH; i++) { int idx = base + i; if (idx < NN) sum += g_deg[idx]; }
    int incl = sum;
    #pragma unroll
    for (int o = 1; o < 32; o <<= 1) {
        int v = __shfl_up_sync(0xffffffffu, incl, o);
        if (lane >= o) incl += v;
    }
    __shared__ int wtot[32];
    if (lane == 31) wtot[wid] = incl;
    __syncthreads();
    if (wid == 0) {
        int v = wtot[lane];
        #pragma unroll
        for (int o = 1; o < 32; o <<= 1) {
            int u = __shfl_up_sync(0xffffffffu, v, o);
            if (lane >= o) v += u;
        }
        wtot[lane] = v;
    }
    __syncthreads();
    int run = (wid ? wtot[wid - 1] : 0) + incl - sum;   // exclusive prefix
    #pragma unroll 7
    for (int i = 0; i < CH; i++) {
        int idx = base + i;
        if (idx < NN) {
            int v = g_deg[idx];
            g_rowptr[idx] = run; g_cursor[idx] = run;
            run += v;
        }
    }
    if (t == 1023) g_rowptr[NN] = run;
}

__global__ void scatter_kernel() {
    int i = blockIdx.x * blockDim.x + threadIdx.x;
    if (i >= EP) return;
    int pos = atomicAdd(&g_cursor[g_dst[i]], 1);
    g_csrc[pos] = g_src[i];
}

// ---------------------------------------------------------------------------
// SGEMM: Y[M, Nd] = scale * X[M, Kd] @ W[Kd, Nd], 128x128 tile, 8x8/thread
// ---------------------------------------------------------------------------
__global__ __launch_bounds__(256)
void sgemm_kernel(const float* __restrict__ X, const float* __restrict__ W,
                  float* __restrict__ Y, int M, int Nd, int Kd, float scale) {
    __shared__ __align__(16) float As[16][128];
    __shared__ __align__(16) float Bs[16][128];
    const int bm = blockIdx.x * 128;
    const int bn = blockIdx.y * 128;
    const int tid = threadIdx.x;
    const int tx = tid & 15, ty = tid >> 4;

    float acc[8][8];
    #pragma unroll
    for (int i = 0; i < 8; i++)
        #pragma unroll
        for (int j = 0; j < 8; j++) acc[i][j] = 0.f;

    for (int kt = 0; kt < Kd / 16; kt++) {
        const int k0 = kt * 16;
        #pragma unroll
        for (int p = 0; p < 2; p++) {
            int r = (tid >> 2) + p * 64;
            int c = (tid & 3) * 4;
            int gr = bm + r;
            float4 v = make_float4(0.f, 0.f, 0.f, 0.f);
            if (gr < M) v = *(const float4*)(X + (size_t)gr * Kd + k0 + c);
            As[c + 0][r] = v.x; As[c + 1][r] = v.y;
            As[c + 2][r] = v.z; As[c + 3][r] = v.w;
        }
        #pragma unroll
        for (int p = 0; p < 2; p++) {
            int r = (tid >> 5) + p * 8;
            int c = (tid & 31) * 4;
            float4 v = *(const float4*)(W + (size_t)(k0 + r) * Nd + bn + c);
            *(float4*)&Bs[r][c] = v;
        }
        __syncthreads();
        #pragma unroll
        for (int k = 0; k < 16; k++) {
            float a[8], b[8];
            *(float4*)(a)     = *(const float4*)&As[k][ty * 8];
            *(float4*)(a + 4) = *(const float4*)&As[k][ty * 8 + 4];
            *(float4*)(b)     = *(const float4*)&Bs[k][tx * 8];
            *(float4*)(b + 4) = *(const float4*)&Bs[k][tx * 8 + 4];
            #pragma unroll
            for (int i = 0; i < 8; i++)
                #pragma unroll
                for (int j = 0; j < 8; j++) acc[i][j] += a[i] * b[j];
        }
        __syncthreads();
    }
    #pragma unroll
    for (int i = 0; i < 8; i++) {
        int gr = bm + ty * 8 + i;
        if (gr >= M) continue;
        #pragma unroll
        for (int j = 0; j < 8; j++) acc[i][j] *= scale;
        *(float4*)(Y + (size_t)gr * Nd + bn + tx * 8)     = *(float4*)&acc[i][0];
        *(float4*)(Y + (size_t)gr * Nd + bn + tx * 8 + 4) = *(float4*)&acc[i][4];
    }
}

// ---------------------------------------------------------------------------
// Attention dots for concat layers (C=32): one warp per (node, head)
// ---------------------------------------------------------------------------
__global__ __launch_bounds__(256)
void att_kernel(const float* __restrict__ xp, const float* __restrict__ asw,
                const float* __restrict__ adw) {
    int gw = (blockIdx.x * blockDim.x + threadIdx.x) >> 5;
    int lane = threadIdx.x & 31;
    if (gw >= NN * HEADS) return;
    int n = gw >> 2, h = gw & 3;
    float v = xp[(size_t)n * 128 + h * 32 + lane];
    float s = v * asw[h * 32 + lane];
    float d = v * adw[h * 32 + lane];
    #pragma unroll
    for (int o = 16; o; o >>= 1) {
        s += __shfl_xor_sync(0xffffffffu, s, o);
        d += __shfl_xor_sync(0xffffffffu, d, o);
    }
    if (lane == 0) { g_as[n * 4 + h] = s; g_ad[n * 4 + h] = d; }
}

// ---------------------------------------------------------------------------
// Layer-2 attention precompute:  u_s[h*128+c] = sum_j W2[c, h*128+j]*as2[h,j]
// ---------------------------------------------------------------------------
__global__ void prep_u_kernel(const float* __restrict__ W2,
                              const float* __restrict__ as2,
                              const float* __restrict__ ad2) {
    int t = blockIdx.x * blockDim.x + threadIdx.x;
    if (t >= 512) return;
    int h = t >> 7, c = t & 127;
    const float* wrow = W2 + (size_t)c * 512 + h * 128;
    const float* av = as2 + h * 128;
    const float* dv = ad2 + h * 128;
    float s = 0.f, d = 0.f;
    for (int j = 0; j < 128; j++) { float w = wrow[j]; s += w * av[j]; d += w * dv[j]; }
    g_us[t] = s; g_ud[t] = d;
}

// Repack W2 [128, 512] -> g_w2r [512, 128]: g_w2r[h*128+c][o] = W2[c][h*128+o]
__global__ void repack_w2_kernel(const float* __restrict__ W2) {
    int i = blockIdx.x * blockDim.x + threadIdx.x;
    if (i >= 512 * 128) return;
    int k = i >> 7, o = i & 127, h = k >> 7, c = k & 127;
    g_w2r[i] = W2[(size_t)c * 512 + h * 128 + o];
}

// Layer-2 attention dots from h-space: a_s[n,h] = h[n] . u_s[h]
__global__ __launch_bounds__(256)
void att2_kernel(const float* __restrict__ hb) {
    int gw = (blockIdx.x * blockDim.x + threadIdx.x) >> 5;
    int lane = threadIdx.x & 31;
    if (gw >= NN) return;
    const float4 v = *(const float4*)(hb + (size_t)gw * 128 + lane * 4);
    float s[4], d[4];
    #pragma unroll
    for (int h = 0; h < 4; h++) {
        const float4 us = *(const float4*)(g_us + h * 128 + lane * 4);
        const float4 ud = *(const float4*)(g_ud + h * 128 + lane * 4);
        s[h] = v.x * us.x + v.y * us.y + v.z * us.z + v.w * us.w;
        d[h] = v.x * ud.x + v.y * ud.y + v.z * ud.z + v.w * ud.w;
    }
    #pragma unroll
    for (int o = 16; o; o >>= 1) {
        #pragma unroll
        for (int h = 0; h < 4; h++) {
            s[h] += __shfl_xor_sync(0xffffffffu, s[h], o);
            d[h] += __shfl_xor_sync(0xffffffffu, d[h], o);
        }
    }
    if (lane == 0) {
        #pragma unroll
        for (int h = 0; h < 4; h++) { g_as[gw * 4 + h] = s[h]; g_ad[gw * 4 + h] = d[h]; }
    }
}

// ---------------------------------------------------------------------------
// Softmax weight helper: per-lane edge weights for up to 32 edges of node n
// ---------------------------------------------------------------------------
struct SoftCtx { float m0, m1, m2, m3, i0, i1, i2, i3; float4 adv; };

__device__ __forceinline__ SoftCtx softmax_ctx(int rs, int re, int n, int lane) {
    SoftCtx c;
    c.adv = *(const float4*)(g_ad + 4 * n);
    float m0 = -1e30f, m1 = -1e30f, m2 = -1e30f, m3 = -1e30f;
    for (int idx = rs + lane; idx < re; idx += 32) {
        int s = g_csrc[idx];
        float4 a = __ldg((const float4*)(g_as + 4 * s));
        m0 = fmaxf(m0, lrelu(a.x + c.adv.x));
        m1 = fmaxf(m1, lrelu(a.y + c.adv.y));
        m2 = fmaxf(m2, lrelu(a.z + c.adv.z));
        m3 = fmaxf(m3, lrelu(a.w + c.adv.w));
    }
    #pragma unroll
    for (int o = 16; o; o >>= 1) {
        m0 = fmaxf(m0, __shfl_xor_sync(0xffffffffu, m0, o));
        m1 = fmaxf(m1, __shfl_xor_sync(0xffffffffu, m1, o));
        m2 = fmaxf(m2, __shfl_xor_sync(0xffffffffu, m2, o));
        m3 = fmaxf(m3, __shfl_xor_sync(0xffffffffu, m3, o));
    }
    float s0 = 0.f, s1 = 0.f, s2 = 0.f, s3 = 0.f;
    for (int idx = rs + lane; idx < re; idx += 32) {
        int s = g_csrc[idx];
        float4 a = __ldg((const float4*)(g_as + 4 * s));
        s0 += __expf(lrelu(a.x + c.adv.x) - m0);
        s1 += __expf(lrelu(a.y + c.adv.y) - m1);
        s2 += __expf(lrelu(a.z + c.adv.z) - m2);
        s3 += __expf(lrelu(a.w + c.adv.w) - m3);
    }
    #pragma unroll
    for (int o = 16; o; o >>= 1) {
        s0 += __shfl_xor_sync(0xffffffffu, s0, o);
        s1 += __shfl_xor_sync(0xffffffffu, s1, o);
        s2 += __shfl_xor_sync(0xffffffffu, s2, o);
        s3 += __shfl_xor_sync(0xffffffffu, s3, o);
    }
    c.m0 = m0; c.m1 = m1; c.m2 = m2; c.m3 = m3;
    c.i0 = 1.f / (s0 + 1e-16f); c.i1 = 1.f / (s1 + 1e-16f);
    c.i2 = 1.f / (s2 + 1e-16f); c.i3 = 1.f / (s3 + 1e-16f);
    return c;
}

// ---------------------------------------------------------------------------
// Concat aggregation (layers 0/1): persistent warps + fused BN stats.
// Bias omitted: a per-column constant cancels exactly under BatchNorm.
// ---------------------------------------------------------------------------
__global__ __launch_bounds__(256)
void aggregate_kernel(const float* __restrict__ xp, float* __restrict__ ob) {
    const int lane = threadIdx.x & 31, w = threadIdx.x >> 5;
    const int gwarp = blockIdx.x * 8 + w;
    const int nwarps = gridDim.x * 8;
    float bs[4] = {0.f, 0.f, 0.f, 0.f}, bq[4] = {0.f, 0.f, 0.f, 0.f};

    for (int n = gwarp; n < NN; n += nwarps) {
        const int rs = g_rowptr[n], re = g_rowptr[n + 1];
        SoftCtx cx = softmax_ctx(rs, re, n, lane);

        float acc0 = 0.f, acc1 = 0.f, acc2 = 0.f, acc3 = 0.f;
        for (int idx = rs; idx < re; idx += 32) {
            int myi = idx + lane;
            int s = 0;
            float w0 = 0.f, w1 = 0.f, w2 = 0.f, w3 = 0.f;
            if (myi < re) {
                s = g_csrc[myi];
                float4 a = __ldg((const float4*)(g_as + 4 * s));
                w0 = __expf(lrelu(a.x + cx.adv.x) - cx.m0) * cx.i0;
                w1 = __expf(lrelu(a.y + cx.adv.y) - cx.m1) * cx.i1;
                w2 = __expf(lrelu(a.z + cx.adv.z) - cx.m2) * cx.i2;
                w3 = __expf(lrelu(a.w + cx.adv.w) - cx.m3) * cx.i3;
            }
            int cnt = min(32, re - idx);
            for (int j = 0; j < cnt; j++) {
                int sj   = __shfl_sync(0xffffffffu, s,  j);
                float b0 = __shfl_sync(0xffffffffu, w0, j);
                float b1 = __shfl_sync(0xffffffffu, w1, j);
                float b2 = __shfl_sync(0xffffffffu, w2, j);
                float b3 = __shfl_sync(0xffffffffu, w3, j);
                float ww = (lane < 16) ? (lane < 8 ? b0 : b1) : (lane < 24 ? b2 : b3);
                float4 v = __ldg((const float4*)(xp + (size_t)sj * 128 + lane * 4));
                acc0 += ww * v.x; acc1 += ww * v.y; acc2 += ww * v.z; acc3 += ww * v.w;
            }
        }
        float* dst = ob + (size_t)n * 128 + lane * 4;
        dst[0] = acc0; dst[1] = acc1; dst[2] = acc2; dst[3] = acc3;
        bs[0] += acc0; bq[0] += acc0 * acc0;
        bs[1] += acc1; bq[1] += acc1 * acc1;
        bs[2] += acc2; bq[2] += acc2 * acc2;
        bs[3] += acc3; bq[3] += acc3 * acc3;
    }

    __shared__ float ssum[8][128];
    __shared__ float ssq[8][128];
    #pragma unroll
    for (int k = 0; k < 4; k++) { ssum[w][lane * 4 + k] = bs[k]; ssq[w][lane * 4 + k] = bq[k]; }
    __syncthreads();
    if (threadIdx.x < 128) {
        float s = 0.f, q = 0.f;
        #pragma unroll
        for (int j = 0; j < 8; j++) { s += ssum[j][threadIdx.x]; q += ssq[j][threadIdx.x]; }
        atomicAdd(&g_bnsum[threadIdx.x], s);
        atomicAdd(&g_bnsq[threadIdx.x], q);
    }
}

// ---------------------------------------------------------------------------
// Layer-2 aggregation in h-space: agg[n, h*128+c] = sum_e alpha[e,h] * h[src, c]
// Reads 512B per edge instead of 2048B. One warp per node.
// ---------------------------------------------------------------------------
__global__ __launch_bounds__(256)
void aggregate2_kernel(const float* __restrict__ hb, float* __restrict__ agg) {
    int n = (blockIdx.x * blockDim.x + threadIdx.x) >> 5;
    int lane = threadIdx.x & 31;
    if (n >= NN) return;
    const int rs = g_rowptr[n], re = g_rowptr[n + 1];
    SoftCtx cx = softmax_ctx(rs, re, n, lane);

    float acc[4][4];
    #pragma unroll
    for (int h = 0; h < 4; h++)
        #pragma unroll
        for (int k = 0; k < 4; k++) acc[h][k] = 0.f;

    for (int idx = rs; idx < re; idx += 32) {
        int myi = idx + lane;
        int s = 0;
        float w0 = 0.f, w1 = 0.f, w2 = 0.f, w3 = 0.f;
        if (myi < re) {
            s = g_csrc[myi];
            float4 a = __ldg((const float4*)(g_as + 4 * s));
            w0 = __expf(lrelu(a.x + cx.adv.x) - cx.m0) * cx.i0;
            w1 = __expf(lrelu(a.y + cx.adv.y) - cx.m1) * cx.i1;
            w2 = __expf(lrelu(a.z + cx.adv.z) - cx.m2) * cx.i2;
            w3 = __expf(lrelu(a.w + cx.adv.w) - cx.m3) * cx.i3;
        }
        int cnt = min(32, re - idx);
        for (int j = 0; j < cnt; j++) {
            int sj   = __shfl_sync(0xffffffffu, s,  j);
            float b0 = __shfl_sync(0xffffffffu, w0, j);
            float b1 = __shfl_sync(0xffffffffu, w1, j);
            float b2 = __shfl_sync(0xffffffffu, w2, j);
            float b3 = __shfl_sync(0xffffffffu, w3, j);
            float4 v = __ldg((const float4*)(hb + (size_t)sj * 128 + lane * 4));
            acc[0][0] += b0 * v.x; acc[0][1] += b0 * v.y; acc[0][2] += b0 * v.z; acc[0][3] += b0 * v.w;
            acc[1][0] += b1 * v.x; acc[1][1] += b1 * v.y; acc[1][2] += b1 * v.z; acc[1][3] += b1 * v.w;
            acc[2][0] += b2 * v.x; acc[2][1] += b2 * v.y; acc[2][2] += b2 * v.z; acc[2][3] += b2 * v.w;
            acc[3][0] += b3 * v.x; acc[3][1] += b3 * v.y; acc[3][2] += b3 * v.z; acc[3][3] += b3 * v.w;
        }
    }
    #pragma unroll
    for (int h = 0; h < 4; h++)
        *(float4*)(agg + (size_t)n * 512 + h * 128 + lane * 4) = *(float4*)acc[h];
}

// ---------------------------------------------------------------------------
// BatchNorm
// ---------------------------------------------------------------------------
__global__ void bn_zero_kernel() {
    if (threadIdx.x < 128) { g_bnsum[threadIdx.x] = 0.f; g_bnsq[threadIdx.x] = 0.f; }
}

__global__ __launch_bounds__(128)
void bn_stats_kernel(const float* __restrict__ v) {
    int col = threadIdx.x;
    float s = 0.f, q = 0.f;
    for (int r = blockIdx.x; r < NN; r += gridDim.x) {
        float x = v[(size_t)r * 128 + col];
        s += x; q += x * x;
    }
    atomicAdd(&g_bnsum[col], s);
    atomicAdd(&g_bnsq[col], q);
}

template <bool ELU>
__global__ __launch_bounds__(256)
void bn_apply_kernel(const float* __restrict__ in, const float* __restrict__ gamma,
                     const float* __restrict__ beta, float* __restrict__ out) {
    int i = blockIdx.x * blockDim.x + threadIdx.x;
    if (i >= NN * 128) return;
    int col = i & 127;
    const float invN = 1.f / (float)NN;
    float mu  = g_bnsum[col] * invN;
    float var = g_bnsq[col] * invN - mu * mu;
    float sc  = gamma[col] * rsqrtf(var + 1e-5f);
    float y   = (in[i] - mu) * sc + beta[col];
    if (ELU) y = (y > 0.f) ? y : expm1f(y);
    out[i] = y;
}

// ---------------------------------------------------------------------------
// Launch
// ---------------------------------------------------------------------------
extern "C" void kernel_launch(void* const* d_in, const int* in_sizes, int n_in,
                              void* d_out, int out_size) {
    const float* x   = (const float*)d_in[0];
    const void*  ei  = d_in[1];
    const float* W0  = (const float*)d_in[2];
    const float* as0 = (const float*)d_in[3];
    const float* ad0 = (const float*)d_in[4];
    const float* g0  = (const float*)d_in[6];
    const float* be0 = (const float*)d_in[7];
    const float* W1  = (const float*)d_in[8];
    const float* as1 = (const float*)d_in[9];
    const float* ad1 = (const float*)d_in[10];
    const float* g1  = (const float*)d_in[12];
    const float* be1 = (const float*)d_in[13];
    const float* W2  = (const float*)d_in[14];
    const float* as2 = (const float*)d_in[15];
    const float* ad2 = (const float*)d_in[16];
    const float* g2  = (const float*)d_in[18];
    const float* be2 = (const float*)d_in[19];
    float* out = (float*)d_out;

    float* xp; cudaGetSymbolAddress((void**)&xp, g_xp);
    float* hb; cudaGetSymbolAddress((void**)&hb, g_h);
    float* ob; cudaGetSymbolAddress((void**)&ob, g_ob);
    float* w2r; cudaGetSymbolAddress((void**)&w2r, g_w2r);

    const int nb_n  = (NN + 255) / 256;
    const int nb_e  = (EP + 255) / 256;
    const int nb_aw = (NN * HEADS + 7) / 8;   // att: 8 warps/block
    const int nb_n8 = (NN + 7) / 8;           // warp-per-node kernels
    const int nb_el = (NN * 128 + 255) / 256;
    const dim3 gemm128((NN + 127) / 128, 1);

    // CSR build (5 launches; ncu -s 5 captures the next one = L0 sgemm)
    zero_deg_kernel<<<nb_n, 256>>>();
    detect_kernel<<<1, 1>>>(ei);
    decode_kernel<<<nb_e, 256>>>(ei);
    scan_kernel<<<1, 1024>>>();
    scatter_kernel<<<nb_e, 256>>>();

    // ---- Layer 0: 128 -> 4x32 concat ----
    sgemm_kernel<<<gemm128, 256>>>(x, W0, xp, NN, 128, 128, 1.f);
    att_kernel<<<nb_aw, 256>>>(xp, as0, ad0);
    bn_zero_kernel<<<1, 128>>>();
    aggregate_kernel<<<1480, 256>>>(xp, ob);
    bn_apply_kernel<true><<<nb_el, 256>>>(ob, g0, be0, hb);

    // ---- Layer 1: 128 -> 4x32 concat ----
    sgemm_kernel<<<gemm128, 256>>>(hb, W1, xp, NN, 128, 128, 1.f);
    att_kernel<<<nb_aw, 256>>>(xp, as1, ad1);
    bn_zero_kernel<<<1, 128>>>();
    aggregate_kernel<<<1480, 256>>>(xp, ob);
    bn_apply_kernel<true><<<nb_el, 256>>>(ob, g1, be1, hb);

    // ---- Layer 2: aggregate in h-space, then W2 GEMM (heads averaged) ----
    prep_u_kernel<<<2, 256>>>(W2, as2, ad2);
    repack_w2_kernel<<<256, 256>>>(W2);
    att2_kernel<<<nb_n8, 256>>>(hb);
    aggregate2_kernel<<<nb_n8, 256>>>(hb, xp);          // xp <- [N,512] agg
    sgemm_kernel<<<gemm128, 256>>>(xp, w2r, ob, NN, 128, 512, 0.25f);
    bn_zero_kernel<<<1, 128>>>();
    bn_stats_kernel<<<512, 128>>>(ob);
    bn_apply_kernel<false><<<nb_el, 256>>>(ob, g2, be2, out);

    (void)in_sizes; (void)n_in; (void)out_size;
}

// round 8
// speedup vs baseline: 1.1811x; 1.1078x over previous
#include <cuda_runtime.h>
#include <cuda_bf16.h>
#include <cstdint>

// Problem constants
#define NN     50000
#define EE     800000
#define EP     (EE + NN)      // edges + self loops = 850000
#define HEADS  4
#define NB     ((NN + 255) / 256)   // 196 scan blocks

// ---------------------------------------------------------------------------
// Scratch (static device globals; no runtime allocation)
// ---------------------------------------------------------------------------
__device__ __align__(16) float g_xp[(size_t)NN * 512];   // GEMM out / L2 agg buffer
__device__ __align__(16) float g_h [(size_t)NN * 128];   // layer activations
__device__ __align__(16) float g_ob[(size_t)NN * 128];   // pre-BN buffer
__device__ __align__(16) float g_as[NN * 4];             // a_src per (node, head)
__device__ __align__(16) float g_ad[NN * 4];             // a_dst per (node, head)
__device__ __align__(16) float g_w2r[512 * 128];         // repacked W2: [h*128+c][o]
__device__ __align__(16) float g_us[512];                // u_src[h*128+c]
__device__ __align__(16) float g_ud[512];                // u_dst[h*128+c]
__device__ int g_rowptr[NN + 1];
__device__ int g_cursor[NN];
__device__ int g_deg[NN];
__device__ int g_csrc[EP];
__device__ int g_src[EP];
__device__ int g_dst[EP];
__device__ int g_bsum[256];
__device__ int g_boff[256];
__device__ int g_is64;
__device__ float g_bnsum[128];
__device__ float g_bnsq[128];

__device__ __forceinline__ float lrelu(float x) { return x > 0.f ? x : 0.2f * x; }

// ---------------------------------------------------------------------------
// Edge-index dtype detection (JAX may emit int32 despite int64 in reference)
// 64 threads in parallel (was 1 thread = 64 serial DRAM loads = ~20us).
// ---------------------------------------------------------------------------
__global__ void detect_kernel(const void* ei) {
    __shared__ int ok;
    if (threadIdx.x == 0) ok = 1;
    __syncthreads();
    const long long* p = (const long long*)ei;   // 512B read: safe either way
    long long v = p[threadIdx.x];
    if (v < 0 || v >= NN) ok = 0;
    __syncthreads();
    if (threadIdx.x == 0) g_is64 = ok;
}

__global__ void zero_deg_kernel() {
    int i = blockIdx.x * blockDim.x + threadIdx.x;
    if (i < NN) g_deg[i] = 0;
}

// decode edges (+self loops) and build degree histogram in one pass
__global__ void decode_kernel(const void* ei) {
    int i = blockIdx.x * blockDim.x + threadIdx.x;
    if (i >= EP) return;
    int src, dst;
    if (i >= EE) {
        src = i - EE; dst = i - EE;
    } else if (g_is64) {
        const long long* p = (const long long*)ei;
        src = (int)p[i]; dst = (int)p[EE + i];
    } else {
        const int* p = (const int*)ei;
        src = p[i]; dst = p[EE + i];
    }
    g_src[i] = src; g_dst[i] = dst;
    atomicAdd(&g_deg[dst], 1);
}

// ---------------------------------------------------------------------------
// Hierarchical exclusive scan of g_deg (3 fully-parallel kernels)
// ---------------------------------------------------------------------------
__global__ __launch_bounds__(256) void block_sum_kernel() {
    int t = threadIdx.x, lane = t & 31, w = t >> 5;
    int idx = blockIdx.x * 256 + t;
    int v = (idx < NN) ? g_deg[idx] : 0;
    #pragma unroll
    for (int o = 16; o; o >>= 1) v += __shfl_xor_sync(0xffffffffu, v, o);
    __shared__ int wt[8];
    if (lane == 0) wt[w] = v;
    __syncthreads();
    if (t == 0) {
        int s = 0;
        #pragma unroll
        for (int j = 0; j < 8; j++) s += wt[j];
        g_bsum[blockIdx.x] = s;
    }
}

__global__ __launch_bounds__(256) void scan_bsum_kernel() {
    int t = threadIdx.x, lane = t & 31, w = t >> 5;
    int v = (t < NB) ? g_bsum[t] : 0;
    int incl = v;
    #pragma unroll
    for (int o = 1; o < 32; o <<= 1) {
        int u = __shfl_up_sync(0xffffffffu, incl, o);
        if (lane >= o) incl += u;
    }
    __shared__ int wt[8];
    if (lane == 31) wt[w] = incl;
    __syncthreads();
    if (w == 0 && lane < 8) {
        int x = wt[lane];
        #pragma unroll
        for (int o = 1; o < 8; o <<= 1) {
            int u = __shfl_up_sync(0xffu, x, o);
            if (lane >= o) x += u;
        }
        wt[lane] = x;
    }
    __syncthreads();
    int off = (w ? wt[w - 1] : 0);
    if (t < NB) g_boff[t] = off + incl - v;   // exclusive
}

__global__ __launch_bounds__(256) void scan_fill_kernel() {
    int t = threadIdx.x, lane = t & 31, w = t >> 5;
    int idx = blockIdx.x * 256 + t;
    int v = (idx < NN) ? g_deg[idx] : 0;
    int incl = v;
    #pragma unroll
    for (int o = 1; o < 32; o <<= 1) {
        int u = __shfl_up_sync(0xffffffffu, incl, o);
        if (lane >= o) incl += u;
    }
    __shared__ int wt[8];
    if (lane == 31) wt[w] = incl;
    __syncthreads();
    if (w == 0 && lane < 8) {
        int x = wt[lane];
        #pragma unroll
        for (int o = 1; o < 8; o <<= 1) {
            int u = __shfl_up_sync(0xffu, x, o);
            if (lane >= o) x += u;
        }
        wt[lane] = x;
    }
    __syncthreads();
    int ex = g_boff[blockIdx.x] + (w ? wt[w - 1] : 0) + incl - v;
    if (idx < NN) { g_rowptr[idx] = ex; g_cursor[idx] = ex; }
    if (idx == NN - 1) g_rowptr[NN] = ex + v;
}

__global__ void scatter_kernel() {
    int i = blockIdx.x * blockDim.x + threadIdx.x;
    if (i >= EP) return;
    int pos = atomicAdd(&g_cursor[g_dst[i]], 1);
    g_csrc[pos] = g_src[i];
}

// ---------------------------------------------------------------------------
// SGEMM: Y[M, Nd] = scale * X[M, Kd] @ W[Kd, Nd], 128x128 tile, 8x8/thread.
// Inner product uses packed fma.rn.f32x2 (Blackwell FFMA2): 32 packed FMAs
// per k-step instead of 64 scalar FFMA.
// ---------------------------------------------------------------------------
__global__ __launch_bounds__(256)
void sgemm_kernel(const float* __restrict__ X, const float* __restrict__ W,
                  float* __restrict__ Y, int M, int Nd, int Kd, float scale) {
    __shared__ __align__(16) float As[16][128];
    __shared__ __align__(16) float Bs[16][128];
    const int bm = blockIdx.x * 128;
    const int bn = blockIdx.y * 128;
    const int tid = threadIdx.x;
    const int tx = tid & 15, ty = tid >> 4;

    unsigned long long acc[8][4];   // 8 rows x 4 packed column-pairs
    #pragma unroll
    for (int i = 0; i < 8; i++)
        #pragma unroll
        for (int j = 0; j < 4; j++) acc[i][j] = 0ull;

    for (int kt = 0; kt < Kd / 16; kt++) {
        const int k0 = kt * 16;
        #pragma unroll
        for (int p = 0; p < 2; p++) {
            int r = (tid >> 2) + p * 64;
            int c = (tid & 3) * 4;
            int gr = bm + r;
            float4 v = make_float4(0.f, 0.f, 0.f, 0.f);
            if (gr < M) v = *(const float4*)(X + (size_t)gr * Kd + k0 + c);
            As[c + 0][r] = v.x; As[c + 1][r] = v.y;
            As[c + 2][r] = v.z; As[c + 3][r] = v.w;
        }
        #pragma unroll
        for (int p = 0; p < 2; p++) {
            int r = (tid >> 5) + p * 8;
            int c = (tid & 31) * 4;
            float4 v = *(const float4*)(W + (size_t)(k0 + r) * Nd + bn + c);
            *(float4*)&Bs[r][c] = v;
        }
        __syncthreads();
        #pragma unroll
        for (int k = 0; k < 16; k++) {
            float a[8];
            *(float4*)(a)     = *(const float4*)&As[k][ty * 8];
            *(float4*)(a + 4) = *(const float4*)&As[k][ty * 8 + 4];
            unsigned long long bp[4];
            bp[0] = *(const unsigned long long*)&Bs[k][tx * 8 + 0];
            bp[1] = *(const unsigned long long*)&Bs[k][tx * 8 + 2];
            bp[2] = *(const unsigned long long*)&Bs[k][tx * 8 + 4];
            bp[3] = *(const unsigned long long*)&Bs[k][tx * 8 + 6];
            #pragma unroll
            for (int i = 0; i < 8; i++) {
                unsigned long long aa;
                unsigned int au = __float_as_uint(a[i]);
                asm("mov.b64 %0, {%1, %1};" : "=l"(aa) : "r"(au));
                #pragma unroll
                for (int j = 0; j < 4; j++)
                    asm("fma.rn.f32x2 %0, %1, %2, %3;"
                        : "=l"(acc[i][j]) : "l"(aa), "l"(bp[j]), "l"(acc[i][j]));
            }
        }
        __syncthreads();
    }
    #pragma unroll
    for (int i = 0; i < 8; i++) {
        int gr = bm + ty * 8 + i;
        if (gr >= M) continue;
        float o8[8];
        #pragma unroll
        for (int j = 0; j < 4; j++) {
            float2 f = *(float2*)&acc[i][j];
            o8[2 * j] = f.x * scale; o8[2 * j + 1] = f.y * scale;
        }
        *(float4*)(Y + (size_t)gr * Nd + bn + tx * 8)     = *(float4*)&o8[0];
        *(float4*)(Y + (size_t)gr * Nd + bn + tx * 8 + 4) = *(float4*)&o8[4];
    }
}

// ---------------------------------------------------------------------------
// Attention dots for concat layers (C=32): one warp per (node, head)
// ---------------------------------------------------------------------------
__global__ __launch_bounds__(256)
void att_kernel(const float* __restrict__ xp, const float* __restrict__ asw,
                const float* __restrict__ adw) {
    int gw = (blockIdx.x * blockDim.x + threadIdx.x) >> 5;
    int lane = threadIdx.x & 31;
    if (gw >= NN * HEADS) return;
    int n = gw >> 2, h = gw & 3;
    float v = xp[(size_t)n * 128 + h * 32 + lane];
    float s = v * asw[h * 32 + lane];
    float d = v * adw[h * 32 + lane];
    #pragma unroll
    for (int o = 16; o; o >>= 1) {
        s += __shfl_xor_sync(0xffffffffu, s, o);
        d += __shfl_xor_sync(0xffffffffu, d, o);
    }
    if (lane == 0) { g_as[n * 4 + h] = s; g_ad[n * 4 + h] = d; }
}

// ---------------------------------------------------------------------------
// Layer-2 attention precompute:  u_s[h*128+c] = sum_j W2[c, h*128+j]*as2[h,j]
// ---------------------------------------------------------------------------
__global__ void prep_u_kernel(const float* __restrict__ W2,
                              const float* __restrict__ as2,
                              const float* __restrict__ ad2) {
    int t = blockIdx.x * blockDim.x + threadIdx.x;
    if (t >= 512) return;
    int h = t >> 7, c = t & 127;
    const float* wrow = W2 + (size_t)c * 512 + h * 128;
    const float* av = as2 + h * 128;
    const float* dv = ad2 + h * 128;
    float s = 0.f, d = 0.f;
    for (int j = 0; j < 128; j++) { float w = wrow[j]; s += w * av[j]; d += w * dv[j]; }
    g_us[t] = s; g_ud[t] = d;
}

// Repack W2 [128, 512] -> g_w2r [512, 128]: g_w2r[h*128+c][o] = W2[c][h*128+o]
__global__ void repack_w2_kernel(const float* __restrict__ W2) {
    int i = blockIdx.x * blockDim.x + threadIdx.x;
    if (i >= 512 * 128) return;
    int k = i >> 7, o = i & 127, h = k >> 7, c = k & 127;
    g_w2r[i] = W2[(size_t)c * 512 + h * 128 + o];
}

// Layer-2 attention dots from h-space: a_s[n,h] = h[n] . u_s[h]
__global__ __launch_bounds__(256)
void att2_kernel(const float* __restrict__ hb) {
    int gw = (blockIdx.x * blockDim.x + threadIdx.x) >> 5;
    int lane = threadIdx.x & 31;
    if (gw >= NN) return;
    const float4 v = *(const float4*)(hb + (size_t)gw * 128 + lane * 4);
    float s[4], d[4];
    #pragma unroll
    for (int h = 0; h < 4; h++) {
        const float4 us = *(const float4*)(g_us + h * 128 + lane * 4);
        const float4 ud = *(const float4*)(g_ud + h * 128 + lane * 4);
        s[h] = v.x * us.x + v.y * us.y + v.z * us.z + v.w * us.w;
        d[h] = v.x * ud.x + v.y * ud.y + v.z * ud.z + v.w * ud.w;
    }
    #pragma unroll
    for (int o = 16; o; o >>= 1) {
        #pragma unroll
        for (int h = 0; h < 4; h++) {
            s[h] += __shfl_xor_sync(0xffffffffu, s[h], o);
            d[h] += __shfl_xor_sync(0xffffffffu, d[h], o);
        }
    }
    if (lane == 0) {
        #pragma unroll
        for (int h = 0; h < 4; h++) { g_as[gw * 4 + h] = s[h]; g_ad[gw * 4 + h] = d[h]; }
    }
}

// ---------------------------------------------------------------------------
// Softmax context: per-head max + inverse sum for node n's incoming edges
// ---------------------------------------------------------------------------
struct SoftCtx { float m0, m1, m2, m3, i0, i1, i2, i3; float4 adv; };

__device__ __forceinline__ SoftCtx softmax_ctx(int rs, int re, int n, int lane) {
    SoftCtx c;
    c.adv = *(const float4*)(g_ad + 4 * n);
    float m0 = -1e30f, m1 = -1e30f, m2 = -1e30f, m3 = -1e30f;
    for (int idx = rs + lane; idx < re; idx += 32) {
        int s = g_csrc[idx];
        float4 a = __ldg((const float4*)(g_as + 4 * s));
        m0 = fmaxf(m0, lrelu(a.x + c.adv.x));
        m1 = fmaxf(m1, lrelu(a.y + c.adv.y));
        m2 = fmaxf(m2, lrelu(a.z + c.adv.z));
        m3 = fmaxf(m3, lrelu(a.w + c.adv.w));
    }
    #pragma unroll
    for (int o = 16; o; o >>= 1) {
        m0 = fmaxf(m0, __shfl_xor_sync(0xffffffffu, m0, o));
        m1 = fmaxf(m1, __shfl_xor_sync(0xffffffffu, m1, o));
        m2 = fmaxf(m2, __shfl_xor_sync(0xffffffffu, m2, o));
        m3 = fmaxf(m3, __shfl_xor_sync(0xffffffffu, m3, o));
    }
    float s0 = 0.f, s1 = 0.f, s2 = 0.f, s3 = 0.f;
    for (int idx = rs + lane; idx < re; idx += 32) {
        int s = g_csrc[idx];
        float4 a = __ldg((const float4*)(g_as + 4 * s));
        s0 += __expf(lrelu(a.x + c.adv.x) - m0);
        s1 += __expf(lrelu(a.y + c.adv.y) - m1);
        s2 += __expf(lrelu(a.z + c.adv.z) - m2);
        s3 += __expf(lrelu(a.w + c.adv.w) - m3);
    }
    #pragma unroll
    for (int o = 16; o; o >>= 1) {
        s0 += __shfl_xor_sync(0xffffffffu, s0, o);
        s1 += __shfl_xor_sync(0xffffffffu, s1, o);
        s2 += __shfl_xor_sync(0xffffffffu, s2, o);
        s3 += __shfl_xor_sync(0xffffffffu, s3, o);
    }
    c.m0 = m0; c.m1 = m1; c.m2 = m2; c.m3 = m3;
    c.i0 = 1.f / (s0 + 1e-16f); c.i1 = 1.f / (s1 + 1e-16f);
    c.i2 = 1.f / (s2 + 1e-16f); c.i3 = 1.f / (s3 + 1e-16f);
    return c;
}

// ---------------------------------------------------------------------------
// Concat aggregation (layers 0/1): persistent warps + fused BN stats.
// Bias omitted: a per-column constant cancels exactly under BatchNorm.
// ---------------------------------------------------------------------------
__global__ __launch_bounds__(256)
void aggregate_kernel(const float* __restrict__ xp, float* __restrict__ ob) {
    const int lane = threadIdx.x & 31, w = threadIdx.x >> 5;
    const int gwarp = blockIdx.x * 8 + w;
    const int nwarps = gridDim.x * 8;
    float bs[4] = {0.f, 0.f, 0.f, 0.f}, bq[4] = {0.f, 0.f, 0.f, 0.f};

    for (int n = gwarp; n < NN; n += nwarps) {
        const int rs = g_rowptr[n], re = g_rowptr[n + 1];
        SoftCtx cx = softmax_ctx(rs, re, n, lane);

        float acc0 = 0.f, acc1 = 0.f, acc2 = 0.f, acc3 = 0.f;
        for (int idx = rs; idx < re; idx += 32) {
            int myi = idx + lane;
            int s = 0;
            float w0 = 0.f, w1 = 0.f, w2 = 0.f, w3 = 0.f;
            if (myi < re) {
                s = g_csrc[myi];
                float4 a = __ldg((const float4*)(g_as + 4 * s));
                w0 = __expf(lrelu(a.x + cx.adv.x) - cx.m0) * cx.i0;
                w1 = __expf(lrelu(a.y + cx.adv.y) - cx.m1) * cx.i1;
                w2 = __expf(lrelu(a.z + cx.adv.z) - cx.m2) * cx.i2;
                w3 = __expf(lrelu(a.w + cx.adv.w) - cx.m3) * cx.i3;
            }
            int cnt = min(32, re - idx);
            for (int j = 0; j < cnt; j++) {
                int sj   = __shfl_sync(0xffffffffu, s,  j);
                float b0 = __shfl_sync(0xffffffffu, w0, j);
                float b1 = __shfl_sync(0xffffffffu, w1, j);
                float b2 = __shfl_sync(0xffffffffu, w2, j);
                float b3 = __shfl_sync(0xffffffffu, w3, j);
                float ww = (lane < 16) ? (lane < 8 ? b0 : b1) : (lane < 24 ? b2 : b3);
                float4 v = __ldg((const float4*)(xp + (size_t)sj * 128 + lane * 4));
                acc0 += ww * v.x; acc1 += ww * v.y; acc2 += ww * v.z; acc3 += ww * v.w;
            }
        }
        float* dst = ob + (size_t)n * 128 + lane * 4;
        dst[0] = acc0; dst[1] = acc1; dst[2] = acc2; dst[3] = acc3;
        bs[0] += acc0; bq[0] += acc0 * acc0;
        bs[1] += acc1; bq[1] += acc1 * acc1;
        bs[2] += acc2; bq[2] += acc2 * acc2;
        bs[3] += acc3; bq[3] += acc3 * acc3;
    }

    __shared__ float ssum[8][128];
    __shared__ float ssq[8][128];
    #pragma unroll
    for (int k = 0; k < 4; k++) { ssum[w][lane * 4 + k] = bs[k]; ssq[w][lane * 4 + k] = bq[k]; }
    __syncthreads();
    if (threadIdx.x < 128) {
        float s = 0.f, q = 0.f;
        #pragma unroll
        for (int j = 0; j < 8; j++) { s += ssum[j][threadIdx.x]; q += ssq[j][threadIdx.x]; }
        atomicAdd(&g_bnsum[threadIdx.x], s);
        atomicAdd(&g_bnsq[threadIdx.x], q);
    }
}

// ---------------------------------------------------------------------------
// Layer-2 aggregation in h-space: agg[n, h*128+c] = sum_e alpha[e,h] * h[src, c]
// ---------------------------------------------------------------------------
__global__ __launch_bounds__(256)
void aggregate2_kernel(const float* __restrict__ hb, float* __restrict__ agg) {
    int n = (blockIdx.x * blockDim.x + threadIdx.x) >> 5;
    int lane = threadIdx.x & 31;
    if (n >= NN) return;
    const int rs = g_rowptr[n], re = g_rowptr[n + 1];
    SoftCtx cx = softmax_ctx(rs, re, n, lane);

    float acc[4][4];
    #pragma unroll
    for (int h = 0; h < 4; h++)
        #pragma unroll
        for (int k = 0; k < 4; k++) acc[h][k] = 0.f;

    for (int idx = rs; idx < re; idx += 32) {
        int myi = idx + lane;
        int s = 0;
        float w0 = 0.f, w1 = 0.f, w2 = 0.f, w3 = 0.f;
        if (myi < re) {
            s = g_csrc[myi];
            float4 a = __ldg((const float4*)(g_as + 4 * s));
            w0 = __expf(lrelu(a.x + cx.adv.x) - cx.m0) * cx.i0;
            w1 = __expf(lrelu(a.y + cx.adv.y) - cx.m1) * cx.i1;
            w2 = __expf(lrelu(a.z + cx.adv.z) - cx.m2) * cx.i2;
            w3 = __expf(lrelu(a.w + cx.adv.w) - cx.m3) * cx.i3;
        }
        int cnt = min(32, re - idx);
        for (int j = 0; j < cnt; j++) {
            int sj   = __shfl_sync(0xffffffffu, s,  j);
            float b0 = __shfl_sync(0xffffffffu, w0, j);
            float b1 = __shfl_sync(0xffffffffu, w1, j);
            float b2 = __shfl_sync(0xffffffffu, w2, j);
            float b3 = __shfl_sync(0xffffffffu, w3, j);
            float4 v = __ldg((const float4*)(hb + (size_t)sj * 128 + lane * 4));
            acc[0][0] += b0 * v.x; acc[0][1] += b0 * v.y; acc[0][2] += b0 * v.z; acc[0][3] += b0 * v.w;
            acc[1][0] += b1 * v.x; acc[1][1] += b1 * v.y; acc[1][2] += b1 * v.z; acc[1][3] += b1 * v.w;
            acc[2][0] += b2 * v.x; acc[2][1] += b2 * v.y; acc[2][2] += b2 * v.z; acc[2][3] += b2 * v.w;
            acc[3][0] += b3 * v.x; acc[3][1] += b3 * v.y; acc[3][2] += b3 * v.z; acc[3][3] += b3 * v.w;
        }
    }
    #pragma unroll
    for (int h = 0; h < 4; h++)
        *(float4*)(agg + (size_t)n * 512 + h * 128 + lane * 4) = *(float4*)acc[h];
}

// ---------------------------------------------------------------------------
// BatchNorm
// ---------------------------------------------------------------------------
__global__ void bn_zero_kernel() {
    if (threadIdx.x < 128) { g_bnsum[threadIdx.x] = 0.f; g_bnsq[threadIdx.x] = 0.f; }
}

__global__ __launch_bounds__(128)
void bn_stats_kernel(const float* __restrict__ v) {
    int col = threadIdx.x;
    float s = 0.f, q = 0.f;
    for (int r = blockIdx.x; r < NN; r += gridDim.x) {
        float x = v[(size_t)r * 128 + col];
        s += x; q += x * x;
    }
    atomicAdd(&g_bnsum[col], s);
    atomicAdd(&g_bnsq[col], q);
}

template <bool ELU>
__global__ __launch_bounds__(256)
void bn_apply_kernel(const float* __restrict__ in, const float* __restrict__ gamma,
                     const float* __restrict__ beta, float* __restrict__ out) {
    int i = blockIdx.x * blockDim.x + threadIdx.x;
    if (i >= NN * 128) return;
    int col = i & 127;
    const float invN = 1.f / (float)NN;
    float mu  = g_bnsum[col] * invN;
    float var = g_bnsq[col] * invN - mu * mu;
    float sc  = gamma[col] * rsqrtf(var + 1e-5f);
    float y   = (in[i] - mu) * sc + beta[col];
    if (ELU) y = (y > 0.f) ? y : expm1f(y);
    out[i] = y;
}

// ---------------------------------------------------------------------------
// Launch
// ---------------------------------------------------------------------------
extern "C" void kernel_launch(void* const* d_in, const int* in_sizes, int n_in,
                              void* d_out, int out_size) {
    const float* x   = (const float*)d_in[0];
    const void*  ei  = d_in[1];
    const float* W0  = (const float*)d_in[2];
    const float* as0 = (const float*)d_in[3];
    const float* ad0 = (const float*)d_in[4];
    const float* g0  = (const float*)d_in[6];
    const float* be0 = (const float*)d_in[7];
    const float* W1  = (const float*)d_in[8];
    const float* as1 = (const float*)d_in[9];
    const float* ad1 = (const float*)d_in[10];
    const float* g1  = (const float*)d_in[12];
    const float* be1 = (const float*)d_in[13];
    const float* W2  = (const float*)d_in[14];
    const float* as2 = (const float*)d_in[15];
    const float* ad2 = (const float*)d_in[16];
    const float* g2  = (const float*)d_in[18];
    const float* be2 = (const float*)d_in[19];
    float* out = (float*)d_out;

    float* xp; cudaGetSymbolAddress((void**)&xp, g_xp);
    float* hb; cudaGetSymbolAddress((void**)&hb, g_h);
    float* ob; cudaGetSymbolAddress((void**)&ob, g_ob);
    float* w2r; cudaGetSymbolAddress((void**)&w2r, g_w2r);

    const int nb_n  = (NN + 255) / 256;
    const int nb_e  = (EP + 255) / 256;
    const int nb_aw = (NN * HEADS + 7) / 8;   // att: 8 warps/block
    const int nb_n8 = (NN + 7) / 8;           // warp-per-node kernels
    const int nb_el = (NN * 128 + 255) / 256;
    const dim3 gemm128((NN + 127) / 128, 1);

    // CSR build
    zero_deg_kernel<<<nb_n, 256>>>();
    detect_kernel<<<1, 64>>>(ei);
    decode_kernel<<<nb_e, 256>>>(ei);
    block_sum_kernel<<<NB, 256>>>();
    scan_bsum_kernel<<<1, 256>>>();
    scan_fill_kernel<<<NB, 256>>>();
    scatter_kernel<<<nb_e, 256>>>();

    // ---- Layer 0: 128 -> 4x32 concat ----
    sgemm_kernel<<<gemm128, 256>>>(x, W0, xp, NN, 128, 128, 1.f);
    att_kernel<<<nb_aw, 256>>>(xp, as0, ad0);
    bn_zero_kernel<<<1, 128>>>();
    aggregate_kernel<<<1480, 256>>>(xp, ob);
    bn_apply_kernel<true><<<nb_el, 256>>>(ob, g0, be0, hb);

    // ---- Layer 1: 128 -> 4x32 concat ----
    sgemm_kernel<<<gemm128, 256>>>(hb, W1, xp, NN, 128, 128, 1.f);
    att_kernel<<<nb_aw, 256>>>(xp, as1, ad1);
    bn_zero_kernel<<<1, 128>>>();
    aggregate_kernel<<<1480, 256>>>(xp, ob);
    bn_apply_kernel<true><<<nb_el, 256>>>(ob, g1, be1, hb);

    // ---- Layer 2: aggregate in h-space, then W2 GEMM (heads averaged) ----
    prep_u_kernel<<<2, 256>>>(W2, as2, ad2);
    repack_w2_kernel<<<256, 256>>>(W2);
    att2_kernel<<<nb_n8, 256>>>(hb);
    aggregate2_kernel<<<nb_n8, 256>>>(hb, xp);          // xp <- [N,512] agg
    sgemm_kernel<<<gemm128, 256>>>(xp, w2r, ob, NN, 128, 512, 0.25f);
    bn_zero_kernel<<<1, 128>>>();
    bn_stats_kernel<<<512, 128>>>(ob);
    bn_apply_kernel<false><<<nb_el, 256>>>(ob, g2, be2, out);

    (void)in_sizes; (void)n_in; (void)out_size;
}

// round 9
// speedup vs baseline: 1.2713x; 1.0764x over previous
#include <cuda_runtime.h>
#include <cuda_bf16.h>
#include <cstdint>

// Problem constants
#define NN     50000
#define EE     800000
#define EP     (EE + NN)      // edges + self loops = 850000
#define HEADS  4
#define NB     ((NN + 255) / 256)   // 196 scan blocks

// ---------------------------------------------------------------------------
// Scratch (static device globals; no runtime allocation)
// ---------------------------------------------------------------------------
__device__ __align__(16) float g_xp[(size_t)NN * 512];   // GEMM out / L2 agg buffer
__device__ __align__(16) float g_h [(size_t)NN * 128];   // layer activations
__device__ __align__(16) float g_ob[(size_t)NN * 128];   // pre-BN buffer
__device__ __align__(16) float g_as[NN * 4];             // a_src per (node, head)
__device__ __align__(16) float g_ad[NN * 4];             // a_dst per (node, head)
__device__ __align__(16) float g_w2r[512 * 128];         // repacked W2: [h*128+c][o]
__device__ __align__(16) float g_us[512];                // u_src[h*128+c]
__device__ __align__(16) float g_ud[512];                // u_dst[h*128+c]
__device__ int g_rowptr[NN + 1];
__device__ int g_cursor[NN];
__device__ int g_deg[NN];
__device__ int g_csrc[EP];
__device__ int g_src[EP];
__device__ int g_dst[EP];
__device__ int g_bsum[256];
__device__ int g_boff[256];
__device__ int g_is64;
__device__ float g_bnsum[128];
__device__ float g_bnsq[128];

__device__ __forceinline__ float lrelu(float x) { return x > 0.f ? x : 0.2f * x; }

// ---------------------------------------------------------------------------
// Edge-index dtype detection (JAX may emit int32 despite int64 in reference)
// ---------------------------------------------------------------------------
__global__ void detect_kernel(const void* ei) {
    __shared__ int ok;
    if (threadIdx.x == 0) ok = 1;
    __syncthreads();
    const long long* p = (const long long*)ei;   // 512B read: safe either way
    long long v = p[threadIdx.x];
    if (v < 0 || v >= NN) ok = 0;
    __syncthreads();
    if (threadIdx.x == 0) g_is64 = ok;
}

__global__ void zero_deg_kernel() {
    int i = blockIdx.x * blockDim.x + threadIdx.x;
    if (i < NN) g_deg[i] = 0;
}

// decode edges (+self loops) and build degree histogram in one pass
__global__ void decode_kernel(const void* ei) {
    int i = blockIdx.x * blockDim.x + threadIdx.x;
    if (i >= EP) return;
    int src, dst;
    if (i >= EE) {
        src = i - EE; dst = i - EE;
    } else if (g_is64) {
        const long long* p = (const long long*)ei;
        src = (int)p[i]; dst = (int)p[EE + i];
    } else {
        const int* p = (const int*)ei;
        src = p[i]; dst = p[EE + i];
    }
    g_src[i] = src; g_dst[i] = dst;
    atomicAdd(&g_deg[dst], 1);
}

// ---------------------------------------------------------------------------
// Hierarchical exclusive scan of g_deg (3 fully-parallel kernels)
// ---------------------------------------------------------------------------
__global__ __launch_bounds__(256) void block_sum_kernel() {
    int t = threadIdx.x, lane = t & 31, w = t >> 5;
    int idx = blockIdx.x * 256 + t;
    int v = (idx < NN) ? g_deg[idx] : 0;
    #pragma unroll
    for (int o = 16; o; o >>= 1) v += __shfl_xor_sync(0xffffffffu, v, o);
    __shared__ int wt[8];
    if (lane == 0) wt[w] = v;
    __syncthreads();
    if (t == 0) {
        int s = 0;
        #pragma unroll
        for (int j = 0; j < 8; j++) s += wt[j];
        g_bsum[blockIdx.x] = s;
    }
}

__global__ __launch_bounds__(256) void scan_bsum_kernel() {
    int t = threadIdx.x, lane = t & 31, w = t >> 5;
    int v = (t < NB) ? g_bsum[t] : 0;
    int incl = v;
    #pragma unroll
    for (int o = 1; o < 32; o <<= 1) {
        int u = __shfl_up_sync(0xffffffffu, incl, o);
        if (lane >= o) incl += u;
    }
    __shared__ int wt[8];
    if (lane == 31) wt[w] = incl;
    __syncthreads();
    if (w == 0 && lane < 8) {
        int x = wt[lane];
        #pragma unroll
        for (int o = 1; o < 8; o <<= 1) {
            int u = __shfl_up_sync(0xffu, x, o);
            if (lane >= o) x += u;
        }
        wt[lane] = x;
    }
    __syncthreads();
    int off = (w ? wt[w - 1] : 0);
    if (t < NB) g_boff[t] = off + incl - v;   // exclusive
}

__global__ __launch_bounds__(256) void scan_fill_kernel() {
    int t = threadIdx.x, lane = t & 31, w = t >> 5;
    int idx = blockIdx.x * 256 + t;
    int v = (idx < NN) ? g_deg[idx] : 0;
    int incl = v;
    #pragma unroll
    for (int o = 1; o < 32; o <<= 1) {
        int u = __shfl_up_sync(0xffffffffu, incl, o);
        if (lane >= o) incl += u;
    }
    __shared__ int wt[8];
    if (lane == 31) wt[w] = incl;
    __syncthreads();
    if (w == 0 && lane < 8) {
        int x = wt[lane];
        #pragma unroll
        for (int o = 1; o < 8; o <<= 1) {
            int u = __shfl_up_sync(0xffu, x, o);
            if (lane >= o) x += u;
        }
        wt[lane] = x;
    }
    __syncthreads();
    int ex = g_boff[blockIdx.x] + (w ? wt[w - 1] : 0) + incl - v;
    if (idx < NN) { g_rowptr[idx] = ex; g_cursor[idx] = ex; }
    if (idx == NN - 1) g_rowptr[NN] = ex + v;
}

__global__ void scatter_kernel() {
    int i = blockIdx.x * blockDim.x + threadIdx.x;
    if (i >= EP) return;
    int pos = atomicAdd(&g_cursor[g_dst[i]], 1);
    g_csrc[pos] = g_src[i];
}

// ---------------------------------------------------------------------------
// SGEMM: Y[M,128] = scale * X[M,KD] @ W[KD,128]. 128x128 tile, 8x8/thread,
// double-buffered smem, packed fma.rn.f32x2 core.
// MODE 1: fused attention-dot epilogue (writes g_as/g_ad).
// MODE 2: fused BN-stats epilogue (atomics into g_bnsum/g_bnsq).
// ---------------------------------------------------------------------------
template <int KD, int MODE>
__global__ __launch_bounds__(256, 2)
void sgemm_kernel(const float* __restrict__ X, const float* __restrict__ W,
                  float* __restrict__ Y, int M, float scale,
                  const float* __restrict__ asw, const float* __restrict__ adw) {
    __shared__ __align__(16) float As[2][16][128];
    __shared__ __align__(16) float Bs[2][16][128];
    const int bm = blockIdx.x * 128;
    const int tid = threadIdx.x;
    const int tx = tid & 15, ty = tid >> 4;
    const int KT = KD / 16;

    unsigned long long acc[8][4];
    #pragma unroll
    for (int i = 0; i < 8; i++)
        #pragma unroll
        for (int j = 0; j < 4; j++) acc[i][j] = 0ull;

    const int ar = tid >> 2, ac = (tid & 3) * 4;      // A-load coords
    const int br = tid >> 5, bc = (tid & 31) * 4;     // B-load coords

    float4 ra[2], rb[2];
    // prologue: tile 0
    #pragma unroll
    for (int p = 0; p < 2; p++) {
        int gr = bm + ar + p * 64;
        ra[p] = make_float4(0.f, 0.f, 0.f, 0.f);
        if (gr < M) ra[p] = *(const float4*)(X + (size_t)gr * KD + ac);
        rb[p] = *(const float4*)(W + (size_t)(br + p * 8) * 128 + bc);
    }
    #pragma unroll
    for (int p = 0; p < 2; p++) {
        int r = ar + p * 64;
        As[0][ac + 0][r] = ra[p].x; As[0][ac + 1][r] = ra[p].y;
        As[0][ac + 2][r] = ra[p].z; As[0][ac + 3][r] = ra[p].w;
        *(float4*)&Bs[0][br + p * 8][bc] = rb[p];
    }
    __syncthreads();

    for (int kt = 0; kt < KT; kt++) {
        const int cur = kt & 1;
        const bool has_next = (kt + 1 < KT);
        if (has_next) {
            const int k0 = (kt + 1) * 16;
            #pragma unroll
            for (int p = 0; p < 2; p++) {
                int gr = bm + ar + p * 64;
                ra[p] = make_float4(0.f, 0.f, 0.f, 0.f);
                if (gr < M) ra[p] = *(const float4*)(X + (size_t)gr * KD + k0 + ac);
                rb[p] = *(const float4*)(W + (size_t)(k0 + br + p * 8) * 128 + bc);
            }
        }
        #pragma unroll
        for (int k = 0; k < 16; k++) {
            float a[8];
            *(float4*)(a)     = *(const float4*)&As[cur][k][ty * 8];
            *(float4*)(a + 4) = *(const float4*)&As[cur][k][ty * 8 + 4];
            unsigned long long bp[4];
            bp[0] = *(const unsigned long long*)&Bs[cur][k][tx * 8 + 0];
            bp[1] = *(const unsigned long long*)&Bs[cur][k][tx * 8 + 2];
            bp[2] = *(const unsigned long long*)&Bs[cur][k][tx * 8 + 4];
            bp[3] = *(const unsigned long long*)&Bs[cur][k][tx * 8 + 6];
            #pragma unroll
            for (int i = 0; i < 8; i++) {
                unsigned long long aa;
                unsigned int au = __float_as_uint(a[i]);
                asm("mov.b64 %0, {%1, %1};" : "=l"(aa) : "r"(au));
                #pragma unroll
                for (int j = 0; j < 4; j++)
                    asm("fma.rn.f32x2 %0, %1, %2, %3;"
                        : "=l"(acc[i][j]) : "l"(aa), "l"(bp[j]), "l"(acc[i][j]));
            }
        }
        if (has_next) {
            const int nxt = (kt + 1) & 1;
            #pragma unroll
            for (int p = 0; p < 2; p++) {
                int r = ar + p * 64;
                As[nxt][ac + 0][r] = ra[p].x; As[nxt][ac + 1][r] = ra[p].y;
                As[nxt][ac + 2][r] = ra[p].z; As[nxt][ac + 3][r] = ra[p].w;
                *(float4*)&Bs[nxt][br + p * 8][bc] = rb[p];
            }
            __syncthreads();
        }
    }

    // attention weights for MODE 1: this thread's 8 cols live in head tx>>2
    float avs[8], avd[8];
    if (MODE == 1) {
        const int h = tx >> 2, cb = (tx & 3) * 8;
        *(float4*)(avs)     = *(const float4*)(asw + h * 32 + cb);
        *(float4*)(avs + 4) = *(const float4*)(asw + h * 32 + cb + 4);
        *(float4*)(avd)     = *(const float4*)(adw + h * 32 + cb);
        *(float4*)(avd + 4) = *(const float4*)(adw + h * 32 + cb + 4);
    }
    float bss[8], bsq[8];
    if (MODE == 2) {
        #pragma unroll
        for (int j = 0; j < 8; j++) { bss[j] = 0.f; bsq[j] = 0.f; }
    }

    #pragma unroll
    for (int i = 0; i < 8; i++) {
        int gr = bm + ty * 8 + i;
        float o8[8];
        #pragma unroll
        for (int j = 0; j < 4; j++) {
            float2 f = *(float2*)&acc[i][j];
            o8[2 * j] = f.x * scale; o8[2 * j + 1] = f.y * scale;
        }
        if (MODE == 1) {
            float s = 0.f, d = 0.f;
            #pragma unroll
            for (int j = 0; j < 8; j++) { s += o8[j] * avs[j]; d += o8[j] * avd[j]; }
            s += __shfl_xor_sync(0xffffffffu, s, 1);
            s += __shfl_xor_sync(0xffffffffu, s, 2);
            d += __shfl_xor_sync(0xffffffffu, d, 1);
            d += __shfl_xor_sync(0xffffffffu, d, 2);
            if ((tx & 3) == 0 && gr < M) {
                g_as[gr * 4 + (tx >> 2)] = s;
                g_ad[gr * 4 + (tx >> 2)] = d;
            }
        }
        if (gr < M) {
            if (MODE == 2) {
                #pragma unroll
                for (int j = 0; j < 8; j++) { bss[j] += o8[j]; bsq[j] += o8[j] * o8[j]; }
            }
            *(float4*)(Y + (size_t)gr * 128 + tx * 8)     = *(float4*)&o8[0];
            *(float4*)(Y + (size_t)gr * 128 + tx * 8 + 4) = *(float4*)&o8[4];
        }
    }

    if (MODE == 2) {
        // block-level column reduce in (reused) smem, then global atomics
        __syncthreads();
        float* ssum = &As[0][0][0];   // [16][128]
        float* ssq  = &Bs[0][0][0];
        #pragma unroll
        for (int j = 0; j < 8; j++) {
            ssum[ty * 128 + tx * 8 + j] = bss[j];
            ssq [ty * 128 + tx * 8 + j] = bsq[j];
        }
        __syncthreads();
        if (tid < 128) {
            float s = 0.f, q = 0.f;
            #pragma unroll
            for (int t = 0; t < 16; t++) { s += ssum[t * 128 + tid]; q += ssq[t * 128 + tid]; }
            atomicAdd(&g_bnsum[tid], s);
            atomicAdd(&g_bnsq[tid], q);
        }
    }
}

// ---------------------------------------------------------------------------
// Layer-2 attention precompute:  u_s[h*128+c] = sum_j W2[c, h*128+j]*as2[h,j]
// ---------------------------------------------------------------------------
__global__ void prep_u_kernel(const float* __restrict__ W2,
                              const float* __restrict__ as2,
                              const float* __restrict__ ad2) {
    int t = blockIdx.x * blockDim.x + threadIdx.x;
    if (t >= 512) return;
    int h = t >> 7, c = t & 127;
    const float* wrow = W2 + (size_t)c * 512 + h * 128;
    const float* av = as2 + h * 128;
    const float* dv = ad2 + h * 128;
    float s = 0.f, d = 0.f;
    for (int j = 0; j < 128; j++) { float w = wrow[j]; s += w * av[j]; d += w * dv[j]; }
    g_us[t] = s; g_ud[t] = d;
}

// Repack W2 [128, 512] -> g_w2r [512, 128]: g_w2r[h*128+c][o] = W2[c][h*128+o]
__global__ void repack_w2_kernel(const float* __restrict__ W2) {
    int i = blockIdx.x * blockDim.x + threadIdx.x;
    if (i >= 512 * 128) return;
    int k = i >> 7, o = i & 127, h = k >> 7, c = k & 127;
    g_w2r[i] = W2[(size_t)c * 512 + h * 128 + o];
}

// Layer-2 attention dots from h-space: a_s[n,h] = h[n] . u_s[h]
__global__ __launch_bounds__(256)
void att2_kernel(const float* __restrict__ hb) {
    int gw = (blockIdx.x * blockDim.x + threadIdx.x) >> 5;
    int lane = threadIdx.x & 31;
    if (gw >= NN) return;
    const float4 v = *(const float4*)(hb + (size_t)gw * 128 + lane * 4);
    float s[4], d[4];
    #pragma unroll
    for (int h = 0; h < 4; h++) {
        const float4 us = *(const float4*)(g_us + h * 128 + lane * 4);
        const float4 ud = *(const float4*)(g_ud + h * 128 + lane * 4);
        s[h] = v.x * us.x + v.y * us.y + v.z * us.z + v.w * us.w;
        d[h] = v.x * ud.x + v.y * ud.y + v.z * ud.z + v.w * ud.w;
    }
    #pragma unroll
    for (int o = 16; o; o >>= 1) {
        #pragma unroll
        for (int h = 0; h < 4; h++) {
            s[h] += __shfl_xor_sync(0xffffffffu, s[h], o);
            d[h] += __shfl_xor_sync(0xffffffffu, d[h], o);
        }
    }
    if (lane == 0) {
        #pragma unroll
        for (int h = 0; h < 4; h++) { g_as[gw * 4 + h] = s[h]; g_ad[gw * 4 + h] = d[h]; }
    }
}

// ---------------------------------------------------------------------------
// Softmax context: per-head max + inverse sum for node n's incoming edges
// ---------------------------------------------------------------------------
struct SoftCtx { float m0, m1, m2, m3, i0, i1, i2, i3; float4 adv; };

__device__ __forceinline__ SoftCtx softmax_ctx(int rs, int re, int n, int lane) {
    SoftCtx c;
    c.adv = *(const float4*)(g_ad + 4 * n);
    float m0 = -1e30f, m1 = -1e30f, m2 = -1e30f, m3 = -1e30f;
    for (int idx = rs + lane; idx < re; idx += 32) {
        int s = g_csrc[idx];
        float4 a = __ldg((const float4*)(g_as + 4 * s));
        m0 = fmaxf(m0, lrelu(a.x + c.adv.x));
        m1 = fmaxf(m1, lrelu(a.y + c.adv.y));
        m2 = fmaxf(m2, lrelu(a.z + c.adv.z));
        m3 = fmaxf(m3, lrelu(a.w + c.adv.w));
    }
    #pragma unroll
    for (int o = 16; o; o >>= 1) {
        m0 = fmaxf(m0, __shfl_xor_sync(0xffffffffu, m0, o));
        m1 = fmaxf(m1, __shfl_xor_sync(0xffffffffu, m1, o));
        m2 = fmaxf(m2, __shfl_xor_sync(0xffffffffu, m2, o));
        m3 = fmaxf(m3, __shfl_xor_sync(0xffffffffu, m3, o));
    }
    float s0 = 0.f, s1 = 0.f, s2 = 0.f, s3 = 0.f;
    for (int idx = rs + lane; idx < re; idx += 32) {
        int s = g_csrc[idx];
        float4 a = __ldg((const float4*)(g_as + 4 * s));
        s0 += __expf(lrelu(a.x + c.adv.x) - m0);
        s1 += __expf(lrelu(a.y + c.adv.y) - m1);
        s2 += __expf(lrelu(a.z + c.adv.z) - m2);
        s3 += __expf(lrelu(a.w + c.adv.w) - m3);
    }
    #pragma unroll
    for (int o = 16; o; o >>= 1) {
        s0 += __shfl_xor_sync(0xffffffffu, s0, o);
        s1 += __shfl_xor_sync(0xffffffffu, s1, o);
        s2 += __shfl_xor_sync(0xffffffffu, s2, o);
        s3 += __shfl_xor_sync(0xffffffffu, s3, o);
    }
    c.m0 = m0; c.m1 = m1; c.m2 = m2; c.m3 = m3;
    c.i0 = 1.f / (s0 + 1e-16f); c.i1 = 1.f / (s1 + 1e-16f);
    c.i2 = 1.f / (s2 + 1e-16f); c.i3 = 1.f / (s3 + 1e-16f);
    return c;
}

// ---------------------------------------------------------------------------
// Concat aggregation (layers 0/1): persistent warps + fused BN stats.
// Bias omitted: a per-column constant cancels exactly under BatchNorm.
// ---------------------------------------------------------------------------
__global__ __launch_bounds__(256)
void aggregate_kernel(const float* __restrict__ xp, float* __restrict__ ob) {
    const int lane = threadIdx.x & 31, w = threadIdx.x >> 5;
    const int gwarp = blockIdx.x * 8 + w;
    const int nwarps = gridDim.x * 8;
    float bs[4] = {0.f, 0.f, 0.f, 0.f}, bq[4] = {0.f, 0.f, 0.f, 0.f};

    for (int n = gwarp; n < NN; n += nwarps) {
        const int rs = g_rowptr[n], re = g_rowptr[n + 1];
        SoftCtx cx = softmax_ctx(rs, re, n, lane);

        float acc0 = 0.f, acc1 = 0.f, acc2 = 0.f, acc3 = 0.f;
        for (int idx = rs; idx < re; idx += 32) {
            int myi = idx + lane;
            int s = 0;
            float w0 = 0.f, w1 = 0.f, w2 = 0.f, w3 = 0.f;
            if (myi < re) {
                s = g_csrc[myi];
                float4 a = __ldg((const float4*)(g_as + 4 * s));
                w0 = __expf(lrelu(a.x + cx.adv.x) - cx.m0) * cx.i0;
                w1 = __expf(lrelu(a.y + cx.adv.y) - cx.m1) * cx.i1;
                w2 = __expf(lrelu(a.z + cx.adv.z) - cx.m2) * cx.i2;
                w3 = __expf(lrelu(a.w + cx.adv.w) - cx.m3) * cx.i3;
            }
            int cnt = min(32, re - idx);
            for (int j = 0; j < cnt; j++) {
                int sj   = __shfl_sync(0xffffffffu, s,  j);
                float b0 = __shfl_sync(0xffffffffu, w0, j);
                float b1 = __shfl_sync(0xffffffffu, w1, j);
                float b2 = __shfl_sync(0xffffffffu, w2, j);
                float b3 = __shfl_sync(0xffffffffu, w3, j);
                float ww = (lane < 16) ? (lane < 8 ? b0 : b1) : (lane < 24 ? b2 : b3);
                float4 v = __ldg((const float4*)(xp + (size_t)sj * 128 + lane * 4));
                acc0 += ww * v.x; acc1 += ww * v.y; acc2 += ww * v.z; acc3 += ww * v.w;
            }
        }
        float* dst = ob + (size_t)n * 128 + lane * 4;
        dst[0] = acc0; dst[1] = acc1; dst[2] = acc2; dst[3] = acc3;
        bs[0] += acc0; bq[0] += acc0 * acc0;
        bs[1] += acc1; bq[1] += acc1 * acc1;
        bs[2] += acc2; bq[2] += acc2 * acc2;
        bs[3] += acc3; bq[3] += acc3 * acc3;
    }

    __shared__ float ssum[8][128];
    __shared__ float ssq[8][128];
    #pragma unroll
    for (int k = 0; k < 4; k++) { ssum[w][lane * 4 + k] = bs[k]; ssq[w][lane * 4 + k] = bq[k]; }
    __syncthreads();
    if (threadIdx.x < 128) {
        float s = 0.f, q = 0.f;
        #pragma unroll
        for (int j = 0; j < 8; j++) { s += ssum[j][threadIdx.x]; q += ssq[j][threadIdx.x]; }
        atomicAdd(&g_bnsum[threadIdx.x], s);
        atomicAdd(&g_bnsq[threadIdx.x], q);
    }
}

// ---------------------------------------------------------------------------
// Layer-2 aggregation in h-space: agg[n, h*128+c] = sum_e alpha[e,h] * h[src, c]
// ---------------------------------------------------------------------------
__global__ __launch_bounds__(256)
void aggregate2_kernel(const float* __restrict__ hb, float* __restrict__ agg) {
    int n = (blockIdx.x * blockDim.x + threadIdx.x) >> 5;
    int lane = threadIdx.x & 31;
    if (n >= NN) return;
    const int rs = g_rowptr[n], re = g_rowptr[n + 1];
    SoftCtx cx = softmax_ctx(rs, re, n, lane);

    float acc[4][4];
    #pragma unroll
    for (int h = 0; h < 4; h++)
        #pragma unroll
        for (int k = 0; k < 4; k++) acc[h][k] = 0.f;

    for (int idx = rs; idx < re; idx += 32) {
        int myi = idx + lane;
        int s = 0;
        float w0 = 0.f, w1 = 0.f, w2 = 0.f, w3 = 0.f;
        if (myi < re) {
            s = g_csrc[myi];
            float4 a = __ldg((const float4*)(g_as + 4 * s));
            w0 = __expf(lrelu(a.x + cx.adv.x) - cx.m0) * cx.i0;
            w1 = __expf(lrelu(a.y + cx.adv.y) - cx.m1) * cx.i1;
            w2 = __expf(lrelu(a.z + cx.adv.z) - cx.m2) * cx.i2;
            w3 = __expf(lrelu(a.w + cx.adv.w) - cx.m3) * cx.i3;
        }
        int cnt = min(32, re - idx);
        for (int j = 0; j < cnt; j++) {
            int sj   = __shfl_sync(0xffffffffu, s,  j);
            float b0 = __shfl_sync(0xffffffffu, w0, j);
            float b1 = __shfl_sync(0xffffffffu, w1, j);
            float b2 = __shfl_sync(0xffffffffu, w2, j);
            float b3 = __shfl_sync(0xffffffffu, w3, j);
            float4 v = __ldg((const float4*)(hb + (size_t)sj * 128 + lane * 4));
            acc[0][0] += b0 * v.x; acc[0][1] += b0 * v.y; acc[0][2] += b0 * v.z; acc[0][3] += b0 * v.w;
            acc[1][0] += b1 * v.x; acc[1][1] += b1 * v.y; acc[1][2] += b1 * v.z; acc[1][3] += b1 * v.w;
            acc[2][0] += b2 * v.x; acc[2][1] += b2 * v.y; acc[2][2] += b2 * v.z; acc[2][3] += b2 * v.w;
            acc[3][0] += b3 * v.x; acc[3][1] += b3 * v.y; acc[3][2] += b3 * v.z; acc[3][3] += b3 * v.w;
        }
    }
    #pragma unroll
    for (int h = 0; h < 4; h++)
        *(float4*)(agg + (size_t)n * 512 + h * 128 + lane * 4) = *(float4*)acc[h];
}

// ---------------------------------------------------------------------------
// BatchNorm
// ---------------------------------------------------------------------------
__global__ void bn_zero_kernel() {
    if (threadIdx.x < 128) { g_bnsum[threadIdx.x] = 0.f; g_bnsq[threadIdx.x] = 0.f; }
}

template <bool ELU>
__global__ __launch_bounds__(256)
void bn_apply_kernel(const float* __restrict__ in, const float* __restrict__ gamma,
                     const float* __restrict__ beta, float* __restrict__ out) {
    int i = blockIdx.x * blockDim.x + threadIdx.x;
    if (i >= NN * 128) return;
    int col = i & 127;
    const float invN = 1.f / (float)NN;
    float mu  = g_bnsum[col] * invN;
    float var = g_bnsq[col] * invN - mu * mu;
    float sc  = gamma[col] * rsqrtf(var + 1e-5f);
    float y   = (in[i] - mu) * sc + beta[col];
    if (ELU) y = (y > 0.f) ? y : expm1f(y);
    out[i] = y;
}

// ---------------------------------------------------------------------------
// Launch
// ---------------------------------------------------------------------------
extern "C" void kernel_launch(void* const* d_in, const int* in_sizes, int n_in,
                              void* d_out, int out_size) {
    const float* x   = (const float*)d_in[0];
    const void*  ei  = d_in[1];
    const float* W0  = (const float*)d_in[2];
    const float* as0 = (const float*)d_in[3];
    const float* ad0 = (const float*)d_in[4];
    const float* g0  = (const float*)d_in[6];
    const float* be0 = (const float*)d_in[7];
    const float* W1  = (const float*)d_in[8];
    const float* as1 = (const float*)d_in[9];
    const float* ad1 = (const float*)d_in[10];
    const float* g1  = (const float*)d_in[12];
    const float* be1 = (const float*)d_in[13];
    const float* W2  = (const float*)d_in[14];
    const float* as2 = (const float*)d_in[15];
    const float* ad2 = (const float*)d_in[16];
    const float* g2  = (const float*)d_in[18];
    const float* be2 = (const float*)d_in[19];
    float* out = (float*)d_out;

    float* xp; cudaGetSymbolAddress((void**)&xp, g_xp);
    float* hb; cudaGetSymbolAddress((void**)&hb, g_h);
    float* ob; cudaGetSymbolAddress((void**)&ob, g_ob);
    float* w2r; cudaGetSymbolAddress((void**)&w2r, g_w2r);

    const int nb_n  = (NN + 255) / 256;
    const int nb_e  = (EP + 255) / 256;
    const int nb_n8 = (NN + 7) / 8;           // warp-per-node kernels
    const int nb_el = (NN * 128 + 255) / 256;
    const dim3 gemm((NN + 127) / 128, 1);

    // Launch index 3 (profiled) = L0 SGEMM: independent of the CSR build.
    detect_kernel<<<1, 64>>>(ei);
    zero_deg_kernel<<<nb_n, 256>>>();
    decode_kernel<<<nb_e, 256>>>(ei);
    sgemm_kernel<128, 1><<<gemm, 256>>>(x, W0, xp, NN, 1.f, as0, ad0);   // + att dots

    // CSR build (overlaps nothing, but independent of sgemm result)
    block_sum_kernel<<<NB, 256>>>();
    scan_bsum_kernel<<<1, 256>>>();
    scan_fill_kernel<<<NB, 256>>>();
    scatter_kernel<<<nb_e, 256>>>();

    // ---- Layer 0 rest ----
    bn_zero_kernel<<<1, 128>>>();
    aggregate_kernel<<<1480, 256>>>(xp, ob);
    bn_apply_kernel<true><<<nb_el, 256>>>(ob, g0, be0, hb);

    // ---- Layer 1 ----
    sgemm_kernel<128, 1><<<gemm, 256>>>(hb, W1, xp, NN, 1.f, as1, ad1);  // + att dots
    bn_zero_kernel<<<1, 128>>>();
    aggregate_kernel<<<1480, 256>>>(xp, ob);
    bn_apply_kernel<true><<<nb_el, 256>>>(ob, g1, be1, hb);

    // ---- Layer 2: aggregate in h-space, then W2 GEMM (heads averaged) ----
    prep_u_kernel<<<2, 256>>>(W2, as2, ad2);
    repack_w2_kernel<<<256, 256>>>(W2);
    att2_kernel<<<nb_n8, 256>>>(hb);
    aggregate2_kernel<<<nb_n8, 256>>>(hb, xp);          // xp <- [N,512] agg
    bn_zero_kernel<<<1, 128>>>();
    sgemm_kernel<512, 2><<<gemm, 256>>>(xp, w2r, ob, NN, 0.25f, nullptr, nullptr); // + BN stats
    bn_apply_kernel<false><<<nb_el, 256>>>(ob, g2, be2, out);

    (void)in_sizes; (void)n_in; (void)out_size;
}

// round 10
// speedup vs baseline: 1.3080x; 1.0288x over previous
#include <cuda_runtime.h>
#include <cuda_bf16.h>
#include <cstdint>

// Problem constants
#define NN     50000
#define EE     800000
#define EP     (EE + NN)      // edges + self loops = 850000
#define HEADS  4
#define NB     ((NN + 255) / 256)   // 196 scan blocks

// ---------------------------------------------------------------------------
// Scratch (static device globals; no runtime allocation)
// ---------------------------------------------------------------------------
__device__ __align__(16) float g_xp[(size_t)NN * 512];   // GEMM out / L2 agg buffer
__device__ __align__(16) float g_h [(size_t)NN * 128];   // layer activations
__device__ __align__(16) float g_ob[(size_t)NN * 128];   // pre-BN buffer
__device__ __align__(16) float g_as[NN * 4];             // a_src per (node, head)
__device__ __align__(16) float g_ad[NN * 4];             // a_dst per (node, head)
__device__ __align__(16) float g_w2r[512 * 128];         // repacked W2: [h*128+c][o]
__device__ __align__(16) float g_us[512];                // u_src[h*128+c]
__device__ __align__(16) float g_ud[512];                // u_dst[h*128+c]
__device__ int g_rowptr[NN + 1];
__device__ int g_cursor[NN];
__device__ int g_deg[NN];
__device__ int g_csrc[EP];
__device__ int g_src[EP];
__device__ int g_dst[EP];
__device__ int g_bsum[256];
__device__ int g_boff[256];
__device__ int g_is64;
__device__ float g_bnsum[128];
__device__ float g_bnsq[128];

__device__ __forceinline__ float lrelu(float x) { return x > 0.f ? x : 0.2f * x; }

// ---------------------------------------------------------------------------
// Edge-index dtype detection (JAX may emit int32 despite int64 in reference)
// ---------------------------------------------------------------------------
__global__ void detect_kernel(const void* ei) {
    __shared__ int ok;
    if (threadIdx.x == 0) ok = 1;
    __syncthreads();
    const long long* p = (const long long*)ei;   // 512B read: safe either way
    long long v = p[threadIdx.x];
    if (v < 0 || v >= NN) ok = 0;
    __syncthreads();
    if (threadIdx.x == 0) g_is64 = ok;
}

__global__ void zero_deg_kernel() {
    int i = blockIdx.x * blockDim.x + threadIdx.x;
    if (i < NN) g_deg[i] = 0;
}

// decode edges (+self loops) and build degree histogram in one pass
__global__ void decode_kernel(const void* ei) {
    int i = blockIdx.x * blockDim.x + threadIdx.x;
    if (i >= EP) return;
    int src, dst;
    if (i >= EE) {
        src = i - EE; dst = i - EE;
    } else if (g_is64) {
        const long long* p = (const long long*)ei;
        src = (int)p[i]; dst = (int)p[EE + i];
    } else {
        const int* p = (const int*)ei;
        src = p[i]; dst = p[EE + i];
    }
    g_src[i] = src; g_dst[i] = dst;
    atomicAdd(&g_deg[dst], 1);
}

// ---------------------------------------------------------------------------
// Hierarchical exclusive scan of g_deg (3 fully-parallel kernels)
// ---------------------------------------------------------------------------
__global__ __launch_bounds__(256) void block_sum_kernel() {
    int t = threadIdx.x, lane = t & 31, w = t >> 5;
    int idx = blockIdx.x * 256 + t;
    int v = (idx < NN) ? g_deg[idx] : 0;
    #pragma unroll
    for (int o = 16; o; o >>= 1) v += __shfl_xor_sync(0xffffffffu, v, o);
    __shared__ int wt[8];
    if (lane == 0) wt[w] = v;
    __syncthreads();
    if (t == 0) {
        int s = 0;
        #pragma unroll
        for (int j = 0; j < 8; j++) s += wt[j];
        g_bsum[blockIdx.x] = s;
    }
}

__global__ __launch_bounds__(256) void scan_bsum_kernel() {
    int t = threadIdx.x, lane = t & 31, w = t >> 5;
    int v = (t < NB) ? g_bsum[t] : 0;
    int incl = v;
    #pragma unroll
    for (int o = 1; o < 32; o <<= 1) {
        int u = __shfl_up_sync(0xffffffffu, incl, o);
        if (lane >= o) incl += u;
    }
    __shared__ int wt[8];
    if (lane == 31) wt[w] = incl;
    __syncthreads();
    if (w == 0 && lane < 8) {
        int x = wt[lane];
        #pragma unroll
        for (int o = 1; o < 8; o <<= 1) {
            int u = __shfl_up_sync(0xffu, x, o);
            if (lane >= o) x += u;
        }
        wt[lane] = x;
    }
    __syncthreads();
    int off = (w ? wt[w - 1] : 0);
    if (t < NB) g_boff[t] = off + incl - v;   // exclusive
}

__global__ __launch_bounds__(256) void scan_fill_kernel() {
    int t = threadIdx.x, lane = t & 31, w = t >> 5;
    int idx = blockIdx.x * 256 + t;
    int v = (idx < NN) ? g_deg[idx] : 0;
    int incl = v;
    #pragma unroll
    for (int o = 1; o < 32; o <<= 1) {
        int u = __shfl_up_sync(0xffffffffu, incl, o);
        if (lane >= o) incl += u;
    }
    __shared__ int wt[8];
    if (lane == 31) wt[w] = incl;
    __syncthreads();
    if (w == 0 && lane < 8) {
        int x = wt[lane];
        #pragma unroll
        for (int o = 1; o < 8; o <<= 1) {
            int u = __shfl_up_sync(0xffu, x, o);
            if (lane >= o) x += u;
        }
        wt[lane] = x;
    }
    __syncthreads();
    int ex = g_boff[blockIdx.x] + (w ? wt[w - 1] : 0) + incl - v;
    if (idx < NN) { g_rowptr[idx] = ex; g_cursor[idx] = ex; }
    if (idx == NN - 1) g_rowptr[NN] = ex + v;
}

__global__ void scatter_kernel() {
    int i = blockIdx.x * blockDim.x + threadIdx.x;
    if (i >= EP) return;
    int pos = atomicAdd(&g_cursor[g_dst[i]], 1);
    g_csrc[pos] = g_src[i];
}

// ---------------------------------------------------------------------------
// SGEMM: Y[M,128] = scale * X[M,KD] @ W[KD,128]. 128x128 tile, 8x8/thread,
// double-buffered smem, packed fma.rn.f32x2 core. B operands fetched as
// ld.shared.v2.b64 (LDS.128 -> two packed f32x2 pairs, no repack movs):
// 4 LDS per k-step instead of 6 (round-9 ncu: L1=67% = LDS-bound).
// MODE 1: fused attention-dot epilogue (writes g_as/g_ad).
// MODE 2: fused BN-stats epilogue (atomics into g_bnsum/g_bnsq).
// ---------------------------------------------------------------------------
template <int KD, int MODE>
__global__ __launch_bounds__(256, 2)
void sgemm_kernel(const float* __restrict__ X, const float* __restrict__ W,
                  float* __restrict__ Y, int M, float scale,
                  const float* __restrict__ asw, const float* __restrict__ adw) {
    __shared__ __align__(16) float As[2][16][128];
    __shared__ __align__(16) float Bs[2][16][128];
    const int bm = blockIdx.x * 128;
    const int tid = threadIdx.x;
    const int tx = tid & 15, ty = tid >> 4;
    const int KT = KD / 16;

    unsigned long long acc[8][4];
    #pragma unroll
    for (int i = 0; i < 8; i++)
        #pragma unroll
        for (int j = 0; j < 4; j++) acc[i][j] = 0ull;

    const int ar = tid >> 2, ac = (tid & 3) * 4;      // A-load coords
    const int br = tid >> 5, bc = (tid & 31) * 4;     // B-load coords
    // shared-space byte address of Bs[0][0][tx*8]
    const uint32_t bsm = (uint32_t)__cvta_generic_to_shared(&Bs[0][0][0]) + tx * 32u;

    float4 ra[2], rb[2];
    // prologue: tile 0
    #pragma unroll
    for (int p = 0; p < 2; p++) {
        int gr = bm + ar + p * 64;
        ra[p] = make_float4(0.f, 0.f, 0.f, 0.f);
        if (gr < M) ra[p] = *(const float4*)(X + (size_t)gr * KD + ac);
        rb[p] = *(const float4*)(W + (size_t)(br + p * 8) * 128 + bc);
    }
    #pragma unroll
    for (int p = 0; p < 2; p++) {
        int r = ar + p * 64;
        As[0][ac + 0][r] = ra[p].x; As[0][ac + 1][r] = ra[p].y;
        As[0][ac + 2][r] = ra[p].z; As[0][ac + 3][r] = ra[p].w;
        *(float4*)&Bs[0][br + p * 8][bc] = rb[p];
    }
    __syncthreads();

    for (int kt = 0; kt < KT; kt++) {
        const int cur = kt & 1;
        const bool has_next = (kt + 1 < KT);
        if (has_next) {
            const int k0 = (kt + 1) * 16;
            #pragma unroll
            for (int p = 0; p < 2; p++) {
                int gr = bm + ar + p * 64;
                ra[p] = make_float4(0.f, 0.f, 0.f, 0.f);
                if (gr < M) ra[p] = *(const float4*)(X + (size_t)gr * KD + k0 + ac);
                rb[p] = *(const float4*)(W + (size_t)(k0 + br + p * 8) * 128 + bc);
            }
        }
        const uint32_t bbuf = bsm + (uint32_t)cur * 8192u;
        #pragma unroll
        for (int k = 0; k < 16; k++) {
            float a[8];
            *(float4*)(a)     = *(const float4*)&As[cur][k][ty * 8];
            *(float4*)(a + 4) = *(const float4*)&As[cur][k][ty * 8 + 4];
            unsigned long long bp[4];
            asm volatile("ld.shared.v2.b64 {%0, %1}, [%2];"
                         : "=l"(bp[0]), "=l"(bp[1]) : "r"(bbuf + k * 512u));
            asm volatile("ld.shared.v2.b64 {%0, %1}, [%2];"
                         : "=l"(bp[2]), "=l"(bp[3]) : "r"(bbuf + k * 512u + 16u));
            #pragma unroll
            for (int i = 0; i < 8; i++) {
                unsigned long long aa;
                unsigned int au = __float_as_uint(a[i]);
                asm("mov.b64 %0, {%1, %1};" : "=l"(aa) : "r"(au));
                #pragma unroll
                for (int j = 0; j < 4; j++)
                    asm("fma.rn.f32x2 %0, %1, %2, %3;"
                        : "=l"(acc[i][j]) : "l"(aa), "l"(bp[j]), "l"(acc[i][j]));
            }
        }
        if (has_next) {
            const int nxt = (kt + 1) & 1;
            #pragma unroll
            for (int p = 0; p < 2; p++) {
                int r = ar + p * 64;
                As[nxt][ac + 0][r] = ra[p].x; As[nxt][ac + 1][r] = ra[p].y;
                As[nxt][ac + 2][r] = ra[p].z; As[nxt][ac + 3][r] = ra[p].w;
                *(float4*)&Bs[nxt][br + p * 8][bc] = rb[p];
            }
            __syncthreads();
        }
    }

    // attention weights for MODE 1: this thread's 8 cols live in head tx>>2
    float avs[8], avd[8];
    if (MODE == 1) {
        const int h = tx >> 2, cb = (tx & 3) * 8;
        *(float4*)(avs)     = *(const float4*)(asw + h * 32 + cb);
        *(float4*)(avs + 4) = *(const float4*)(asw + h * 32 + cb + 4);
        *(float4*)(avd)     = *(const float4*)(adw + h * 32 + cb);
        *(float4*)(avd + 4) = *(const float4*)(adw + h * 32 + cb + 4);
    }
    float bss[8], bsq[8];
    if (MODE == 2) {
        #pragma unroll
        for (int j = 0; j < 8; j++) { bss[j] = 0.f; bsq[j] = 0.f; }
    }

    #pragma unroll
    for (int i = 0; i < 8; i++) {
        int gr = bm + ty * 8 + i;
        float o8[8];
        #pragma unroll
        for (int j = 0; j < 4; j++) {
            float2 f = *(float2*)&acc[i][j];
            o8[2 * j] = f.x * scale; o8[2 * j + 1] = f.y * scale;
        }
        if (MODE == 1) {
            float s = 0.f, d = 0.f;
            #pragma unroll
            for (int j = 0; j < 8; j++) { s += o8[j] * avs[j]; d += o8[j] * avd[j]; }
            s += __shfl_xor_sync(0xffffffffu, s, 1);
            s += __shfl_xor_sync(0xffffffffu, s, 2);
            d += __shfl_xor_sync(0xffffffffu, d, 1);
            d += __shfl_xor_sync(0xffffffffu, d, 2);
            if ((tx & 3) == 0 && gr < M) {
                g_as[gr * 4 + (tx >> 2)] = s;
                g_ad[gr * 4 + (tx >> 2)] = d;
            }
        }
        if (gr < M) {
            if (MODE == 2) {
                #pragma unroll
                for (int j = 0; j < 8; j++) { bss[j] += o8[j]; bsq[j] += o8[j] * o8[j]; }
            }
            *(float4*)(Y + (size_t)gr * 128 + tx * 8)     = *(float4*)&o8[0];
            *(float4*)(Y + (size_t)gr * 128 + tx * 8 + 4) = *(float4*)&o8[4];
        }
    }

    if (MODE == 2) {
        // block-level column reduce in (reused) smem, then global atomics
        __syncthreads();
        float* ssum = &As[0][0][0];   // [16][128]
        float* ssq  = &Bs[0][0][0];
        #pragma unroll
        for (int j = 0; j < 8; j++) {
            ssum[ty * 128 + tx * 8 + j] = bss[j];
            ssq [ty * 128 + tx * 8 + j] = bsq[j];
        }
        __syncthreads();
        if (tid < 128) {
            float s = 0.f, q = 0.f;
            #pragma unroll
            for (int t = 0; t < 16; t++) { s += ssum[t * 128 + tid]; q += ssq[t * 128 + tid]; }
            atomicAdd(&g_bnsum[tid], s);
            atomicAdd(&g_bnsq[tid], q);
        }
    }
}

// ---------------------------------------------------------------------------
// Layer-2 attention precompute:  u_s[h*128+c] = sum_j W2[c, h*128+j]*as2[h,j]
// ---------------------------------------------------------------------------
__global__ void prep_u_kernel(const float* __restrict__ W2,
                              const float* __restrict__ as2,
                              const float* __restrict__ ad2) {
    int t = blockIdx.x * blockDim.x + threadIdx.x;
    if (t >= 512) return;
    int h = t >> 7, c = t & 127;
    const float* wrow = W2 + (size_t)c * 512 + h * 128;
    const float* av = as2 + h * 128;
    const float* dv = ad2 + h * 128;
    float s = 0.f, d = 0.f;
    for (int j = 0; j < 128; j++) { float w = wrow[j]; s += w * av[j]; d += w * dv[j]; }
    g_us[t] = s; g_ud[t] = d;
}

// Repack W2 [128, 512] -> g_w2r [512, 128]: g_w2r[h*128+c][o] = W2[c][h*128+o]
__global__ void repack_w2_kernel(const float* __restrict__ W2) {
    int i = blockIdx.x * blockDim.x + threadIdx.x;
    if (i >= 512 * 128) return;
    int k = i >> 7, o = i & 127, h = k >> 7, c = k & 127;
    g_w2r[i] = W2[(size_t)c * 512 + h * 128 + o];
}

// Layer-2 attention dots from h-space: a_s[n,h] = h[n] . u_s[h]
__global__ __launch_bounds__(256)
void att2_kernel(const float* __restrict__ hb) {
    int gw = (blockIdx.x * blockDim.x + threadIdx.x) >> 5;
    int lane = threadIdx.x & 31;
    if (gw >= NN) return;
    const float4 v = *(const float4*)(hb + (size_t)gw * 128 + lane * 4);
    float s[4], d[4];
    #pragma unroll
    for (int h = 0; h < 4; h++) {
        const float4 us = *(const float4*)(g_us + h * 128 + lane * 4);
        const float4 ud = *(const float4*)(g_ud + h * 128 + lane * 4);
        s[h] = v.x * us.x + v.y * us.y + v.z * us.z + v.w * us.w;
        d[h] = v.x * ud.x + v.y * ud.y + v.z * ud.z + v.w * ud.w;
    }
    #pragma unroll
    for (int o = 16; o; o >>= 1) {
        #pragma unroll
        for (int h = 0; h < 4; h++) {
            s[h] += __shfl_xor_sync(0xffffffffu, s[h], o);
            d[h] += __shfl_xor_sync(0xffffffffu, d[h], o);
        }
    }
    if (lane == 0) {
        #pragma unroll
        for (int h = 0; h < 4; h++) { g_as[gw * 4 + h] = s[h]; g_ad[gw * 4 + h] = d[h]; }
    }
}

// ---------------------------------------------------------------------------
// Softmax context: per-head max + inverse sum for node n's incoming edges
// ---------------------------------------------------------------------------
struct SoftCtx { float m0, m1, m2, m3, i0, i1, i2, i3; float4 adv; };

__device__ __forceinline__ SoftCtx softmax_ctx(int rs, int re, int n, int lane) {
    SoftCtx c;
    c.adv = *(const float4*)(g_ad + 4 * n);
    float m0 = -1e30f, m1 = -1e30f, m2 = -1e30f, m3 = -1e30f;
    for (int idx = rs + lane; idx < re; idx += 32) {
        int s = g_csrc[idx];
        float4 a = __ldg((const float4*)(g_as + 4 * s));
        m0 = fmaxf(m0, lrelu(a.x + c.adv.x));
        m1 = fmaxf(m1, lrelu(a.y + c.adv.y));
        m2 = fmaxf(m2, lrelu(a.z + c.adv.z));
        m3 = fmaxf(m3, lrelu(a.w + c.adv.w));
    }
    #pragma unroll
    for (int o = 16; o; o >>= 1) {
        m0 = fmaxf(m0, __shfl_xor_sync(0xffffffffu, m0, o));
        m1 = fmaxf(m1, __shfl_xor_sync(0xffffffffu, m1, o));
        m2 = fmaxf(m2, __shfl_xor_sync(0xffffffffu, m2, o));
        m3 = fmaxf(m3, __shfl_xor_sync(0xffffffffu, m3, o));
    }
    float s0 = 0.f, s1 = 0.f, s2 = 0.f, s3 = 0.f;
    for (int idx = rs + lane; idx < re; idx += 32) {
        int s = g_csrc[idx];
        float4 a = __ldg((const float4*)(g_as + 4 * s));
        s0 += __expf(lrelu(a.x + c.adv.x) - m0);
        s1 += __expf(lrelu(a.y + c.adv.y) - m1);
        s2 += __expf(lrelu(a.z + c.adv.z) - m2);
        s3 += __expf(lrelu(a.w + c.adv.w) - m3);
    }
    #pragma unroll
    for (int o = 16; o; o >>= 1) {
        s0 += __shfl_xor_sync(0xffffffffu, s0, o);
        s1 += __shfl_xor_sync(0xffffffffu, s1, o);
        s2 += __shfl_xor_sync(0xffffffffu, s2, o);
        s3 += __shfl_xor_sync(0xffffffffu, s3, o);
    }
    c.m0 = m0; c.m1 = m1; c.m2 = m2; c.m3 = m3;
    c.i0 = 1.f / (s0 + 1e-16f); c.i1 = 1.f / (s1 + 1e-16f);
    c.i2 = 1.f / (s2 + 1e-16f); c.i3 = 1.f / (s3 + 1e-16f);
    return c;
}

// ---------------------------------------------------------------------------
// Concat aggregation (layers 0/1): persistent warps + fused BN stats.
// Bias omitted: a per-column constant cancels exactly under BatchNorm.
// ---------------------------------------------------------------------------
__global__ __launch_bounds__(256)
void aggregate_kernel(const float* __restrict__ xp, float* __restrict__ ob) {
    const int lane = threadIdx.x & 31, w = threadIdx.x >> 5;
    const int gwarp = blockIdx.x * 8 + w;
    const int nwarps = gridDim.x * 8;
    float bs[4] = {0.f, 0.f, 0.f, 0.f}, bq[4] = {0.f, 0.f, 0.f, 0.f};

    for (int n = gwarp; n < NN; n += nwarps) {
        const int rs = g_rowptr[n], re = g_rowptr[n + 1];
        SoftCtx cx = softmax_ctx(rs, re, n, lane);

        float acc0 = 0.f, acc1 = 0.f, acc2 = 0.f, acc3 = 0.f;
        for (int idx = rs; idx < re; idx += 32) {
            int myi = idx + lane;
            int s = 0;
            float w0 = 0.f, w1 = 0.f, w2 = 0.f, w3 = 0.f;
            if (myi < re) {
                s = g_csrc[myi];
                float4 a = __ldg((const float4*)(g_as + 4 * s));
                w0 = __expf(lrelu(a.x + cx.adv.x) - cx.m0) * cx.i0;
                w1 = __expf(lrelu(a.y + cx.adv.y) - cx.m1) * cx.i1;
                w2 = __expf(lrelu(a.z + cx.adv.z) - cx.m2) * cx.i2;
                w3 = __expf(lrelu(a.w + cx.adv.w) - cx.m3) * cx.i3;
            }
            int cnt = min(32, re - idx);
            for (int j = 0; j < cnt; j++) {
                int sj   = __shfl_sync(0xffffffffu, s,  j);
                float b0 = __shfl_sync(0xffffffffu, w0, j);
                float b1 = __shfl_sync(0xffffffffu, w1, j);
                float b2 = __shfl_sync(0xffffffffu, w2, j);
                float b3 = __shfl_sync(0xffffffffu, w3, j);
                float ww = (lane < 16) ? (lane < 8 ? b0 : b1) : (lane < 24 ? b2 : b3);
                float4 v = __ldg((const float4*)(xp + (size_t)sj * 128 + lane * 4));
                acc0 += ww * v.x; acc1 += ww * v.y; acc2 += ww * v.z; acc3 += ww * v.w;
            }
        }
        float* dst = ob + (size_t)n * 128 + lane * 4;
        dst[0] = acc0; dst[1] = acc1; dst[2] = acc2; dst[3] = acc3;
        bs[0] += acc0; bq[0] += acc0 * acc0;
        bs[1] += acc1; bq[1] += acc1 * acc1;
        bs[2] += acc2; bq[2] += acc2 * acc2;
        bs[3] += acc3; bq[3] += acc3 * acc3;
    }

    __shared__ float ssum[8][128];
    __shared__ float ssq[8][128];
    #pragma unroll
    for (int k = 0; k < 4; k++) { ssum[w][lane * 4 + k] = bs[k]; ssq[w][lane * 4 + k] = bq[k]; }
    __syncthreads();
    if (threadIdx.x < 128) {
        float s = 0.f, q = 0.f;
        #pragma unroll
        for (int j = 0; j < 8; j++) { s += ssum[j][threadIdx.x]; q += ssq[j][threadIdx.x]; }
        atomicAdd(&g_bnsum[threadIdx.x], s);
        atomicAdd(&g_bnsq[threadIdx.x], q);
    }
}

// ---------------------------------------------------------------------------
// Layer-2 aggregation in h-space: agg[n, h*128+c] = sum_e alpha[e,h] * h[src, c]
// ---------------------------------------------------------------------------
__global__ __launch_bounds__(256)
void aggregate2_kernel(const float* __restrict__ hb, float* __restrict__ agg) {
    int n = (blockIdx.x * blockDim.x + threadIdx.x) >> 5;
    int lane = threadIdx.x & 31;
    if (n >= NN) return;
    const int rs = g_rowptr[n], re = g_rowptr[n + 1];
    SoftCtx cx = softmax_ctx(rs, re, n, lane);

    float acc[4][4];
    #pragma unroll
    for (int h = 0; h < 4; h++)
        #pragma unroll
        for (int k = 0; k < 4; k++) acc[h][k] = 0.f;

    for (int idx = rs; idx < re; idx += 32) {
        int myi = idx + lane;
        int s = 0;
        float w0 = 0.f, w1 = 0.f, w2 = 0.f, w3 = 0.f;
        if (myi < re) {
            s = g_csrc[myi];
            float4 a = __ldg((const float4*)(g_as + 4 * s));
            w0 = __expf(lrelu(a.x + cx.adv.x) - cx.m0) * cx.i0;
            w1 = __expf(lrelu(a.y + cx.adv.y) - cx.m1) * cx.i1;
            w2 = __expf(lrelu(a.z + cx.adv.z) - cx.m2) * cx.i2;
            w3 = __expf(lrelu(a.w + cx.adv.w) - cx.m3) * cx.i3;
        }
        int cnt = min(32, re - idx);
        for (int j = 0; j < cnt; j++) {
            int sj   = __shfl_sync(0xffffffffu, s,  j);
            float b0 = __shfl_sync(0xffffffffu, w0, j);
            float b1 = __shfl_sync(0xffffffffu, w1, j);
            float b2 = __shfl_sync(0xffffffffu, w2, j);
            float b3 = __shfl_sync(0xffffffffu, w3, j);
            float4 v = __ldg((const float4*)(hb + (size_t)sj * 128 + lane * 4));
            acc[0][0] += b0 * v.x; acc[0][1] += b0 * v.y; acc[0][2] += b0 * v.z; acc[0][3] += b0 * v.w;
            acc[1][0] += b1 * v.x; acc[1][1] += b1 * v.y; acc[1][2] += b1 * v.z; acc[1][3] += b1 * v.w;
            acc[2][0] += b2 * v.x; acc[2][1] += b2 * v.y; acc[2][2] += b2 * v.z; acc[2][3] += b2 * v.w;
            acc[3][0] += b3 * v.x; acc[3][1] += b3 * v.y; acc[3][2] += b3 * v.z; acc[3][3] += b3 * v.w;
        }
    }
    #pragma unroll
    for (int h = 0; h < 4; h++)
        *(float4*)(agg + (size_t)n * 512 + h * 128 + lane * 4) = *(float4*)acc[h];
}

// ---------------------------------------------------------------------------
// BatchNorm
// ---------------------------------------------------------------------------
__global__ void bn_zero_kernel() {
    if (threadIdx.x < 128) { g_bnsum[threadIdx.x] = 0.f; g_bnsq[threadIdx.x] = 0.f; }
}

template <bool ELU>
__global__ __launch_bounds__(256)
void bn_apply_kernel(const float* __restrict__ in, const float* __restrict__ gamma,
                     const float* __restrict__ beta, float* __restrict__ out) {
    int i = blockIdx.x * blockDim.x + threadIdx.x;
    if (i >= NN * 128) return;
    int col = i & 127;
    const float invN = 1.f / (float)NN;
    float mu  = g_bnsum[col] * invN;
    float var = g_bnsq[col] * invN - mu * mu;
    float sc  = gamma[col] * rsqrtf(var + 1e-5f);
    float y   = (in[i] - mu) * sc + beta[col];
    if (ELU) y = (y > 0.f) ? y : expm1f(y);
    out[i] = y;
}

// ---------------------------------------------------------------------------
// Launch
// ---------------------------------------------------------------------------
extern "C" void kernel_launch(void* const* d_in, const int* in_sizes, int n_in,
                              void* d_out, int out_size) {
    const float* x   = (const float*)d_in[0];
    const void*  ei  = d_in[1];
    const float* W0  = (const float*)d_in[2];
    const float* as0 = (const float*)d_in[3];
    const float* ad0 = (const float*)d_in[4];
    const float* g0  = (const float*)d_in[6];
    const float* be0 = (const float*)d_in[7];
    const float* W1  = (const float*)d_in[8];
    const float* as1 = (const float*)d_in[9];
    const float* ad1 = (const float*)d_in[10];
    const float* g1  = (const float*)d_in[12];
    const float* be1 = (const float*)d_in[13];
    const float* W2  = (const float*)d_in[14];
    const float* as2 = (const float*)d_in[15];
    const float* ad2 = (const float*)d_in[16];
    const float* g2  = (const float*)d_in[18];
    const float* be2 = (const float*)d_in[19];
    float* out = (float*)d_out;

    float* xp; cudaGetSymbolAddress((void**)&xp, g_xp);
    float* hb; cudaGetSymbolAddress((void**)&hb, g_h);
    float* ob; cudaGetSymbolAddress((void**)&ob, g_ob);
    float* w2r; cudaGetSymbolAddress((void**)&w2r, g_w2r);

    const int nb_n  = (NN + 255) / 256;
    const int nb_e  = (EP + 255) / 256;
    const int nb_n8 = (NN + 7) / 8;           // warp-per-node kernels
    const int nb_el = (NN * 128 + 255) / 256;
    const dim3 gemm((NN + 127) / 128, 1);

    // Launch index 3 (profiled) = L0 SGEMM: independent of the CSR build.
    detect_kernel<<<1, 64>>>(ei);
    zero_deg_kernel<<<nb_n, 256>>>();
    decode_kernel<<<nb_e, 256>>>(ei);
    sgemm_kernel<128, 1><<<gemm, 256>>>(x, W0, xp, NN, 1.f, as0, ad0);   // + att dots

    // CSR build
    block_sum_kernel<<<NB, 256>>>();
    scan_bsum_kernel<<<1, 256>>>();
    scan_fill_kernel<<<NB, 256>>>();
    scatter_kernel<<<nb_e, 256>>>();

    // ---- Layer 0 rest ----
    bn_zero_kernel<<<1, 128>>>();
    aggregate_kernel<<<1480, 256>>>(xp, ob);
    bn_apply_kernel<true><<<nb_el, 256>>>(ob, g0, be0, hb);

    // ---- Layer 1 ----
    sgemm_kernel<128, 1><<<gemm, 256>>>(hb, W1, xp, NN, 1.f, as1, ad1);  // + att dots
    bn_zero_kernel<<<1, 128>>>();
    aggregate_kernel<<<1480, 256>>>(xp, ob);
    bn_apply_kernel<true><<<nb_el, 256>>>(ob, g1, be1, hb);

    // ---- Layer 2: aggregate in h-space, then W2 GEMM (heads averaged) ----
    prep_u_kernel<<<2, 256>>>(W2, as2, ad2);
    repack_w2_kernel<<<256, 256>>>(W2);
    att2_kernel<<<nb_n8, 256>>>(hb);
    aggregate2_kernel<<<nb_n8, 256>>>(hb, xp);          // xp <- [N,512] agg
    bn_zero_kernel<<<1, 128>>>();
    sgemm_kernel<512, 2><<<gemm, 256>>>(xp, w2r, ob, NN, 0.25f, nullptr, nullptr); // + BN stats
    bn_apply_kernel<false><<<nb_el, 256>>>(ob, g2, be2, out);

    (void)in_sizes; (void)n_in; (void)out_size;
}

// round 12
// speedup vs baseline: 1.3486x; 1.0311x over previous
#include <cuda_runtime.h>
#include <cuda_bf16.h>
#include <cstdint>

// Problem constants
#define NN     50000
#define EE     800000
#define EP     (EE + NN)      // edges + self loops = 850000
#define HEADS  4
#define NB     ((NN + 255) / 256)   // 196 scan blocks

// ---------------------------------------------------------------------------
// Scratch (static device globals; no runtime allocation)
// ---------------------------------------------------------------------------
__device__ __align__(16) float g_xp[(size_t)NN * 512];   // GEMM out / L2 agg buffer
__device__ __align__(16) float g_h [(size_t)NN * 128];   // layer activations
__device__ __align__(16) float g_ob[(size_t)NN * 128];   // pre-BN buffer
__device__ __align__(16) float g_as[NN * 4];             // a_src per (node, head)
__device__ __align__(16) float g_ad[NN * 4];             // a_dst per (node, head)
__device__ __align__(16) float g_w2r[512 * 128];         // repacked W2: [h*128+c][o]
__device__ __align__(16) float g_us[512];                // u_src[h*128+c]
__device__ __align__(16) float g_ud[512];                // u_dst[h*128+c]
__device__ int g_rowptr[NN + 1];
__device__ int g_cursor[NN];
__device__ int g_deg[NN];
__device__ int g_csrc[EP];
__device__ int g_src[EP];
__device__ int g_dst[EP];
__device__ int g_bsum[256];
__device__ int g_boff[256];
__device__ int g_is64;
__device__ float g_bnsum[128];
__device__ float g_bnsq[128];

__device__ __forceinline__ float lrelu(float x) { return x > 0.f ? x : 0.2f * x; }

// ---------------------------------------------------------------------------
// Edge-index dtype detection (JAX may emit int32 despite int64 in reference)
// ---------------------------------------------------------------------------
__global__ void detect_kernel(const void* ei) {
    __shared__ int ok;
    if (threadIdx.x == 0) ok = 1;
    __syncthreads();
    const long long* p = (const long long*)ei;   // 512B read: safe either way
    long long v = p[threadIdx.x];
    if (v < 0 || v >= NN) ok = 0;
    __syncthreads();
    if (threadIdx.x == 0) g_is64 = ok;
}

__global__ void zero_deg_kernel() {
    int i = blockIdx.x * blockDim.x + threadIdx.x;
    if (i < NN) g_deg[i] = 0;
}

// decode edges (+self loops) and build degree histogram in one pass
__global__ void decode_kernel(const void* ei) {
    int i = blockIdx.x * blockDim.x + threadIdx.x;
    if (i >= EP) return;
    int src, dst;
    if (i >= EE) {
        src = i - EE; dst = i - EE;
    } else if (g_is64) {
        const long long* p = (const long long*)ei;
        src = (int)p[i]; dst = (int)p[EE + i];
    } else {
        const int* p = (const int*)ei;
        src = p[i]; dst = p[EE + i];
    }
    g_src[i] = src; g_dst[i] = dst;
    atomicAdd(&g_deg[dst], 1);
}

// ---------------------------------------------------------------------------
// Hierarchical exclusive scan of g_deg (3 fully-parallel kernels)
// ---------------------------------------------------------------------------
__global__ __launch_bounds__(256) void block_sum_kernel() {
    int t = threadIdx.x, lane = t & 31, w = t >> 5;
    int idx = blockIdx.x * 256 + t;
    int v = (idx < NN) ? g_deg[idx] : 0;
    #pragma unroll
    for (int o = 16; o; o >>= 1) v += __shfl_xor_sync(0xffffffffu, v, o);
    __shared__ int wt[8];
    if (lane == 0) wt[w] = v;
    __syncthreads();
    if (t == 0) {
        int s = 0;
        #pragma unroll
        for (int j = 0; j < 8; j++) s += wt[j];
        g_bsum[blockIdx.x] = s;
    }
}

__global__ __launch_bounds__(256) void scan_bsum_kernel() {
    int t = threadIdx.x, lane = t & 31, w = t >> 5;
    int v = (t < NB) ? g_bsum[t] : 0;
    int incl = v;
    #pragma unroll
    for (int o = 1; o < 32; o <<= 1) {
        int u = __shfl_up_sync(0xffffffffu, incl, o);
        if (lane >= o) incl += u;
    }
    __shared__ int wt[8];
    if (lane == 31) wt[w] = incl;
    __syncthreads();
    if (w == 0 && lane < 8) {
        int x = wt[lane];
        #pragma unroll
        for (int o = 1; o < 8; o <<= 1) {
            int u = __shfl_up_sync(0xffu, x, o);
            if (lane >= o) x += u;
        }
        wt[lane] = x;
    }
    __syncthreads();
    int off = (w ? wt[w - 1] : 0);
    if (t < NB) g_boff[t] = off + incl - v;   // exclusive
}

__global__ __launch_bounds__(256) void scan_fill_kernel() {
    int t = threadIdx.x, lane = t & 31, w = t >> 5;
    int idx = blockIdx.x * 256 + t;
    int v = (idx < NN) ? g_deg[idx] : 0;
    int incl = v;
    #pragma unroll
    for (int o = 1; o < 32; o <<= 1) {
        int u = __shfl_up_sync(0xffffffffu, incl, o);
        if (lane >= o) incl += u;
    }
    __shared__ int wt[8];
    if (lane == 31) wt[w] = incl;
    __syncthreads();
    if (w == 0 && lane < 8) {
        int x = wt[lane];
        #pragma unroll
        for (int o = 1; o < 8; o <<= 1) {
            int u = __shfl_up_sync(0xffu, x, o);
            if (lane >= o) x += u;
        }
        wt[lane] = x;
    }
    __syncthreads();
    int ex = g_boff[blockIdx.x] + (w ? wt[w - 1] : 0) + incl - v;
    if (idx < NN) { g_rowptr[idx] = ex; g_cursor[idx] = ex; }
    if (idx == NN - 1) g_rowptr[NN] = ex + v;
}

__global__ void scatter_kernel() {
    int i = blockIdx.x * blockDim.x + threadIdx.x;
    if (i >= EP) return;
    int pos = atomicAdd(&g_cursor[g_dst[i]], 1);
    g_csrc[pos] = g_src[i];
}

// ---------------------------------------------------------------------------
// SGEMM: Y[M,128] = scale * X[M,KD] @ W[KD,128]. 128x128 tile, 8x8/thread.
// Square warp footprint: 8 warps tiled 4(row)x2(col); lane r2=lane>>3,
// c2=lane&7. Per k-step LDS wavefronts: A 2x64B broadcast + B 2x128B
// (chunk-swizzled Bs rows, conflict-free) = 4 wf vs 6 in the tx/ty map.
// BS_ROW = 144: 16 chunks*8 floats + 4-float pad per 4 chunks (max swizzled
// index 139; 132 in round 11 was an OOB bug).
// MODE 1: fused attention-dot epilogue. MODE 2: fused BN-stats epilogue.
// ---------------------------------------------------------------------------
#define BS_ROW 144

template <int KD, int MODE>
__global__ __launch_bounds__(256, 2)
void sgemm_kernel(const float* __restrict__ X, const float* __restrict__ W,
                  float* __restrict__ Y, int M, float scale,
                  const float* __restrict__ asw, const float* __restrict__ adw) {
    __shared__ __align__(16) float As[2][16][128];
    __shared__ __align__(16) float Bs[2][16][BS_ROW];
    const int bm = blockIdx.x * 128;
    const int tid = threadIdx.x;
    const int lane = tid & 31, w = tid >> 5;
    const int r2 = lane >> 3, c2 = lane & 7;
    const int m0 = (w & 3) * 32 + r2 * 8;          // 8 rows m0..m0+7
    const int n0 = (w >> 2) * 64 + c2 * 8;         // 8 cols n0..n0+7
    const int jch = n0 >> 3;                        // B chunk id (0..15)
    const int KT = KD / 16;

    unsigned long long acc[8][4];
    #pragma unroll
    for (int i = 0; i < 8; i++)
        #pragma unroll
        for (int j = 0; j < 4; j++) acc[i][j] = 0ull;

    const int ar = tid >> 2, ac = (tid & 3) * 4;      // A-load coords
    const int br = tid >> 5, bc = (tid & 31) * 4;     // B-load coords
    const int jb = bc >> 3;
    const int bo = jb * 8 + (jb >> 2) * 4 + (bc & 7); // swizzled B float offset
    // shared-space byte address of this thread's B chunk in buffer 0
    const uint32_t bsm = (uint32_t)__cvta_generic_to_shared(&Bs[0][0][0])
                       + (uint32_t)(jch * 32 + (jch >> 2) * 16);

    float4 ra[2], rb[2];
    // prologue: tile 0
    #pragma unroll
    for (int p = 0; p < 2; p++) {
        int gr = bm + ar + p * 64;
        ra[p] = make_float4(0.f, 0.f, 0.f, 0.f);
        if (gr < M) ra[p] = *(const float4*)(X + (size_t)gr * KD + ac);
        rb[p] = *(const float4*)(W + (size_t)(br + p * 8) * 128 + bc);
    }
    #pragma unroll
    for (int p = 0; p < 2; p++) {
        int r = ar + p * 64;
        As[0][ac + 0][r] = ra[p].x; As[0][ac + 1][r] = ra[p].y;
        As[0][ac + 2][r] = ra[p].z; As[0][ac + 3][r] = ra[p].w;
        *(float4*)&Bs[0][br + p * 8][bo] = rb[p];
    }
    __syncthreads();

    for (int kt = 0; kt < KT; kt++) {
        const int cur = kt & 1;
        const bool has_next = (kt + 1 < KT);
        if (has_next) {
            const int k0 = (kt + 1) * 16;
            #pragma unroll
            for (int p = 0; p < 2; p++) {
                int gr = bm + ar + p * 64;
                ra[p] = make_float4(0.f, 0.f, 0.f, 0.f);
                if (gr < M) ra[p] = *(const float4*)(X + (size_t)gr * KD + k0 + ac);
                rb[p] = *(const float4*)(W + (size_t)(k0 + br + p * 8) * 128 + bc);
            }
        }
        const uint32_t bbuf = bsm + (uint32_t)cur * (16 * BS_ROW * 4);
        #pragma unroll
        for (int k = 0; k < 16; k++) {
            float a[8];
            *(float4*)(a)     = *(const float4*)&As[cur][k][m0];
            *(float4*)(a + 4) = *(const float4*)&As[cur][k][m0 + 4];
            unsigned long long bp[4];
            asm volatile("ld.shared.v2.b64 {%0, %1}, [%2];"
                         : "=l"(bp[0]), "=l"(bp[1]) : "r"(bbuf + k * (BS_ROW * 4u)));
            asm volatile("ld.shared.v2.b64 {%0, %1}, [%2];"
                         : "=l"(bp[2]), "=l"(bp[3]) : "r"(bbuf + k * (BS_ROW * 4u) + 16u));
            #pragma unroll
            for (int i = 0; i < 8; i++) {
                unsigned long long aa;
                unsigned int au = __float_as_uint(a[i]);
                asm("mov.b64 %0, {%1, %1};" : "=l"(aa) : "r"(au));
                #pragma unroll
                for (int j = 0; j < 4; j++)
                    asm("fma.rn.f32x2 %0, %1, %2, %3;"
                        : "=l"(acc[i][j]) : "l"(aa), "l"(bp[j]), "l"(acc[i][j]));
            }
        }
        if (has_next) {
            const int nxt = (kt + 1) & 1;
            #pragma unroll
            for (int p = 0; p < 2; p++) {
                int r = ar + p * 64;
                As[nxt][ac + 0][r] = ra[p].x; As[nxt][ac + 1][r] = ra[p].y;
                As[nxt][ac + 2][r] = ra[p].z; As[nxt][ac + 3][r] = ra[p].w;
                *(float4*)&Bs[nxt][br + p * 8][bo] = rb[p];
            }
            __syncthreads();
        }
    }

    // MODE 1: this thread's 8 cols live in head (w>>2)*2 + (c2>>2)
    const int hh = (w >> 2) * 2 + (c2 >> 2);
    float avs[8], avd[8];
    if (MODE == 1) {
        const int cb = (c2 & 3) * 8;   // n0 & 31
        *(float4*)(avs)     = *(const float4*)(asw + hh * 32 + cb);
        *(float4*)(avs + 4) = *(const float4*)(asw + hh * 32 + cb + 4);
        *(float4*)(avd)     = *(const float4*)(adw + hh * 32 + cb);
        *(float4*)(avd + 4) = *(const float4*)(adw + hh * 32 + cb + 4);
    }
    float bss[8], bsq[8];
    if (MODE == 2) {
        #pragma unroll
        for (int j = 0; j < 8; j++) { bss[j] = 0.f; bsq[j] = 0.f; }
    }

    #pragma unroll
    for (int i = 0; i < 8; i++) {
        int gr = bm + m0 + i;
        float o8[8];
        #pragma unroll
        for (int j = 0; j < 4; j++) {
            float2 f = *(float2*)&acc[i][j];
            o8[2 * j] = f.x * scale; o8[2 * j + 1] = f.y * scale;
        }
        if (MODE == 1) {
            float s = 0.f, d = 0.f;
            #pragma unroll
            for (int j = 0; j < 8; j++) { s += o8[j] * avs[j]; d += o8[j] * avd[j]; }
            s += __shfl_xor_sync(0xffffffffu, s, 1);
            s += __shfl_xor_sync(0xffffffffu, s, 2);
            d += __shfl_xor_sync(0xffffffffu, d, 1);
            d += __shfl_xor_sync(0xffffffffu, d, 2);
            if ((c2 & 3) == 0 && gr < M) {
                g_as[gr * 4 + hh] = s;
                g_ad[gr * 4 + hh] = d;
            }
        }
        if (gr < M) {
            if (MODE == 2) {
                #pragma unroll
                for (int j = 0; j < 8; j++) { bss[j] += o8[j]; bsq[j] += o8[j] * o8[j]; }
            }
            *(float4*)(Y + (size_t)gr * 128 + n0)     = *(float4*)&o8[0];
            *(float4*)(Y + (size_t)gr * 128 + n0 + 4) = *(float4*)&o8[4];
        }
    }

    if (MODE == 2) {
        // block-level column reduce in (reused) As smem, then global atomics
        __syncthreads();
        float* ssum = &As[0][0][0];          // [16][128]
        float* ssq  = &As[1][0][0];          // [16][128]
        const int idx16 = (w & 3) * 4 + r2;  // 16 distinct row-groups
        #pragma unroll
        for (int j = 0; j < 8; j++) {
            ssum[idx16 * 128 + n0 + j] = bss[j];
            ssq [idx16 * 128 + n0 + j] = bsq[j];
        }
        __syncthreads();
        if (tid < 128) {
            float s = 0.f, q = 0.f;
            #pragma unroll
            for (int t = 0; t < 16; t++) { s += ssum[t * 128 + tid]; q += ssq[t * 128 + tid]; }
            atomicAdd(&g_bnsum[tid], s);
            atomicAdd(&g_bnsq[tid], q);
        }
    }
}

// ---------------------------------------------------------------------------
// Layer-2 attention precompute:  u_s[h*128+c] = sum_j W2[c, h*128+j]*as2[h,j]
// ---------------------------------------------------------------------------
__global__ void prep_u_kernel(const float* __restrict__ W2,
                              const float* __restrict__ as2,
                              const float* __restrict__ ad2) {
    int t = blockIdx.x * blockDim.x + threadIdx.x;
    if (t >= 512) return;
    int h = t >> 7, c = t & 127;
    const float* wrow = W2 + (size_t)c * 512 + h * 128;
    const float* av = as2 + h * 128;
    const float* dv = ad2 + h * 128;
    float s = 0.f, d = 0.f;
    for (int j = 0; j < 128; j++) { float w = wrow[j]; s += w * av[j]; d += w * dv[j]; }
    g_us[t] = s; g_ud[t] = d;
}

// Repack W2 [128, 512] -> g_w2r [512, 128]: g_w2r[h*128+c][o] = W2[c][h*128+o]
__global__ void repack_w2_kernel(const float* __restrict__ W2) {
    int i = blockIdx.x * blockDim.x + threadIdx.x;
    if (i >= 512 * 128) return;
    int k = i >> 7, o = i & 127, h = k >> 7, c = k & 127;
    g_w2r[i] = W2[(size_t)c * 512 + h * 128 + o];
}

// Layer-2 attention dots from h-space: a_s[n,h] = h[n] . u_s[h]
__global__ __launch_bounds__(256)
void att2_kernel(const float* __restrict__ hb) {
    int gw = (blockIdx.x * blockDim.x + threadIdx.x) >> 5;
    int lane = threadIdx.x & 31;
    if (gw >= NN) return;
    const float4 v = *(const float4*)(hb + (size_t)gw * 128 + lane * 4);
    float s[4], d[4];
    #pragma unroll
    for (int h = 0; h < 4; h++) {
        const float4 us = *(const float4*)(g_us + h * 128 + lane * 4);
        const float4 ud = *(const float4*)(g_ud + h * 128 + lane * 4);
        s[h] = v.x * us.x + v.y * us.y + v.z * us.z + v.w * us.w;
        d[h] = v.x * ud.x + v.y * ud.y + v.z * ud.z + v.w * ud.w;
    }
    #pragma unroll
    for (int o = 16; o; o >>= 1) {
        #pragma unroll
        for (int h = 0; h < 4; h++) {
            s[h] += __shfl_xor_sync(0xffffffffu, s[h], o);
            d[h] += __shfl_xor_sync(0xffffffffu, d[h], o);
        }
    }
    if (lane == 0) {
        #pragma unroll
        for (int h = 0; h < 4; h++) { g_as[gw * 4 + h] = s[h]; g_ad[gw * 4 + h] = d[h]; }
    }
}

// ---------------------------------------------------------------------------
// Softmax context: per-head max + inverse sum for node n's incoming edges
// ---------------------------------------------------------------------------
struct SoftCtx { float m0, m1, m2, m3, i0, i1, i2, i3; float4 adv; };

__device__ __forceinline__ SoftCtx softmax_ctx(int rs, int re, int n, int lane) {
    SoftCtx c;
    c.adv = *(const float4*)(g_ad + 4 * n);
    float m0 = -1e30f, m1 = -1e30f, m2 = -1e30f, m3 = -1e30f;
    for (int idx = rs + lane; idx < re; idx += 32) {
        int s = g_csrc[idx];
        float4 a = __ldg((const float4*)(g_as + 4 * s));
        m0 = fmaxf(m0, lrelu(a.x + c.adv.x));
        m1 = fmaxf(m1, lrelu(a.y + c.adv.y));
        m2 = fmaxf(m2, lrelu(a.z + c.adv.z));
        m3 = fmaxf(m3, lrelu(a.w + c.adv.w));
    }
    #pragma unroll
    for (int o = 16; o; o >>= 1) {
        m0 = fmaxf(m0, __shfl_xor_sync(0xffffffffu, m0, o));
        m1 = fmaxf(m1, __shfl_xor_sync(0xffffffffu, m1, o));
        m2 = fmaxf(m2, __shfl_xor_sync(0xffffffffu, m2, o));
        m3 = fmaxf(m3, __shfl_xor_sync(0xffffffffu, m3, o));
    }
    float s0 = 0.f, s1 = 0.f, s2 = 0.f, s3 = 0.f;
    for (int idx = rs + lane; idx < re; idx += 32) {
        int s = g_csrc[idx];
        float4 a = __ldg((const float4*)(g_as + 4 * s));
        s0 += __expf(lrelu(a.x + c.adv.x) - m0);
        s1 += __expf(lrelu(a.y + c.adv.y) - m1);
        s2 += __expf(lrelu(a.z + c.adv.z) - m2);
        s3 += __expf(lrelu(a.w + c.adv.w) - m3);
    }
    #pragma unroll
    for (int o = 16; o; o >>= 1) {
        s0 += __shfl_xor_sync(0xffffffffu, s0, o);
        s1 += __shfl_xor_sync(0xffffffffu, s1, o);
        s2 += __shfl_xor_sync(0xffffffffu, s2, o);
        s3 += __shfl_xor_sync(0xffffffffu, s3, o);
    }
    c.m0 = m0; c.m1 = m1; c.m2 = m2; c.m3 = m3;
    c.i0 = 1.f / (s0 + 1e-16f); c.i1 = 1.f / (s1 + 1e-16f);
    c.i2 = 1.f / (s2 + 1e-16f); c.i3 = 1.f / (s3 + 1e-16f);
    return c;
}

// ---------------------------------------------------------------------------
// Concat aggregation (layers 0/1): persistent warps + fused BN stats.
// Bias omitted: a per-column constant cancels exactly under BatchNorm.
// ---------------------------------------------------------------------------
__global__ __launch_bounds__(256)
void aggregate_kernel(const float* __restrict__ xp, float* __restrict__ ob) {
    const int lane = threadIdx.x & 31, w = threadIdx.x >> 5;
    const int gwarp = blockIdx.x * 8 + w;
    const int nwarps = gridDim.x * 8;
    float bs[4] = {0.f, 0.f, 0.f, 0.f}, bq[4] = {0.f, 0.f, 0.f, 0.f};

    for (int n = gwarp; n < NN; n += nwarps) {
        const int rs = g_rowptr[n], re = g_rowptr[n + 1];
        SoftCtx cx = softmax_ctx(rs, re, n, lane);

        float acc0 = 0.f, acc1 = 0.f, acc2 = 0.f, acc3 = 0.f;
        for (int idx = rs; idx < re; idx += 32) {
            int myi = idx + lane;
            int s = 0;
            float w0 = 0.f, w1 = 0.f, w2 = 0.f, w3 = 0.f;
            if (myi < re) {
                s = g_csrc[myi];
                float4 a = __ldg((const float4*)(g_as + 4 * s));
                w0 = __expf(lrelu(a.x + cx.adv.x) - cx.m0) * cx.i0;
                w1 = __expf(lrelu(a.y + cx.adv.y) - cx.m1) * cx.i1;
                w2 = __expf(lrelu(a.z + cx.adv.z) - cx.m2) * cx.i2;
                w3 = __expf(lrelu(a.w + cx.adv.w) - cx.m3) * cx.i3;
            }
            int cnt = min(32, re - idx);
            for (int j = 0; j < cnt; j++) {
                int sj   = __shfl_sync(0xffffffffu, s,  j);
                float b0 = __shfl_sync(0xffffffffu, w0, j);
                float b1 = __shfl_sync(0xffffffffu, w1, j);
                float b2 = __shfl_sync(0xffffffffu, w2, j);
                float b3 = __shfl_sync(0xffffffffu, w3, j);
                float ww = (lane < 16) ? (lane < 8 ? b0 : b1) : (lane < 24 ? b2 : b3);
                float4 v = __ldg((const float4*)(xp + (size_t)sj * 128 + lane * 4));
                acc0 += ww * v.x; acc1 += ww * v.y; acc2 += ww * v.z; acc3 += ww * v.w;
            }
        }
        float* dst = ob + (size_t)n * 128 + lane * 4;
        dst[0] = acc0; dst[1] = acc1; dst[2] = acc2; dst[3] = acc3;
        bs[0] += acc0; bq[0] += acc0 * acc0;
        bs[1] += acc1; bq[1] += acc1 * acc1;
        bs[2] += acc2; bq[2] += acc2 * acc2;
        bs[3] += acc3; bq[3] += acc3 * acc3;
    }

    __shared__ float ssum[8][128];
    __shared__ float ssq[8][128];
    #pragma unroll
    for (int k = 0; k < 4; k++) { ssum[w][lane * 4 + k] = bs[k]; ssq[w][lane * 4 + k] = bq[k]; }
    __syncthreads();
    if (threadIdx.x < 128) {
        float s = 0.f, q = 0.f;
        #pragma unroll
        for (int j = 0; j < 8; j++) { s += ssum[j][threadIdx.x]; q += ssq[j][threadIdx.x]; }
        atomicAdd(&g_bnsum[threadIdx.x], s);
        atomicAdd(&g_bnsq[threadIdx.x], q);
    }
}

// ---------------------------------------------------------------------------
// Layer-2 aggregation in h-space: agg[n, h*128+c] = sum_e alpha[e,h] * h[src, c]
// ---------------------------------------------------------------------------
__global__ __launch_bounds__(256)
void aggregate2_kernel(const float* __restrict__ hb, float* __restrict__ agg) {
    int n = (blockIdx.x * blockDim.x + threadIdx.x) >> 5;
    int lane = threadIdx.x & 31;
    if (n >= NN) return;
    const int rs = g_rowptr[n], re = g_rowptr[n + 1];
    SoftCtx cx = softmax_ctx(rs, re, n, lane);

    float acc[4][4];
    #pragma unroll
    for (int h = 0; h < 4; h++)
        #pragma unroll
        for (int k = 0; k < 4; k++) acc[h][k] = 0.f;

    for (int idx = rs; idx < re; idx += 32) {
        int myi = idx + lane;
        int s = 0;
        float w0 = 0.f, w1 = 0.f, w2 = 0.f, w3 = 0.f;
        if (myi < re) {
            s = g_csrc[myi];
            float4 a = __ldg((const float4*)(g_as + 4 * s));
            w0 = __expf(lrelu(a.x + cx.adv.x) - cx.m0) * cx.i0;
            w1 = __expf(lrelu(a.y + cx.adv.y) - cx.m1) * cx.i1;
            w2 = __expf(lrelu(a.z + cx.adv.z) - cx.m2) * cx.i2;
            w3 = __expf(lrelu(a.w + cx.adv.w) - cx.m3) * cx.i3;
        }
        int cnt = min(32, re - idx);
        for (int j = 0; j < cnt; j++) {
            int sj   = __shfl_sync(0xffffffffu, s,  j);
            float b0 = __shfl_sync(0xffffffffu, w0, j);
            float b1 = __shfl_sync(0xffffffffu, w1, j);
            float b2 = __shfl_sync(0xffffffffu, w2, j);
            float b3 = __shfl_sync(0xffffffffu, w3, j);
            float4 v = __ldg((const float4*)(hb + (size_t)sj * 128 + lane * 4));
            acc[0][0] += b0 * v.x; acc[0][1] += b0 * v.y; acc[0][2] += b0 * v.z; acc[0][3] += b0 * v.w;
            acc[1][0] += b1 * v.x; acc[1][1] += b1 * v.y; acc[1][2] += b1 * v.z; acc[1][3] += b1 * v.w;
            acc[2][0] += b2 * v.x; acc[2][1] += b2 * v.y; acc[2][2] += b2 * v.z; acc[2][3] += b2 * v.w;
            acc[3][0] += b3 * v.x; acc[3][1] += b3 * v.y; acc[3][2] += b3 * v.z; acc[3][3] += b3 * v.w;
        }
    }
    #pragma unroll
    for (int h = 0; h < 4; h++)
        *(float4*)(agg + (size_t)n * 512 + h * 128 + lane * 4) = *(float4*)acc[h];
}

// ---------------------------------------------------------------------------
// BatchNorm
// ---------------------------------------------------------------------------
__global__ void bn_zero_kernel() {
    if (threadIdx.x < 128) { g_bnsum[threadIdx.x] = 0.f; g_bnsq[threadIdx.x] = 0.f; }
}

template <bool ELU>
__global__ __launch_bounds__(256)
void bn_apply_kernel(const float* __restrict__ in, const float* __restrict__ gamma,
                     const float* __restrict__ beta, float* __restrict__ out) {
    int i = blockIdx.x * blockDim.x + threadIdx.x;
    if (i >= NN * 128) return;
    int col = i & 127;
    const float invN = 1.f / (float)NN;
    float mu  = g_bnsum[col] * invN;
    float var = g_bnsq[col] * invN - mu * mu;
    float sc  = gamma[col] * rsqrtf(var + 1e-5f);
    float y   = (in[i] - mu) * sc + beta[col];
    if (ELU) y = (y > 0.f) ? y : expm1f(y);
    out[i] = y;
}

// ---------------------------------------------------------------------------
// Launch
// ---------------------------------------------------------------------------
extern "C" void kernel_launch(void* const* d_in, const int* in_sizes, int n_in,
                              void* d_out, int out_size) {
    const float* x   = (const float*)d_in[0];
    const void*  ei  = d_in[1];
    const float* W0  = (const float*)d_in[2];
    const float* as0 = (const float*)d_in[3];
    const float* ad0 = (const float*)d_in[4];
    const float* g0  = (const float*)d_in[6];
    const float* be0 = (const float*)d_in[7];
    const float* W1  = (const float*)d_in[8];
    const float* as1 = (const float*)d_in[9];
    const float* ad1 = (const float*)d_in[10];
    const float* g1  = (const float*)d_in[12];
    const float* be1 = (const float*)d_in[13];
    const float* W2  = (const float*)d_in[14];
    const float* as2 = (const float*)d_in[15];
    const float* ad2 = (const float*)d_in[16];
    const float* g2  = (const float*)d_in[18];
    const float* be2 = (const float*)d_in[19];
    float* out = (float*)d_out;

    float* xp; cudaGetSymbolAddress((void**)&xp, g_xp);
    float* hb; cudaGetSymbolAddress((void**)&hb, g_h);
    float* ob; cudaGetSymbolAddress((void**)&ob, g_ob);
    float* w2r; cudaGetSymbolAddress((void**)&w2r, g_w2r);

    const int nb_n  = (NN + 255) / 256;
    const int nb_e  = (EP + 255) / 256;
    const int nb_n8 = (NN + 7) / 8;           // warp-per-node kernels
    const int nb_el = (NN * 128 + 255) / 256;
    const dim3 gemm((NN + 127) / 128, 1);

    // Launch index 3 (profiled) = L0 SGEMM: independent of the CSR build.
    detect_kernel<<<1, 64>>>(ei);
    zero_deg_kernel<<<nb_n, 256>>>();
    decode_kernel<<<nb_e, 256>>>(ei);
    sgemm_kernel<128, 1><<<gemm, 256>>>(x, W0, xp, NN, 1.f, as0, ad0);   // + att dots

    // CSR build
    block_sum_kernel<<<NB, 256>>>();
    scan_bsum_kernel<<<1, 256>>>();
    scan_fill_kernel<<<NB, 256>>>();
    scatter_kernel<<<nb_e, 256>>>();

    // ---- Layer 0 rest ----
    bn_zero_kernel<<<1, 128>>>();
    aggregate_kernel<<<1480, 256>>>(xp, ob);
    bn_apply_kernel<true><<<nb_el, 256>>>(ob, g0, be0, hb);

    // ---- Layer 1 ----
    sgemm_kernel<128, 1><<<gemm, 256>>>(hb, W1, xp, NN, 1.f, as1, ad1);  // + att dots
    bn_zero_kernel<<<1, 128>>>();
    aggregate_kernel<<<1480, 256>>>(xp, ob);
    bn_apply_kernel<true><<<nb_el, 256>>>(ob, g1, be1, hb);

    // ---- Layer 2: aggregate in h-space, then W2 GEMM (heads averaged) ----
    prep_u_kernel<<<2, 256>>>(W2, as2, ad2);
    repack_w2_kernel<<<256, 256>>>(W2);
    att2_kernel<<<nb_n8, 256>>>(hb);
    aggregate2_kernel<<<nb_n8, 256>>>(hb, xp);          // xp <- [N,512] agg
    bn_zero_kernel<<<1, 128>>>();
    sgemm_kernel<512, 2><<<gemm, 256>>>(xp, w2r, ob, NN, 0.25f, nullptr, nullptr); // + BN stats
    bn_apply_kernel<false><<<nb_el, 256>>>(ob, g2, be2, out);

    (void)in_sizes; (void)n_in; (void)out_size;
}

// round 13
// speedup vs baseline: 1.3958x; 1.0350x over previous
#include <cuda_runtime.h>
#include <cuda_bf16.h>
#include <cstdint>

// Problem constants
#define NN     50000
#define EE     800000
#define EP     (EE + NN)      // edges + self loops = 850000
#define HEADS  4
#define NB     ((NN + 255) / 256)   // 196 scan blocks

// ---------------------------------------------------------------------------
// Scratch (static device globals; no runtime allocation)
// ---------------------------------------------------------------------------
__device__ __align__(16) float g_xp[(size_t)NN * 512];   // GEMM out / L2 agg buffer
__device__ __align__(16) float g_h [(size_t)NN * 128];   // layer activations
__device__ __align__(16) float g_ob[(size_t)NN * 128];   // pre-BN buffer
__device__ __align__(16) float g_as[NN * 4];             // a_src per (node, head)
__device__ __align__(16) float g_ad[NN * 4];             // a_dst per (node, head)
__device__ __align__(16) float g_w2r[512 * 128];         // repacked W2: [h*128+c][o]
__device__ __align__(16) float g_us[512];                // u_src[h*128+c]
__device__ __align__(16) float g_ud[512];                // u_dst[h*128+c]
__device__ int g_rowptr[NN + 1];
__device__ int g_cursor[NN];
__device__ int g_deg[NN];
__device__ int g_csrc[EP];
__device__ int g_src[EP];
__device__ int g_dst[EP];
__device__ int g_bsum[256];
__device__ int g_boff[256];
__device__ int g_is64;
__device__ float g_bnsum[128];
__device__ float g_bnsq[128];

__device__ __forceinline__ float lrelu(float x) { return x > 0.f ? x : 0.2f * x; }

// ---------------------------------------------------------------------------
// Edge-index dtype detection (JAX may emit int32 despite int64 in reference)
// ---------------------------------------------------------------------------
__global__ void detect_kernel(const void* ei) {
    __shared__ int ok;
    if (threadIdx.x == 0) ok = 1;
    __syncthreads();
    const long long* p = (const long long*)ei;   // 512B read: safe either way
    long long v = p[threadIdx.x];
    if (v < 0 || v >= NN) ok = 0;
    __syncthreads();
    if (threadIdx.x == 0) g_is64 = ok;
}

__global__ void zero_deg_kernel() {
    int i = blockIdx.x * blockDim.x + threadIdx.x;
    if (i < NN) g_deg[i] = 0;
}

// decode edges (+self loops) and build degree histogram in one pass
__global__ void decode_kernel(const void* ei) {
    int i = blockIdx.x * blockDim.x + threadIdx.x;
    if (i >= EP) return;
    int src, dst;
    if (i >= EE) {
        src = i - EE; dst = i - EE;
    } else if (g_is64) {
        const long long* p = (const long long*)ei;
        src = (int)p[i]; dst = (int)p[EE + i];
    } else {
        const int* p = (const int*)ei;
        src = p[i]; dst = p[EE + i];
    }
    g_src[i] = src; g_dst[i] = dst;
    atomicAdd(&g_deg[dst], 1);
}

// ---------------------------------------------------------------------------
// Hierarchical exclusive scan of g_deg (3 fully-parallel kernels)
// ---------------------------------------------------------------------------
__global__ __launch_bounds__(256) void block_sum_kernel() {
    int t = threadIdx.x, lane = t & 31, w = t >> 5;
    int idx = blockIdx.x * 256 + t;
    int v = (idx < NN) ? g_deg[idx] : 0;
    #pragma unroll
    for (int o = 16; o; o >>= 1) v += __shfl_xor_sync(0xffffffffu, v, o);
    __shared__ int wt[8];
    if (lane == 0) wt[w] = v;
    __syncthreads();
    if (t == 0) {
        int s = 0;
        #pragma unroll
        for (int j = 0; j < 8; j++) s += wt[j];
        g_bsum[blockIdx.x] = s;
    }
}

__global__ __launch_bounds__(256) void scan_bsum_kernel() {
    int t = threadIdx.x, lane = t & 31, w = t >> 5;
    int v = (t < NB) ? g_bsum[t] : 0;
    int incl = v;
    #pragma unroll
    for (int o = 1; o < 32; o <<= 1) {
        int u = __shfl_up_sync(0xffffffffu, incl, o);
        if (lane >= o) incl += u;
    }
    __shared__ int wt[8];
    if (lane == 31) wt[w] = incl;
    __syncthreads();
    if (w == 0 && lane < 8) {
        int x = wt[lane];
        #pragma unroll
        for (int o = 1; o < 8; o <<= 1) {
            int u = __shfl_up_sync(0xffu, x, o);
            if (lane >= o) x += u;
        }
        wt[lane] = x;
    }
    __syncthreads();
    int off = (w ? wt[w - 1] : 0);
    if (t < NB) g_boff[t] = off + incl - v;   // exclusive
}

__global__ __launch_bounds__(256) void scan_fill_kernel() {
    int t = threadIdx.x, lane = t & 31, w = t >> 5;
    int idx = blockIdx.x * 256 + t;
    int v = (idx < NN) ? g_deg[idx] : 0;
    int incl = v;
    #pragma unroll
    for (int o = 1; o < 32; o <<= 1) {
        int u = __shfl_up_sync(0xffffffffu, incl, o);
        if (lane >= o) incl += u;
    }
    __shared__ int wt[8];
    if (lane == 31) wt[w] = incl;
    __syncthreads();
    if (w == 0 && lane < 8) {
        int x = wt[lane];
        #pragma unroll
        for (int o = 1; o < 8; o <<= 1) {
            int u = __shfl_up_sync(0xffu, x, o);
            if (lane >= o) x += u;
        }
        wt[lane] = x;
    }
    __syncthreads();
    int ex = g_boff[blockIdx.x] + (w ? wt[w - 1] : 0) + incl - v;
    if (idx < NN) { g_rowptr[idx] = ex; g_cursor[idx] = ex; }
    if (idx == NN - 1) g_rowptr[NN] = ex + v;
}

__global__ void scatter_kernel() {
    int i = blockIdx.x * blockDim.x + threadIdx.x;
    if (i >= EP) return;
    int pos = atomicAdd(&g_cursor[g_dst[i]], 1);
    g_csrc[pos] = g_src[i];
}

// ---------------------------------------------------------------------------
// SGEMM: Y[M,128] = scale * X[M,KD] @ W[KD,128]. 64x128 tile, 8x4/thread,
// row-paired f32x2 accumulators (acc[4][4] u64 = 32 regs -> ~80 regs total,
// 3 CTAs/SM). Warps: 2 row-bands x 4 col-bands; lane r2=lane>>3, c2=lane&7.
// Per k-step: A = 2x ld.shared.v2.b64 (packed row-pairs, zero repack),
// B = 1x LDS.128 + 4 dup movs. All load footprints conflict-free; As rows
// padded to 68 floats (16B-aligned, store conflict 2-way max).
// MODE 1: fused attention-dot epilogue. MODE 2: fused BN-stats epilogue.
// ---------------------------------------------------------------------------
#define AS_ROW 68

template <int KD, int MODE>
__global__ __launch_bounds__(256, 3)
void sgemm_kernel(const float* __restrict__ X, const float* __restrict__ W,
                  float* __restrict__ Y, int M, float scale,
                  const float* __restrict__ asw, const float* __restrict__ adw) {
    __shared__ __align__(16) float As[2][16][AS_ROW];
    __shared__ __align__(16) float Bs[2][16][128];
    const int bm = blockIdx.x * 64;
    const int tid = threadIdx.x;
    const int lane = tid & 31, w = tid >> 5;
    const int r2 = lane >> 3, c2 = lane & 7;
    const int wb = w & 1, cb = w >> 1;
    const int m0 = wb * 32 + r2 * 8;               // 8 rows m0..m0+7
    const int n0 = cb * 32 + c2 * 4;               // 4 cols n0..n0+3
    const int KT = KD / 16;

    // acc[p][c]: rows (m0+2p, m0+2p+1), col n0+c, packed f32x2
    unsigned long long acc[4][4];
    #pragma unroll
    for (int p = 0; p < 4; p++)
        #pragma unroll
        for (int c = 0; c < 4; c++) acc[p][c] = 0ull;

    const int ar = tid >> 2, ac = (tid & 3) * 4;      // A-load: row 0..63, 4 k-cols
    const int br = tid >> 5, bc = (tid & 31) * 4;     // B-load coords

    const uint32_t abase = (uint32_t)__cvta_generic_to_shared(&As[0][0][0]) + m0 * 4u;

    float4 ra, rb[2];
    // prologue: tile 0
    {
        int gr = bm + ar;
        ra = make_float4(0.f, 0.f, 0.f, 0.f);
        if (gr < M) ra = *(const float4*)(X + (size_t)gr * KD + ac);
        rb[0] = *(const float4*)(W + (size_t)br * 128 + bc);
        rb[1] = *(const float4*)(W + (size_t)(br + 8) * 128 + bc);
    }
    As[0][ac + 0][ar] = ra.x; As[0][ac + 1][ar] = ra.y;
    As[0][ac + 2][ar] = ra.z; As[0][ac + 3][ar] = ra.w;
    *(float4*)&Bs[0][br][bc]     = rb[0];
    *(float4*)&Bs[0][br + 8][bc] = rb[1];
    __syncthreads();

    for (int kt = 0; kt < KT; kt++) {
        const int cur = kt & 1;
        const bool has_next = (kt + 1 < KT);
        if (has_next) {
            const int k0 = (kt + 1) * 16;
            int gr = bm + ar;
            ra = make_float4(0.f, 0.f, 0.f, 0.f);
            if (gr < M) ra = *(const float4*)(X + (size_t)gr * KD + k0 + ac);
            rb[0] = *(const float4*)(W + (size_t)(k0 + br) * 128 + bc);
            rb[1] = *(const float4*)(W + (size_t)(k0 + br + 8) * 128 + bc);
        }
        const uint32_t abuf = abase + (uint32_t)cur * (16 * AS_ROW * 4);
        #pragma unroll
        for (int k = 0; k < 16; k++) {
            unsigned long long ap[4];
            asm volatile("ld.shared.v2.b64 {%0, %1}, [%2];"
                         : "=l"(ap[0]), "=l"(ap[1]) : "r"(abuf + k * (AS_ROW * 4u)));
            asm volatile("ld.shared.v2.b64 {%0, %1}, [%2];"
                         : "=l"(ap[2]), "=l"(ap[3]) : "r"(abuf + k * (AS_ROW * 4u) + 16u));
            float4 b4 = *(const float4*)&Bs[cur][k][n0];
            float bv[4] = {b4.x, b4.y, b4.z, b4.w};
            #pragma unroll
            for (int c = 0; c < 4; c++) {
                unsigned long long bb;
                unsigned int bu = __float_as_uint(bv[c]);
                asm("mov.b64 %0, {%1, %1};" : "=l"(bb) : "r"(bu));
                #pragma unroll
                for (int p = 0; p < 4; p++)
                    asm("fma.rn.f32x2 %0, %1, %2, %3;"
                        : "=l"(acc[p][c]) : "l"(ap[p]), "l"(bb), "l"(acc[p][c]));
            }
        }
        if (has_next) {
            const int nxt = (kt + 1) & 1;
            As[nxt][ac + 0][ar] = ra.x; As[nxt][ac + 1][ar] = ra.y;
            As[nxt][ac + 2][ar] = ra.z; As[nxt][ac + 3][ar] = ra.w;
            *(float4*)&Bs[nxt][br][bc]     = rb[0];
            *(float4*)&Bs[nxt][br + 8][bc] = rb[1];
            __syncthreads();
        }
    }

    // MODE 1: this thread's 4 cols all live in head cb
    float avs[4], avd[4];
    if (MODE == 1) {
        *(float4*)avs = *(const float4*)(asw + cb * 32 + c2 * 4);
        *(float4*)avd = *(const float4*)(adw + cb * 32 + c2 * 4);
    }
    float bss[4], bsq[4];
    if (MODE == 2) {
        #pragma unroll
        for (int c = 0; c < 4; c++) { bss[c] = 0.f; bsq[c] = 0.f; }
    }

    #pragma unroll
    for (int p = 0; p < 4; p++) {
        #pragma unroll
        for (int h = 0; h < 2; h++) {
            int gr = bm + m0 + p * 2 + h;
            float o4[4];
            #pragma unroll
            for (int c = 0; c < 4; c++) {
                float2 f = *(float2*)&acc[p][c];
                o4[c] = (h == 0 ? f.x : f.y) * scale;
            }
            if (MODE == 1) {
                float s = 0.f, d = 0.f;
                #pragma unroll
                for (int c = 0; c < 4; c++) { s += o4[c] * avs[c]; d += o4[c] * avd[c]; }
                s += __shfl_xor_sync(0xffffffffu, s, 1);
                s += __shfl_xor_sync(0xffffffffu, s, 2);
                s += __shfl_xor_sync(0xffffffffu, s, 4);
                d += __shfl_xor_sync(0xffffffffu, d, 1);
                d += __shfl_xor_sync(0xffffffffu, d, 2);
                d += __shfl_xor_sync(0xffffffffu, d, 4);
                if (c2 == 0 && gr < M) {
                    g_as[gr * 4 + cb] = s;
                    g_ad[gr * 4 + cb] = d;
                }
            }
            if (gr < M) {
                if (MODE == 2) {
                    #pragma unroll
                    for (int c = 0; c < 4; c++) { bss[c] += o4[c]; bsq[c] += o4[c] * o4[c]; }
                }
                *(float4*)(Y + (size_t)gr * 128 + n0) = *(float4*)o4;
            }
        }
    }

    if (MODE == 2) {
        // block-level column reduce in (reused) As smem, then global atomics
        __syncthreads();
        float* ssum = &As[0][0][0];          // 1024 floats
        float* ssq  = &As[0][0][0] + 1024;   // 1024 floats (As holds 2176)
        const int idx8 = wb * 4 + r2;        // 8 distinct row-groups
        *(float4*)&ssum[idx8 * 128 + n0] = *(float4*)bss;
        *(float4*)&ssq [idx8 * 128 + n0] = *(float4*)bsq;
        __syncthreads();
        if (tid < 128) {
            float s = 0.f, q = 0.f;
            #pragma unroll
            for (int t = 0; t < 8; t++) { s += ssum[t * 128 + tid]; q += ssq[t * 128 + tid]; }
            atomicAdd(&g_bnsum[tid], s);
            atomicAdd(&g_bnsq[tid], q);
        }
    }
}

// ---------------------------------------------------------------------------
// Layer-2 attention precompute:  u_s[h*128+c] = sum_j W2[c, h*128+j]*as2[h,j]
// ---------------------------------------------------------------------------
__global__ void prep_u_kernel(const float* __restrict__ W2,
                              const float* __restrict__ as2,
                              const float* __restrict__ ad2) {
    int t = blockIdx.x * blockDim.x + threadIdx.x;
    if (t >= 512) return;
    int h = t >> 7, c = t & 127;
    const float* wrow = W2 + (size_t)c * 512 + h * 128;
    const float* av = as2 + h * 128;
    const float* dv = ad2 + h * 128;
    float s = 0.f, d = 0.f;
    for (int j = 0; j < 128; j++) { float w = wrow[j]; s += w * av[j]; d += w * dv[j]; }
    g_us[t] = s; g_ud[t] = d;
}

// Repack W2 [128, 512] -> g_w2r [512, 128]: g_w2r[h*128+c][o] = W2[c][h*128+o]
__global__ void repack_w2_kernel(const float* __restrict__ W2) {
    int i = blockIdx.x * blockDim.x + threadIdx.x;
    if (i >= 512 * 128) return;
    int k = i >> 7, o = i & 127, h = k >> 7, c = k & 127;
    g_w2r[i] = W2[(size_t)c * 512 + h * 128 + o];
}

// Layer-2 attention dots from h-space: a_s[n,h] = h[n] . u_s[h]
__global__ __launch_bounds__(256)
void att2_kernel(const float* __restrict__ hb) {
    int gw = (blockIdx.x * blockDim.x + threadIdx.x) >> 5;
    int lane = threadIdx.x & 31;
    if (gw >= NN) return;
    const float4 v = *(const float4*)(hb + (size_t)gw * 128 + lane * 4);
    float s[4], d[4];
    #pragma unroll
    for (int h = 0; h < 4; h++) {
        const float4 us = *(const float4*)(g_us + h * 128 + lane * 4);
        const float4 ud = *(const float4*)(g_ud + h * 128 + lane * 4);
        s[h] = v.x * us.x + v.y * us.y + v.z * us.z + v.w * us.w;
        d[h] = v.x * ud.x + v.y * ud.y + v.z * ud.z + v.w * ud.w;
    }
    #pragma unroll
    for (int o = 16; o; o >>= 1) {
        #pragma unroll
        for (int h = 0; h < 4; h++) {
            s[h] += __shfl_xor_sync(0xffffffffu, s[h], o);
            d[h] += __shfl_xor_sync(0xffffffffu, d[h], o);
        }
    }
    if (lane == 0) {
        #pragma unroll
        for (int h = 0; h < 4; h++) { g_as[gw * 4 + h] = s[h]; g_ad[gw * 4 + h] = d[h]; }
    }
}

// ---------------------------------------------------------------------------
// Softmax context: per-head max + inverse sum for node n's incoming edges
// ---------------------------------------------------------------------------
struct SoftCtx { float m0, m1, m2, m3, i0, i1, i2, i3; float4 adv; };

__device__ __forceinline__ SoftCtx softmax_ctx(int rs, int re, int n, int lane) {
    SoftCtx c;
    c.adv = *(const float4*)(g_ad + 4 * n);
    float m0 = -1e30f, m1 = -1e30f, m2 = -1e30f, m3 = -1e30f;
    for (int idx = rs + lane; idx < re; idx += 32) {
        int s = g_csrc[idx];
        float4 a = __ldg((const float4*)(g_as + 4 * s));
        m0 = fmaxf(m0, lrelu(a.x + c.adv.x));
        m1 = fmaxf(m1, lrelu(a.y + c.adv.y));
        m2 = fmaxf(m2, lrelu(a.z + c.adv.z));
        m3 = fmaxf(m3, lrelu(a.w + c.adv.w));
    }
    #pragma unroll
    for (int o = 16; o; o >>= 1) {
        m0 = fmaxf(m0, __shfl_xor_sync(0xffffffffu, m0, o));
        m1 = fmaxf(m1, __shfl_xor_sync(0xffffffffu, m1, o));
        m2 = fmaxf(m2, __shfl_xor_sync(0xffffffffu, m2, o));
        m3 = fmaxf(m3, __shfl_xor_sync(0xffffffffu, m3, o));
    }
    float s0 = 0.f, s1 = 0.f, s2 = 0.f, s3 = 0.f;
    for (int idx = rs + lane; idx < re; idx += 32) {
        int s = g_csrc[idx];
        float4 a = __ldg((const float4*)(g_as + 4 * s));
        s0 += __expf(lrelu(a.x + c.adv.x) - m0);
        s1 += __expf(lrelu(a.y + c.adv.y) - m1);
        s2 += __expf(lrelu(a.z + c.adv.z) - m2);
        s3 += __expf(lrelu(a.w + c.adv.w) - m3);
    }
    #pragma unroll
    for (int o = 16; o; o >>= 1) {
        s0 += __shfl_xor_sync(0xffffffffu, s0, o);
        s1 += __shfl_xor_sync(0xffffffffu, s1, o);
        s2 += __shfl_xor_sync(0xffffffffu, s2, o);
        s3 += __shfl_xor_sync(0xffffffffu, s3, o);
    }
    c.m0 = m0; c.m1 = m1; c.m2 = m2; c.m3 = m3;
    c.i0 = 1.f / (s0 + 1e-16f); c.i1 = 1.f / (s1 + 1e-16f);
    c.i2 = 1.f / (s2 + 1e-16f); c.i3 = 1.f / (s3 + 1e-16f);
    return c;
}

// ---------------------------------------------------------------------------
// Concat aggregation (layers 0/1): persistent warps + fused BN stats.
// Bias omitted: a per-column constant cancels exactly under BatchNorm.
// ---------------------------------------------------------------------------
__global__ __launch_bounds__(256)
void aggregate_kernel(const float* __restrict__ xp, float* __restrict__ ob) {
    const int lane = threadIdx.x & 31, w = threadIdx.x >> 5;
    const int gwarp = blockIdx.x * 8 + w;
    const int nwarps = gridDim.x * 8;
    float bs[4] = {0.f, 0.f, 0.f, 0.f}, bq[4] = {0.f, 0.f, 0.f, 0.f};

    for (int n = gwarp; n < NN; n += nwarps) {
        const int rs = g_rowptr[n], re = g_rowptr[n + 1];
        SoftCtx cx = softmax_ctx(rs, re, n, lane);

        float acc0 = 0.f, acc1 = 0.f, acc2 = 0.f, acc3 = 0.f;
        for (int idx = rs; idx < re; idx += 32) {
            int myi = idx + lane;
            int s = 0;
            float w0 = 0.f, w1 = 0.f, w2 = 0.f, w3 = 0.f;
            if (myi < re) {
                s = g_csrc[myi];
                float4 a = __ldg((const float4*)(g_as + 4 * s));
                w0 = __expf(lrelu(a.x + cx.adv.x) - cx.m0) * cx.i0;
                w1 = __expf(lrelu(a.y + cx.adv.y) - cx.m1) * cx.i1;
                w2 = __expf(lrelu(a.z + cx.adv.z) - cx.m2) * cx.i2;
                w3 = __expf(lrelu(a.w + cx.adv.w) - cx.m3) * cx.i3;
            }
            int cnt = min(32, re - idx);
            for (int j = 0; j < cnt; j++) {
                int sj   = __shfl_sync(0xffffffffu, s,  j);
                float b0 = __shfl_sync(0xffffffffu, w0, j);
                float b1 = __shfl_sync(0xffffffffu, w1, j);
                float b2 = __shfl_sync(0xffffffffu, w2, j);
                float b3 = __shfl_sync(0xffffffffu, w3, j);
                float ww = (lane < 16) ? (lane < 8 ? b0 : b1) : (lane < 24 ? b2 : b3);
                float4 v = __ldg((const float4*)(xp + (size_t)sj * 128 + lane * 4));
                acc0 += ww * v.x; acc1 += ww * v.y; acc2 += ww * v.z; acc3 += ww * v.w;
            }
        }
        float* dst = ob + (size_t)n * 128 + lane * 4;
        dst[0] = acc0; dst[1] = acc1; dst[2] = acc2; dst[3] = acc3;
        bs[0] += acc0; bq[0] += acc0 * acc0;
        bs[1] += acc1; bq[1] += acc1 * acc1;
        bs[2] += acc2; bq[2] += acc2 * acc2;
        bs[3] += acc3; bq[3] += acc3 * acc3;
    }

    __shared__ float ssum[8][128];
    __shared__ float ssq[8][128];
    #pragma unroll
    for (int k = 0; k < 4; k++) { ssum[w][lane * 4 + k] = bs[k]; ssq[w][lane * 4 + k] = bq[k]; }
    __syncthreads();
    if (threadIdx.x < 128) {
        float s = 0.f, q = 0.f;
        #pragma unroll
        for (int j = 0; j < 8; j++) { s += ssum[j][threadIdx.x]; q += ssq[j][threadIdx.x]; }
        atomicAdd(&g_bnsum[threadIdx.x], s);
        atomicAdd(&g_bnsq[threadIdx.x], q);
    }
}

// ---------------------------------------------------------------------------
// Layer-2 aggregation in h-space: agg[n, h*128+c] = sum_e alpha[e,h] * h[src, c]
// ---------------------------------------------------------------------------
__global__ __launch_bounds__(256)
void aggregate2_kernel(const float* __restrict__ hb, float* __restrict__ agg) {
    int n = (blockIdx.x * blockDim.x + threadIdx.x) >> 5;
    int lane = threadIdx.x & 31;
    if (n >= NN) return;
    const int rs = g_rowptr[n], re = g_rowptr[n + 1];
    SoftCtx cx = softmax_ctx(rs, re, n, lane);

    float acc[4][4];
    #pragma unroll
    for (int h = 0; h < 4; h++)
        #pragma unroll
        for (int k = 0; k < 4; k++) acc[h][k] = 0.f;

    for (int idx = rs; idx < re; idx += 32) {
        int myi = idx + lane;
        int s = 0;
        float w0 = 0.f, w1 = 0.f, w2 = 0.f, w3 = 0.f;
        if (myi < re) {
            s = g_csrc[myi];
            float4 a = __ldg((const float4*)(g_as + 4 * s));
            w0 = __expf(lrelu(a.x + cx.adv.x) - cx.m0) * cx.i0;
            w1 = __expf(lrelu(a.y + cx.adv.y) - cx.m1) * cx.i1;
            w2 = __expf(lrelu(a.z + cx.adv.z) - cx.m2) * cx.i2;
            w3 = __expf(lrelu(a.w + cx.adv.w) - cx.m3) * cx.i3;
        }
        int cnt = min(32, re - idx);
        for (int j = 0; j < cnt; j++) {
            int sj   = __shfl_sync(0xffffffffu, s,  j);
            float b0 = __shfl_sync(0xffffffffu, w0, j);
            float b1 = __shfl_sync(0xffffffffu, w1, j);
            float b2 = __shfl_sync(0xffffffffu, w2, j);
            float b3 = __shfl_sync(0xffffffffu, w3, j);
            float4 v = __ldg((const float4*)(hb + (size_t)sj * 128 + lane * 4));
            acc[0][0] += b0 * v.x; acc[0][1] += b0 * v.y; acc[0][2] += b0 * v.z; acc[0][3] += b0 * v.w;
            acc[1][0] += b1 * v.x; acc[1][1] += b1 * v.y; acc[1][2] += b1 * v.z; acc[1][3] += b1 * v.w;
            acc[2][0] += b2 * v.x; acc[2][1] += b2 * v.y; acc[2][2] += b2 * v.z; acc[2][3] += b2 * v.w;
            acc[3][0] += b3 * v.x; acc[3][1] += b3 * v.y; acc[3][2] += b3 * v.z; acc[3][3] += b3 * v.w;
        }
    }
    #pragma unroll
    for (int h = 0; h < 4; h++)
        *(float4*)(agg + (size_t)n * 512 + h * 128 + lane * 4) = *(float4*)acc[h];
}

// ---------------------------------------------------------------------------
// BatchNorm
// ---------------------------------------------------------------------------
__global__ void bn_zero_kernel() {
    if (threadIdx.x < 128) { g_bnsum[threadIdx.x] = 0.f; g_bnsq[threadIdx.x] = 0.f; }
}

template <bool ELU>
__global__ __launch_bounds__(256)
void bn_apply_kernel(const float* __restrict__ in, const float* __restrict__ gamma,
                     const float* __restrict__ beta, float* __restrict__ out) {
    int i = blockIdx.x * blockDim.x + threadIdx.x;
    if (i >= NN * 128) return;
    int col = i & 127;
    const float invN = 1.f / (float)NN;
    float mu  = g_bnsum[col] * invN;
    float var = g_bnsq[col] * invN - mu * mu;
    float sc  = gamma[col] * rsqrtf(var + 1e-5f);
    float y   = (in[i] - mu) * sc + beta[col];
    if (ELU) y = (y > 0.f) ? y : expm1f(y);
    out[i] = y;
}

// ---------------------------------------------------------------------------
// Launch
// ---------------------------------------------------------------------------
extern "C" void kernel_launch(void* const* d_in, const int* in_sizes, int n_in,
                              void* d_out, int out_size) {
    const float* x   = (const float*)d_in[0];
    const void*  ei  = d_in[1];
    const float* W0  = (const float*)d_in[2];
    const float* as0 = (const float*)d_in[3];
    const float* ad0 = (const float*)d_in[4];
    const float* g0  = (const float*)d_in[6];
    const float* be0 = (const float*)d_in[7];
    const float* W1  = (const float*)d_in[8];
    const float* as1 = (const float*)d_in[9];
    const float* ad1 = (const float*)d_in[10];
    const float* g1  = (const float*)d_in[12];
    const float* be1 = (const float*)d_in[13];
    const float* W2  = (const float*)d_in[14];
    const float* as2 = (const float*)d_in[15];
    const float* ad2 = (const float*)d_in[16];
    const float* g2  = (const float*)d_in[18];
    const float* be2 = (const float*)d_in[19];
    float* out = (float*)d_out;

    float* xp; cudaGetSymbolAddress((void**)&xp, g_xp);
    float* hb; cudaGetSymbolAddress((void**)&hb, g_h);
    float* ob; cudaGetSymbolAddress((void**)&ob, g_ob);
    float* w2r; cudaGetSymbolAddress((void**)&w2r, g_w2r);

    const int nb_n  = (NN + 255) / 256;
    const int nb_e  = (EP + 255) / 256;
    const int nb_n8 = (NN + 7) / 8;           // warp-per-node kernels
    const int nb_el = (NN * 128 + 255) / 256;
    const dim3 gemm((NN + 63) / 64, 1);       // 64-row tiles: 782 CTAs

    // Launch index 3 (profiled) = L0 SGEMM: independent of the CSR build.
    detect_kernel<<<1, 64>>>(ei);
    zero_deg_kernel<<<nb_n, 256>>>();
    decode_kernel<<<nb_e, 256>>>(ei);
    sgemm_kernel<128, 1><<<gemm, 256>>>(x, W0, xp, NN, 1.f, as0, ad0);   // + att dots

    // CSR build
    block_sum_kernel<<<NB, 256>>>();
    scan_bsum_kernel<<<1, 256>>>();
    scan_fill_kernel<<<NB, 256>>>();
    scatter_kernel<<<nb_e, 256>>>();

    // ---- Layer 0 rest ----
    bn_zero_kernel<<<1, 128>>>();
    aggregate_kernel<<<1480, 256>>>(xp, ob);
    bn_apply_kernel<true><<<nb_el, 256>>>(ob, g0, be0, hb);

    // ---- Layer 1 ----
    sgemm_kernel<128, 1><<<gemm, 256>>>(hb, W1, xp, NN, 1.f, as1, ad1);  // + att dots
    bn_zero_kernel<<<1, 128>>>();
    aggregate_kernel<<<1480, 256>>>(xp, ob);
    bn_apply_kernel<true><<<nb_el, 256>>>(ob, g1, be1, hb);

    // ---- Layer 2: aggregate in h-space, then W2 GEMM (heads averaged) ----
    prep_u_kernel<<<2, 256>>>(W2, as2, ad2);
    repack_w2_kernel<<<256, 256>>>(W2);
    att2_kernel<<<nb_n8, 256>>>(hb);
    aggregate2_kernel<<<nb_n8, 256>>>(hb, xp);          // xp <- [N,512] agg
    bn_zero_kernel<<<1, 128>>>();
    sgemm_kernel<512, 2><<<gemm, 256>>>(xp, w2r, ob, NN, 0.25f, nullptr, nullptr); // + BN stats
    bn_apply_kernel<false><<<nb_el, 256>>>(ob, g2, be2, out);

    (void)in_sizes; (void)n_in; (void)out_size;
}

// round 14
// speedup vs baseline: 1.5464x; 1.1078x over previous
#include <cuda_runtime.h>
#include <cuda_bf16.h>
#include <cstdint>

// Problem constants
#define NN     50000
#define EE     800000
#define EP     (EE + NN)      // edges + self loops = 850000
#define HEADS  4
#define NB     ((NN + 255) / 256)   // 196 scan blocks

// ---------------------------------------------------------------------------
// Scratch (static device globals; no runtime allocation)
// ---------------------------------------------------------------------------
__device__ __align__(16) float g_xp[(size_t)NN * 512];   // GEMM out / L2 agg buffer
__device__ __align__(16) float g_h [(size_t)NN * 128];   // layer activations
__device__ __align__(16) float g_ob[(size_t)NN * 128];   // pre-BN buffer
__device__ __align__(16) float g_as[NN * 4];             // a_src per (node, head)
__device__ __align__(16) float g_ad[NN * 4];             // a_dst per (node, head)
__device__ __align__(16) float g_w2r[512 * 128];         // repacked W2: [h*128+c][o]
__device__ __align__(16) float g_us[512];                // u_src[h*128+c]
__device__ __align__(16) float g_ud[512];                // u_dst[h*128+c]
__device__ int g_rowptr[NN + 1];
__device__ int g_cursor[NN];
__device__ int g_deg[NN];
__device__ int g_csrc[EP];
__device__ int g_src[EP];
__device__ int g_dst[EP];
__device__ int g_bsum[256];
__device__ int g_boff[256];
__device__ int g_is64;
__device__ float g_bnsum[128];
__device__ float g_bnsq[128];

__device__ __forceinline__ float lrelu(float x) { return x > 0.f ? x : 0.2f * x; }

// ---------------------------------------------------------------------------
// Edge-index dtype detection (JAX may emit int32 despite int64 in reference)
// ---------------------------------------------------------------------------
__global__ void detect_kernel(const void* ei) {
    __shared__ int ok;
    if (threadIdx.x == 0) ok = 1;
    __syncthreads();
    const long long* p = (const long long*)ei;   // 512B read: safe either way
    long long v = p[threadIdx.x];
    if (v < 0 || v >= NN) ok = 0;
    __syncthreads();
    if (threadIdx.x == 0) g_is64 = ok;
}

__global__ void zero_deg_kernel() {
    int i = blockIdx.x * blockDim.x + threadIdx.x;
    if (i < NN) g_deg[i] = 0;
}

// decode edges (+self loops) and build degree histogram in one pass
__global__ void decode_kernel(const void* ei) {
    int i = blockIdx.x * blockDim.x + threadIdx.x;
    if (i >= EP) return;
    int src, dst;
    if (i >= EE) {
        src = i - EE; dst = i - EE;
    } else if (g_is64) {
        const long long* p = (const long long*)ei;
        src = (int)p[i]; dst = (int)p[EE + i];
    } else {
        const int* p = (const int*)ei;
        src = p[i]; dst = p[EE + i];
    }
    g_src[i] = src; g_dst[i] = dst;
    atomicAdd(&g_deg[dst], 1);
}

// ---------------------------------------------------------------------------
// Hierarchical exclusive scan of g_deg (3 fully-parallel kernels)
// ---------------------------------------------------------------------------
__global__ __launch_bounds__(256) void block_sum_kernel() {
    int t = threadIdx.x, lane = t & 31, w = t >> 5;
    int idx = blockIdx.x * 256 + t;
    int v = (idx < NN) ? g_deg[idx] : 0;
    #pragma unroll
    for (int o = 16; o; o >>= 1) v += __shfl_xor_sync(0xffffffffu, v, o);
    __shared__ int wt[8];
    if (lane == 0) wt[w] = v;
    __syncthreads();
    if (t == 0) {
        int s = 0;
        #pragma unroll
        for (int j = 0; j < 8; j++) s += wt[j];
        g_bsum[blockIdx.x] = s;
    }
}

__global__ __launch_bounds__(256) void scan_bsum_kernel() {
    int t = threadIdx.x, lane = t & 31, w = t >> 5;
    int v = (t < NB) ? g_bsum[t] : 0;
    int incl = v;
    #pragma unroll
    for (int o = 1; o < 32; o <<= 1) {
        int u = __shfl_up_sync(0xffffffffu, incl, o);
        if (lane >= o) incl += u;
    }
    __shared__ int wt[8];
    if (lane == 31) wt[w] = incl;
    __syncthreads();
    if (w == 0 && lane < 8) {
        int x = wt[lane];
        #pragma unroll
        for (int o = 1; o < 8; o <<= 1) {
            int u = __shfl_up_sync(0xffu, x, o);
            if (lane >= o) x += u;
        }
        wt[lane] = x;
    }
    __syncthreads();
    int off = (w ? wt[w - 1] : 0);
    if (t < NB) g_boff[t] = off + incl - v;   // exclusive
}

__global__ __launch_bounds__(256) void scan_fill_kernel() {
    int t = threadIdx.x, lane = t & 31, w = t >> 5;
    int idx = blockIdx.x * 256 + t;
    int v = (idx < NN) ? g_deg[idx] : 0;
    int incl = v;
    #pragma unroll
    for (int o = 1; o < 32; o <<= 1) {
        int u = __shfl_up_sync(0xffffffffu, incl, o);
        if (lane >= o) incl += u;
    }
    __shared__ int wt[8];
    if (lane == 31) wt[w] = incl;
    __syncthreads();
    if (w == 0 && lane < 8) {
        int x = wt[lane];
        #pragma unroll
        for (int o = 1; o < 8; o <<= 1) {
            int u = __shfl_up_sync(0xffu, x, o);
            if (lane >= o) x += u;
        }
        wt[lane] = x;
    }
    __syncthreads();
    int ex = g_boff[blockIdx.x] + (w ? wt[w - 1] : 0) + incl - v;
    if (idx < NN) { g_rowptr[idx] = ex; g_cursor[idx] = ex; }
    if (idx == NN - 1) g_rowptr[NN] = ex + v;
}

__global__ void scatter_kernel() {
    int i = blockIdx.x * blockDim.x + threadIdx.x;
    if (i >= EP) return;
    int pos = atomicAdd(&g_cursor[g_dst[i]], 1);
    g_csrc[pos] = g_src[i];
}

// ---------------------------------------------------------------------------
// SGEMM: Y[M,128] = scale * X[M,KD] @ W[KD,128]. 64x128 tile, 8x4/thread,
// row-paired f32x2 accumulators (~80 regs, 3 CTAs/SM).
// MODE 1: fused attention-dot epilogue. MODE 2: fused BN-stats epilogue.
// (unchanged from round 13 — confirmed win)
// ---------------------------------------------------------------------------
#define AS_ROW 68

template <int KD, int MODE>
__global__ __launch_bounds__(256, 3)
void sgemm_kernel(const float* __restrict__ X, const float* __restrict__ W,
                  float* __restrict__ Y, int M, float scale,
                  const float* __restrict__ asw, const float* __restrict__ adw) {
    __shared__ __align__(16) float As[2][16][AS_ROW];
    __shared__ __align__(16) float Bs[2][16][128];
    const int bm = blockIdx.x * 64;
    const int tid = threadIdx.x;
    const int lane = tid & 31, w = tid >> 5;
    const int r2 = lane >> 3, c2 = lane & 7;
    const int wb = w & 1, cb = w >> 1;
    const int m0 = wb * 32 + r2 * 8;
    const int n0 = cb * 32 + c2 * 4;
    const int KT = KD / 16;

    unsigned long long acc[4][4];
    #pragma unroll
    for (int p = 0; p < 4; p++)
        #pragma unroll
        for (int c = 0; c < 4; c++) acc[p][c] = 0ull;

    const int ar = tid >> 2, ac = (tid & 3) * 4;
    const int br = tid >> 5, bc = (tid & 31) * 4;

    const uint32_t abase = (uint32_t)__cvta_generic_to_shared(&As[0][0][0]) + m0 * 4u;

    float4 ra, rb[2];
    {
        int gr = bm + ar;
        ra = make_float4(0.f, 0.f, 0.f, 0.f);
        if (gr < M) ra = *(const float4*)(X + (size_t)gr * KD + ac);
        rb[0] = *(const float4*)(W + (size_t)br * 128 + bc);
        rb[1] = *(const float4*)(W + (size_t)(br + 8) * 128 + bc);
    }
    As[0][ac + 0][ar] = ra.x; As[0][ac + 1][ar] = ra.y;
    As[0][ac + 2][ar] = ra.z; As[0][ac + 3][ar] = ra.w;
    *(float4*)&Bs[0][br][bc]     = rb[0];
    *(float4*)&Bs[0][br + 8][bc] = rb[1];
    __syncthreads();

    for (int kt = 0; kt < KT; kt++) {
        const int cur = kt & 1;
        const bool has_next = (kt + 1 < KT);
        if (has_next) {
            const int k0 = (kt + 1) * 16;
            int gr = bm + ar;
            ra = make_float4(0.f, 0.f, 0.f, 0.f);
            if (gr < M) ra = *(const float4*)(X + (size_t)gr * KD + k0 + ac);
            rb[0] = *(const float4*)(W + (size_t)(k0 + br) * 128 + bc);
            rb[1] = *(const float4*)(W + (size_t)(k0 + br + 8) * 128 + bc);
        }
        const uint32_t abuf = abase + (uint32_t)cur * (16 * AS_ROW * 4);
        #pragma unroll
        for (int k = 0; k < 16; k++) {
            unsigned long long ap[4];
            asm volatile("ld.shared.v2.b64 {%0, %1}, [%2];"
                         : "=l"(ap[0]), "=l"(ap[1]) : "r"(abuf + k * (AS_ROW * 4u)));
            asm volatile("ld.shared.v2.b64 {%0, %1}, [%2];"
                         : "=l"(ap[2]), "=l"(ap[3]) : "r"(abuf + k * (AS_ROW * 4u) + 16u));
            float4 b4 = *(const float4*)&Bs[cur][k][n0];
            float bv[4] = {b4.x, b4.y, b4.z, b4.w};
            #pragma unroll
            for (int c = 0; c < 4; c++) {
                unsigned long long bb;
                unsigned int bu = __float_as_uint(bv[c]);
                asm("mov.b64 %0, {%1, %1};" : "=l"(bb) : "r"(bu));
                #pragma unroll
                for (int p = 0; p < 4; p++)
                    asm("fma.rn.f32x2 %0, %1, %2, %3;"
                        : "=l"(acc[p][c]) : "l"(ap[p]), "l"(bb), "l"(acc[p][c]));
            }
        }
        if (has_next) {
            const int nxt = (kt + 1) & 1;
            As[nxt][ac + 0][ar] = ra.x; As[nxt][ac + 1][ar] = ra.y;
            As[nxt][ac + 2][ar] = ra.z; As[nxt][ac + 3][ar] = ra.w;
            *(float4*)&Bs[nxt][br][bc]     = rb[0];
            *(float4*)&Bs[nxt][br + 8][bc] = rb[1];
            __syncthreads();
        }
    }

    float avs[4], avd[4];
    if (MODE == 1) {
        *(float4*)avs = *(const float4*)(asw + cb * 32 + c2 * 4);
        *(float4*)avd = *(const float4*)(adw + cb * 32 + c2 * 4);
    }
    float bss[4], bsq[4];
    if (MODE == 2) {
        #pragma unroll
        for (int c = 0; c < 4; c++) { bss[c] = 0.f; bsq[c] = 0.f; }
    }

    #pragma unroll
    for (int p = 0; p < 4; p++) {
        #pragma unroll
        for (int h = 0; h < 2; h++) {
            int gr = bm + m0 + p * 2 + h;
            float o4[4];
            #pragma unroll
            for (int c = 0; c < 4; c++) {
                float2 f = *(float2*)&acc[p][c];
                o4[c] = (h == 0 ? f.x : f.y) * scale;
            }
            if (MODE == 1) {
                float s = 0.f, d = 0.f;
                #pragma unroll
                for (int c = 0; c < 4; c++) { s += o4[c] * avs[c]; d += o4[c] * avd[c]; }
                s += __shfl_xor_sync(0xffffffffu, s, 1);
                s += __shfl_xor_sync(0xffffffffu, s, 2);
                s += __shfl_xor_sync(0xffffffffu, s, 4);
                d += __shfl_xor_sync(0xffffffffu, d, 1);
                d += __shfl_xor_sync(0xffffffffu, d, 2);
                d += __shfl_xor_sync(0xffffffffu, d, 4);
                if (c2 == 0 && gr < M) {
                    g_as[gr * 4 + cb] = s;
                    g_ad[gr * 4 + cb] = d;
                }
            }
            if (gr < M) {
                if (MODE == 2) {
                    #pragma unroll
                    for (int c = 0; c < 4; c++) { bss[c] += o4[c]; bsq[c] += o4[c] * o4[c]; }
                }
                *(float4*)(Y + (size_t)gr * 128 + n0) = *(float4*)o4;
            }
        }
    }

    if (MODE == 2) {
        __syncthreads();
        float* ssum = &As[0][0][0];
        float* ssq  = &As[0][0][0] + 1024;
        const int idx8 = wb * 4 + r2;
        *(float4*)&ssum[idx8 * 128 + n0] = *(float4*)bss;
        *(float4*)&ssq [idx8 * 128 + n0] = *(float4*)bsq;
        __syncthreads();
        if (tid < 128) {
            float s = 0.f, q = 0.f;
            #pragma unroll
            for (int t = 0; t < 8; t++) { s += ssum[t * 128 + tid]; q += ssq[t * 128 + tid]; }
            atomicAdd(&g_bnsum[tid], s);
            atomicAdd(&g_bnsq[tid], q);
        }
    }
}

// ---------------------------------------------------------------------------
// Layer-2 attention precompute:  u_s[h*128+c] = sum_j W2[c, h*128+j]*as2[h,j]
// ---------------------------------------------------------------------------
__global__ void prep_u_kernel(const float* __restrict__ W2,
                              const float* __restrict__ as2,
                              const float* __restrict__ ad2) {
    int t = blockIdx.x * blockDim.x + threadIdx.x;
    if (t >= 512) return;
    int h = t >> 7, c = t & 127;
    const float* wrow = W2 + (size_t)c * 512 + h * 128;
    const float* av = as2 + h * 128;
    const float* dv = ad2 + h * 128;
    float s = 0.f, d = 0.f;
    for (int j = 0; j < 128; j++) { float w = wrow[j]; s += w * av[j]; d += w * dv[j]; }
    g_us[t] = s; g_ud[t] = d;
}

// Repack W2 [128, 512] -> g_w2r [512, 128]: g_w2r[h*128+c][o] = W2[c][h*128+o]
__global__ void repack_w2_kernel(const float* __restrict__ W2) {
    int i = blockIdx.x * blockDim.x + threadIdx.x;
    if (i >= 512 * 128) return;
    int k = i >> 7, o = i & 127, h = k >> 7, c = k & 127;
    g_w2r[i] = W2[(size_t)c * 512 + h * 128 + o];
}

// Layer-2 attention dots from h-space: a_s[n,h] = h[n] . u_s[h]
__global__ __launch_bounds__(256)
void att2_kernel(const float* __restrict__ hb) {
    int gw = (blockIdx.x * blockDim.x + threadIdx.x) >> 5;
    int lane = threadIdx.x & 31;
    if (gw >= NN) return;
    const float4 v = *(const float4*)(hb + (size_t)gw * 128 + lane * 4);
    float s[4], d[4];
    #pragma unroll
    for (int h = 0; h < 4; h++) {
        const float4 us = *(const float4*)(g_us + h * 128 + lane * 4);
        const float4 ud = *(const float4*)(g_ud + h * 128 + lane * 4);
        s[h] = v.x * us.x + v.y * us.y + v.z * us.z + v.w * us.w;
        d[h] = v.x * ud.x + v.y * ud.y + v.z * ud.z + v.w * ud.w;
    }
    #pragma unroll
    for (int o = 16; o; o >>= 1) {
        #pragma unroll
        for (int h = 0; h < 4; h++) {
            s[h] += __shfl_xor_sync(0xffffffffu, s[h], o);
            d[h] += __shfl_xor_sync(0xffffffffu, d[h], o);
        }
    }
    if (lane == 0) {
        #pragma unroll
        for (int h = 0; h < 4; h++) { g_as[gw * 4 + h] = s[h]; g_ad[gw * 4 + h] = d[h]; }
    }
}

// ---------------------------------------------------------------------------
// Edge weights, fast path (deg <= 32, ~all nodes: mean deg 17): ONE g_as
// gather, logits in registers, two warp reductions, weights in registers.
// Returns this lane's (s, w0..w3) for edge rs+lane.
// ---------------------------------------------------------------------------
struct EdgeW { int s; float w0, w1, w2, w3; };

__device__ __forceinline__ EdgeW edge_weights_fast(int rs, int deg, int n, int lane) {
    const float4 adv = *(const float4*)(g_ad + 4 * n);
    EdgeW r; r.s = 0;
    float e0 = -1e30f, e1 = -1e30f, e2 = -1e30f, e3 = -1e30f;
    if (lane < deg) {
        r.s = g_csrc[rs + lane];
        float4 a = __ldg((const float4*)(g_as + 4 * r.s));
        e0 = lrelu(a.x + adv.x); e1 = lrelu(a.y + adv.y);
        e2 = lrelu(a.z + adv.z); e3 = lrelu(a.w + adv.w);
    }
    float m0 = e0, m1 = e1, m2 = e2, m3 = e3;
    #pragma unroll
    for (int o = 16; o; o >>= 1) {
        m0 = fmaxf(m0, __shfl_xor_sync(0xffffffffu, m0, o));
        m1 = fmaxf(m1, __shfl_xor_sync(0xffffffffu, m1, o));
        m2 = fmaxf(m2, __shfl_xor_sync(0xffffffffu, m2, o));
        m3 = fmaxf(m3, __shfl_xor_sync(0xffffffffu, m3, o));
    }
    float p0 = 0.f, p1 = 0.f, p2 = 0.f, p3 = 0.f;
    if (lane < deg) {
        p0 = __expf(e0 - m0); p1 = __expf(e1 - m1);
        p2 = __expf(e2 - m2); p3 = __expf(e3 - m3);
    }
    float s0 = p0, s1 = p1, s2 = p2, s3 = p3;
    #pragma unroll
    for (int o = 16; o; o >>= 1) {
        s0 += __shfl_xor_sync(0xffffffffu, s0, o);
        s1 += __shfl_xor_sync(0xffffffffu, s1, o);
        s2 += __shfl_xor_sync(0xffffffffu, s2, o);
        s3 += __shfl_xor_sync(0xffffffffu, s3, o);
    }
    r.w0 = p0 * (1.f / (s0 + 1e-16f));
    r.w1 = p1 * (1.f / (s1 + 1e-16f));
    r.w2 = p2 * (1.f / (s2 + 1e-16f));
    r.w3 = p3 * (1.f / (s3 + 1e-16f));
    return r;
}

// Slow-path context (deg > 32; ~3 nodes)
struct SoftCtx { float m0, m1, m2, m3, i0, i1, i2, i3; float4 adv; };

__device__ __forceinline__ SoftCtx softmax_ctx(int rs, int re, int n, int lane) {
    SoftCtx c;
    c.adv = *(const float4*)(g_ad + 4 * n);
    float m0 = -1e30f, m1 = -1e30f, m2 = -1e30f, m3 = -1e30f;
    for (int idx = rs + lane; idx < re; idx += 32) {
        int s = g_csrc[idx];
        float4 a = __ldg((const float4*)(g_as + 4 * s));
        m0 = fmaxf(m0, lrelu(a.x + c.adv.x));
        m1 = fmaxf(m1, lrelu(a.y + c.adv.y));
        m2 = fmaxf(m2, lrelu(a.z + c.adv.z));
        m3 = fmaxf(m3, lrelu(a.w + c.adv.w));
    }
    #pragma unroll
    for (int o = 16; o; o >>= 1) {
        m0 = fmaxf(m0, __shfl_xor_sync(0xffffffffu, m0, o));
        m1 = fmaxf(m1, __shfl_xor_sync(0xffffffffu, m1, o));
        m2 = fmaxf(m2, __shfl_xor_sync(0xffffffffu, m2, o));
        m3 = fmaxf(m3, __shfl_xor_sync(0xffffffffu, m3, o));
    }
    float s0 = 0.f, s1 = 0.f, s2 = 0.f, s3 = 0.f;
    for (int idx = rs + lane; idx < re; idx += 32) {
        int s = g_csrc[idx];
        float4 a = __ldg((const float4*)(g_as + 4 * s));
        s0 += __expf(lrelu(a.x + c.adv.x) - m0);
        s1 += __expf(lrelu(a.y + c.adv.y) - m1);
        s2 += __expf(lrelu(a.z + c.adv.z) - m2);
        s3 += __expf(lrelu(a.w + c.adv.w) - m3);
    }
    #pragma unroll
    for (int o = 16; o; o >>= 1) {
        s0 += __shfl_xor_sync(0xffffffffu, s0, o);
        s1 += __shfl_xor_sync(0xffffffffu, s1, o);
        s2 += __shfl_xor_sync(0xffffffffu, s2, o);
        s3 += __shfl_xor_sync(0xffffffffu, s3, o);
    }
    c.m0 = m0; c.m1 = m1; c.m2 = m2; c.m3 = m3;
    c.i0 = 1.f / (s0 + 1e-16f); c.i1 = 1.f / (s1 + 1e-16f);
    c.i2 = 1.f / (s2 + 1e-16f); c.i3 = 1.f / (s3 + 1e-16f);
    return c;
}

// ---------------------------------------------------------------------------
// Concat aggregation (layers 0/1): persistent warps + fused BN stats.
// Bias omitted: a per-column constant cancels exactly under BatchNorm.
// ---------------------------------------------------------------------------
__global__ __launch_bounds__(256)
void aggregate_kernel(const float* __restrict__ xp, float* __restrict__ ob) {
    const int lane = threadIdx.x & 31, w = threadIdx.x >> 5;
    const int gwarp = blockIdx.x * 8 + w;
    const int nwarps = gridDim.x * 8;
    float bs[4] = {0.f, 0.f, 0.f, 0.f}, bq[4] = {0.f, 0.f, 0.f, 0.f};

    for (int n = gwarp; n < NN; n += nwarps) {
        const int rs = g_rowptr[n], re = g_rowptr[n + 1];
        const int deg = re - rs;
        float acc0 = 0.f, acc1 = 0.f, acc2 = 0.f, acc3 = 0.f;

        if (deg <= 32) {
            EdgeW ew = edge_weights_fast(rs, deg, n, lane);
            for (int j = 0; j < deg; j++) {
                int sj   = __shfl_sync(0xffffffffu, ew.s,  j);
                float b0 = __shfl_sync(0xffffffffu, ew.w0, j);
                float b1 = __shfl_sync(0xffffffffu, ew.w1, j);
                float b2 = __shfl_sync(0xffffffffu, ew.w2, j);
                float b3 = __shfl_sync(0xffffffffu, ew.w3, j);
                float ww = (lane < 16) ? (lane < 8 ? b0 : b1) : (lane < 24 ? b2 : b3);
                float4 v = __ldg((const float4*)(xp + (size_t)sj * 128 + lane * 4));
                acc0 += ww * v.x; acc1 += ww * v.y; acc2 += ww * v.z; acc3 += ww * v.w;
            }
        } else {
            SoftCtx cx = softmax_ctx(rs, re, n, lane);
            for (int idx = rs; idx < re; idx += 32) {
                int myi = idx + lane;
                int s = 0;
                float w0 = 0.f, w1 = 0.f, w2 = 0.f, w3 = 0.f;
                if (myi < re) {
                    s = g_csrc[myi];
                    float4 a = __ldg((const float4*)(g_as + 4 * s));
                    w0 = __expf(lrelu(a.x + cx.adv.x) - cx.m0) * cx.i0;
                    w1 = __expf(lrelu(a.y + cx.adv.y) - cx.m1) * cx.i1;
                    w2 = __expf(lrelu(a.z + cx.adv.z) - cx.m2) * cx.i2;
                    w3 = __expf(lrelu(a.w + cx.adv.w) - cx.m3) * cx.i3;
                }
                int cnt = min(32, re - idx);
                for (int j = 0; j < cnt; j++) {
                    int sj   = __shfl_sync(0xffffffffu, s,  j);
                    float b0 = __shfl_sync(0xffffffffu, w0, j);
                    float b1 = __shfl_sync(0xffffffffu, w1, j);
                    float b2 = __shfl_sync(0xffffffffu, w2, j);
                    float b3 = __shfl_sync(0xffffffffu, w3, j);
                    float ww = (lane < 16) ? (lane < 8 ? b0 : b1) : (lane < 24 ? b2 : b3);
                    float4 v = __ldg((const float4*)(xp + (size_t)sj * 128 + lane * 4));
                    acc0 += ww * v.x; acc1 += ww * v.y; acc2 += ww * v.z; acc3 += ww * v.w;
                }
            }
        }
        float* dst = ob + (size_t)n * 128 + lane * 4;
        dst[0] = acc0; dst[1] = acc1; dst[2] = acc2; dst[3] = acc3;
        bs[0] += acc0; bq[0] += acc0 * acc0;
        bs[1] += acc1; bq[1] += acc1 * acc1;
        bs[2] += acc2; bq[2] += acc2 * acc2;
        bs[3] += acc3; bq[3] += acc3 * acc3;
    }

    __shared__ float ssum[8][128];
    __shared__ float ssq[8][128];
    #pragma unroll
    for (int k = 0; k < 4; k++) { ssum[w][lane * 4 + k] = bs[k]; ssq[w][lane * 4 + k] = bq[k]; }
    __syncthreads();
    if (threadIdx.x < 128) {
        float s = 0.f, q = 0.f;
        #pragma unroll
        for (int j = 0; j < 8; j++) { s += ssum[j][threadIdx.x]; q += ssq[j][threadIdx.x]; }
        atomicAdd(&g_bnsum[threadIdx.x], s);
        atomicAdd(&g_bnsq[threadIdx.x], q);
    }
}

// ---------------------------------------------------------------------------
// Layer-2 aggregation in h-space: agg[n, h*128+c] = sum_e alpha[e,h] * h[src, c]
// ---------------------------------------------------------------------------
__global__ __launch_bounds__(256)
void aggregate2_kernel(const float* __restrict__ hb, float* __restrict__ agg) {
    int n = (blockIdx.x * blockDim.x + threadIdx.x) >> 5;
    int lane = threadIdx.x & 31;
    if (n >= NN) return;
    const int rs = g_rowptr[n], re = g_rowptr[n + 1];
    const int deg = re - rs;

    float acc[4][4];
    #pragma unroll
    for (int h = 0; h < 4; h++)
        #pragma unroll
        for (int k = 0; k < 4; k++) acc[h][k] = 0.f;

    if (deg <= 32) {
        EdgeW ew = edge_weights_fast(rs, deg, n, lane);
        for (int j = 0; j < deg; j++) {
            int sj   = __shfl_sync(0xffffffffu, ew.s,  j);
            float b0 = __shfl_sync(0xffffffffu, ew.w0, j);
            float b1 = __shfl_sync(0xffffffffu, ew.w1, j);
            float b2 = __shfl_sync(0xffffffffu, ew.w2, j);
            float b3 = __shfl_sync(0xffffffffu, ew.w3, j);
            float4 v = __ldg((const float4*)(hb + (size_t)sj * 128 + lane * 4));
            acc[0][0] += b0 * v.x; acc[0][1] += b0 * v.y; acc[0][2] += b0 * v.z; acc[0][3] += b0 * v.w;
            acc[1][0] += b1 * v.x; acc[1][1] += b1 * v.y; acc[1][2] += b1 * v.z; acc[1][3] += b1 * v.w;
            acc[2][0] += b2 * v.x; acc[2][1] += b2 * v.y; acc[2][2] += b2 * v.z; acc[2][3] += b2 * v.w;
            acc[3][0] += b3 * v.x; acc[3][1] += b3 * v.y; acc[3][2] += b3 * v.z; acc[3][3] += b3 * v.w;
        }
    } else {
        SoftCtx cx = softmax_ctx(rs, re, n, lane);
        for (int idx = rs; idx < re; idx += 32) {
            int myi = idx + lane;
            int s = 0;
            float w0 = 0.f, w1 = 0.f, w2 = 0.f, w3 = 0.f;
            if (myi < re) {
                s = g_csrc[myi];
                float4 a = __ldg((const float4*)(g_as + 4 * s));
                w0 = __expf(lrelu(a.x + cx.adv.x) - cx.m0) * cx.i0;
                w1 = __expf(lrelu(a.y + cx.adv.y) - cx.m1) * cx.i1;
                w2 = __expf(lrelu(a.z + cx.adv.z) - cx.m2) * cx.i2;
                w3 = __expf(lrelu(a.w + cx.adv.w) - cx.m3) * cx.i3;
            }
            int cnt = min(32, re - idx);
            for (int j = 0; j < cnt; j++) {
                int sj   = __shfl_sync(0xffffffffu, s,  j);
                float b0 = __shfl_sync(0xffffffffu, w0, j);
                float b1 = __shfl_sync(0xffffffffu, w1, j);
                float b2 = __shfl_sync(0xffffffffu, w2, j);
                float b3 = __shfl_sync(0xffffffffu, w3, j);
                float4 v = __ldg((const float4*)(hb + (size_t)sj * 128 + lane * 4));
                acc[0][0] += b0 * v.x; acc[0][1] += b0 * v.y; acc[0][2] += b0 * v.z; acc[0][3] += b0 * v.w;
                acc[1][0] += b1 * v.x; acc[1][1] += b1 * v.y; acc[1][2] += b1 * v.z; acc[1][3] += b1 * v.w;
                acc[2][0] += b2 * v.x; acc[2][1] += b2 * v.y; acc[2][2] += b2 * v.z; acc[2][3] += b2 * v.w;
                acc[3][0] += b3 * v.x; acc[3][1] += b3 * v.y; acc[3][2] += b3 * v.z; acc[3][3] += b3 * v.w;
            }
        }
    }
    #pragma unroll
    for (int h = 0; h < 4; h++)
        *(float4*)(agg + (size_t)n * 512 + h * 128 + lane * 4) = *(float4*)acc[h];
}

// ---------------------------------------------------------------------------
// BatchNorm
// ---------------------------------------------------------------------------
__global__ void bn_zero_kernel() {
    if (threadIdx.x < 128) { g_bnsum[threadIdx.x] = 0.f; g_bnsq[threadIdx.x] = 0.f; }
}

template <bool ELU>
__global__ __launch_bounds__(256)
void bn_apply_kernel(const float* __restrict__ in, const float* __restrict__ gamma,
                     const float* __restrict__ beta, float* __restrict__ out) {
    int i = blockIdx.x * blockDim.x + threadIdx.x;
    if (i >= NN * 128) return;
    int col = i & 127;
    const float invN = 1.f / (float)NN;
    float mu  = g_bnsum[col] * invN;
    float var = g_bnsq[col] * invN - mu * mu;
    float sc  = gamma[col] * rsqrtf(var + 1e-5f);
    float y   = (in[i] - mu) * sc + beta[col];
    if (ELU) y = (y > 0.f) ? y : expm1f(y);
    out[i] = y;
}

// ---------------------------------------------------------------------------
// Launch
// ---------------------------------------------------------------------------
extern "C" void kernel_launch(void* const* d_in, const int* in_sizes, int n_in,
                              void* d_out, int out_size) {
    const float* x   = (const float*)d_in[0];
    const void*  ei  = d_in[1];
    const float* W0  = (const float*)d_in[2];
    const float* as0 = (const float*)d_in[3];
    const float* ad0 = (const float*)d_in[4];
    const float* g0  = (const float*)d_in[6];
    const float* be0 = (const float*)d_in[7];
    const float* W1  = (const float*)d_in[8];
    const float* as1 = (const float*)d_in[9];
    const float* ad1 = (const float*)d_in[10];
    const float* g1  = (const float*)d_in[12];
    const float* be1 = (const float*)d_in[13];
    const float* W2  = (const float*)d_in[14];
    const float* as2 = (const float*)d_in[15];
    const float* ad2 = (const float*)d_in[16];
    const float* g2  = (const float*)d_in[18];
    const float* be2 = (const float*)d_in[19];
    float* out = (float*)d_out;

    float* xp; cudaGetSymbolAddress((void**)&xp, g_xp);
    float* hb; cudaGetSymbolAddress((void**)&hb, g_h);
    float* ob; cudaGetSymbolAddress((void**)&ob, g_ob);
    float* w2r; cudaGetSymbolAddress((void**)&w2r, g_w2r);

    const int nb_n  = (NN + 255) / 256;
    const int nb_e  = (EP + 255) / 256;
    const int nb_n8 = (NN + 7) / 8;           // warp-per-node kernels
    const int nb_el = (NN * 128 + 255) / 256;
    const dim3 gemm((NN + 63) / 64, 1);       // 64-row tiles: 782 CTAs

    // Launch index 3 (profiled) = L0 SGEMM: independent of the CSR build.
    detect_kernel<<<1, 64>>>(ei);
    zero_deg_kernel<<<nb_n, 256>>>();
    decode_kernel<<<nb_e, 256>>>(ei);
    sgemm_kernel<128, 1><<<gemm, 256>>>(x, W0, xp, NN, 1.f, as0, ad0);   // + att dots

    // CSR build
    block_sum_kernel<<<NB, 256>>>();
    scan_bsum_kernel<<<1, 256>>>();
    scan_fill_kernel<<<NB, 256>>>();
    scatter_kernel<<<nb_e, 256>>>();

    // ---- Layer 0 rest ----
    bn_zero_kernel<<<1, 128>>>();
    aggregate_kernel<<<1480, 256>>>(xp, ob);
    bn_apply_kernel<true><<<nb_el, 256>>>(ob, g0, be0, hb);

    // ---- Layer 1 ----
    sgemm_kernel<128, 1><<<gemm, 256>>>(hb, W1, xp, NN, 1.f, as1, ad1);  // + att dots
    bn_zero_kernel<<<1, 128>>>();
    aggregate_kernel<<<1480, 256>>>(xp, ob);
    bn_apply_kernel<true><<<nb_el, 256>>>(ob, g1, be1, hb);

    // ---- Layer 2: aggregate in h-space, then W2 GEMM (heads averaged) ----
    prep_u_kernel<<<2, 256>>>(W2, as2, ad2);
    repack_w2_kernel<<<256, 256>>>(W2);
    att2_kernel<<<nb_n8, 256>>>(hb);
    aggregate2_kernel<<<nb_n8, 256>>>(hb, xp);          // xp <- [N,512] agg
    bn_zero_kernel<<<1, 128>>>();
    sgemm_kernel<512, 2><<<gemm, 256>>>(xp, w2r, ob, NN, 0.25f, nullptr, nullptr); // + BN stats
    bn_apply_kernel<false><<<nb_el, 256>>>(ob, g2, be2, out);

    (void)in_sizes; (void)n_in; (void)out_size;
}

// round 15
// speedup vs baseline: 1.6731x; 1.0819x over previous
#include <cuda_runtime.h>
#include <cuda_bf16.h>
#include <cstdint>

// Problem constants
#define NN     50000
#define EE     800000
#define EP     (EE + NN)      // edges + self loops = 850000
#define HEADS  4
#define NB     ((NN + 255) / 256)   // 196 scan blocks

// ---------------------------------------------------------------------------
// Scratch (static device globals; no runtime allocation)
// ---------------------------------------------------------------------------
__device__ __align__(16) float g_xp[(size_t)NN * 512];   // GEMM out / L2 agg buffer
__device__ __align__(16) float g_h [(size_t)NN * 128];   // layer activations
__device__ __align__(16) float g_ob[(size_t)NN * 128];   // pre-BN buffer
__device__ __align__(16) float g_as[NN * 4];             // a_src per (node, head)
__device__ __align__(16) float g_ad[NN * 4];             // a_dst per (node, head)
__device__ __align__(16) float g_w2r[512 * 128];         // repacked W2: [h*128+c][o]
__device__ __align__(16) float g_us[512];                // u_src[h*128+c]
__device__ __align__(16) float g_ud[512];                // u_dst[h*128+c]
__device__ int g_rowptr[NN + 1];
__device__ int g_cursor[NN];
__device__ int g_deg[NN];
__device__ int g_csrc[EP];
__device__ int g_src[EP];
__device__ int g_dst[EP];
__device__ int g_bsum[256];
__device__ int g_boff[256];
__device__ int g_is64;
__device__ float g_bnsum[128];
__device__ float g_bnsq[128];

__device__ __forceinline__ float lrelu(float x) { return x > 0.f ? x : 0.2f * x; }

// ---------------------------------------------------------------------------
// Edge-index dtype detection (JAX may emit int32 despite int64 in reference)
// ---------------------------------------------------------------------------
__global__ void detect_kernel(const void* ei) {
    __shared__ int ok;
    if (threadIdx.x == 0) ok = 1;
    __syncthreads();
    const long long* p = (const long long*)ei;   // 512B read: safe either way
    long long v = p[threadIdx.x];
    if (v < 0 || v >= NN) ok = 0;
    __syncthreads();
    if (threadIdx.x == 0) g_is64 = ok;
}

__global__ void zero_deg_kernel() {
    int i = blockIdx.x * blockDim.x + threadIdx.x;
    if (i < NN) g_deg[i] = 0;
}

// decode edges (+self loops) and build degree histogram in one pass
__global__ void decode_kernel(const void* ei) {
    int i = blockIdx.x * blockDim.x + threadIdx.x;
    if (i >= EP) return;
    int src, dst;
    if (i >= EE) {
        src = i - EE; dst = i - EE;
    } else if (g_is64) {
        const long long* p = (const long long*)ei;
        src = (int)p[i]; dst = (int)p[EE + i];
    } else {
        const int* p = (const int*)ei;
        src = p[i]; dst = p[EE + i];
    }
    g_src[i] = src; g_dst[i] = dst;
    atomicAdd(&g_deg[dst], 1);
}

// ---------------------------------------------------------------------------
// Hierarchical exclusive scan of g_deg (3 fully-parallel kernels)
// ---------------------------------------------------------------------------
__global__ __launch_bounds__(256) void block_sum_kernel() {
    int t = threadIdx.x, lane = t & 31, w = t >> 5;
    int idx = blockIdx.x * 256 + t;
    int v = (idx < NN) ? g_deg[idx] : 0;
    #pragma unroll
    for (int o = 16; o; o >>= 1) v += __shfl_xor_sync(0xffffffffu, v, o);
    __shared__ int wt[8];
    if (lane == 0) wt[w] = v;
    __syncthreads();
    if (t == 0) {
        int s = 0;
        #pragma unroll
        for (int j = 0; j < 8; j++) s += wt[j];
        g_bsum[blockIdx.x] = s;
    }
}

__global__ __launch_bounds__(256) void scan_bsum_kernel() {
    int t = threadIdx.x, lane = t & 31, w = t >> 5;
    int v = (t < NB) ? g_bsum[t] : 0;
    int incl = v;
    #pragma unroll
    for (int o = 1; o < 32; o <<= 1) {
        int u = __shfl_up_sync(0xffffffffu, incl, o);
        if (lane >= o) incl += u;
    }
    __shared__ int wt[8];
    if (lane == 31) wt[w] = incl;
    __syncthreads();
    if (w == 0 && lane < 8) {
        int x = wt[lane];
        #pragma unroll
        for (int o = 1; o < 8; o <<= 1) {
            int u = __shfl_up_sync(0xffu, x, o);
            if (lane >= o) x += u;
        }
        wt[lane] = x;
    }
    __syncthreads();
    int off = (w ? wt[w - 1] : 0);
    if (t < NB) g_boff[t] = off + incl - v;   // exclusive
}

__global__ __launch_bounds__(256) void scan_fill_kernel() {
    int t = threadIdx.x, lane = t & 31, w = t >> 5;
    int idx = blockIdx.x * 256 + t;
    int v = (idx < NN) ? g_deg[idx] : 0;
    int incl = v;
    #pragma unroll
    for (int o = 1; o < 32; o <<= 1) {
        int u = __shfl_up_sync(0xffffffffu, incl, o);
        if (lane >= o) incl += u;
    }
    __shared__ int wt[8];
    if (lane == 31) wt[w] = incl;
    __syncthreads();
    if (w == 0 && lane < 8) {
        int x = wt[lane];
        #pragma unroll
        for (int o = 1; o < 8; o <<= 1) {
            int u = __shfl_up_sync(0xffu, x, o);
            if (lane >= o) x += u;
        }
        wt[lane] = x;
    }
    __syncthreads();
    int ex = g_boff[blockIdx.x] + (w ? wt[w - 1] : 0) + incl - v;
    if (idx < NN) { g_rowptr[idx] = ex; g_cursor[idx] = ex; }
    if (idx == NN - 1) g_rowptr[NN] = ex + v;
}

__global__ void scatter_kernel() {
    int i = blockIdx.x * blockDim.x + threadIdx.x;
    if (i >= EP) return;
    int pos = atomicAdd(&g_cursor[g_dst[i]], 1);
    g_csrc[pos] = g_src[i];
}

// ---------------------------------------------------------------------------
// SGEMM: Y[M,128] = scale * X[M,KD] @ W[KD,128]. 64x128 tile, 8x4/thread,
// row-paired f32x2 accumulators (~80 regs, 3 CTAs/SM).
// MODE 1: fused attention-dot epilogue. MODE 2: fused BN-stats epilogue.
// BNIN: apply BatchNorm+ELU to A during the tile load (stats from
// g_bnsum/g_bnsq; per-column scale/offset cached in smem).
// ---------------------------------------------------------------------------
#define AS_ROW 68

__device__ __forceinline__ float bn_elu_v(float v, float sc, float off) {
    float y = v * sc + off;
    return y > 0.f ? y : expm1f(y);
}

template <int KD, int MODE, bool BNIN>
__global__ __launch_bounds__(256, 3)
void sgemm_kernel(const float* __restrict__ X, const float* __restrict__ W,
                  float* __restrict__ Y, int M, float scale,
                  const float* __restrict__ asw, const float* __restrict__ adw,
                  const float* __restrict__ gamma, const float* __restrict__ beta) {
    __shared__ __align__(16) float As[2][16][AS_ROW];
    __shared__ __align__(16) float Bs[2][16][128];
    __shared__ __align__(16) float s_sc[128], s_off[128];
    const int bm = blockIdx.x * 64;
    const int tid = threadIdx.x;
    const int lane = tid & 31, w = tid >> 5;
    const int r2 = lane >> 3, c2 = lane & 7;
    const int wb = w & 1, cb = w >> 1;
    const int m0 = wb * 32 + r2 * 8;
    const int n0 = cb * 32 + c2 * 4;
    const int KT = KD / 16;

    if (BNIN) {
        if (tid < 128) {
            const float invN = 1.f / (float)NN;
            float mu  = g_bnsum[tid] * invN;
            float var = g_bnsq[tid] * invN - mu * mu;
            float sc  = gamma[tid] * rsqrtf(var + 1e-5f);
            s_sc[tid]  = sc;
            s_off[tid] = beta[tid] - mu * sc;
        }
        __syncthreads();
    }

    unsigned long long acc[4][4];
    #pragma unroll
    for (int p = 0; p < 4; p++)
        #pragma unroll
        for (int c = 0; c < 4; c++) acc[p][c] = 0ull;

    const int ar = tid >> 2, ac = (tid & 3) * 4;
    const int br = tid >> 5, bc = (tid & 31) * 4;

    const uint32_t abase = (uint32_t)__cvta_generic_to_shared(&As[0][0][0]) + m0 * 4u;

    float4 ra, rb[2];
    {
        int gr = bm + ar;
        ra = make_float4(0.f, 0.f, 0.f, 0.f);
        if (gr < M) ra = *(const float4*)(X + (size_t)gr * KD + ac);
        if (BNIN) {
            ra.x = bn_elu_v(ra.x, s_sc[ac + 0], s_off[ac + 0]);
            ra.y = bn_elu_v(ra.y, s_sc[ac + 1], s_off[ac + 1]);
            ra.z = bn_elu_v(ra.z, s_sc[ac + 2], s_off[ac + 2]);
            ra.w = bn_elu_v(ra.w, s_sc[ac + 3], s_off[ac + 3]);
        }
        rb[0] = *(const float4*)(W + (size_t)br * 128 + bc);
        rb[1] = *(const float4*)(W + (size_t)(br + 8) * 128 + bc);
    }
    As[0][ac + 0][ar] = ra.x; As[0][ac + 1][ar] = ra.y;
    As[0][ac + 2][ar] = ra.z; As[0][ac + 3][ar] = ra.w;
    *(float4*)&Bs[0][br][bc]     = rb[0];
    *(float4*)&Bs[0][br + 8][bc] = rb[1];
    __syncthreads();

    for (int kt = 0; kt < KT; kt++) {
        const int cur = kt & 1;
        const bool has_next = (kt + 1 < KT);
        if (has_next) {
            const int k0 = (kt + 1) * 16;
            int gr = bm + ar;
            ra = make_float4(0.f, 0.f, 0.f, 0.f);
            if (gr < M) ra = *(const float4*)(X + (size_t)gr * KD + k0 + ac);
            if (BNIN) {
                ra.x = bn_elu_v(ra.x, s_sc[k0 + ac + 0], s_off[k0 + ac + 0]);
                ra.y = bn_elu_v(ra.y, s_sc[k0 + ac + 1], s_off[k0 + ac + 1]);
                ra.z = bn_elu_v(ra.z, s_sc[k0 + ac + 2], s_off[k0 + ac + 2]);
                ra.w = bn_elu_v(ra.w, s_sc[k0 + ac + 3], s_off[k0 + ac + 3]);
            }
            rb[0] = *(const float4*)(W + (size_t)(k0 + br) * 128 + bc);
            rb[1] = *(const float4*)(W + (size_t)(k0 + br + 8) * 128 + bc);
        }
        const uint32_t abuf = abase + (uint32_t)cur * (16 * AS_ROW * 4);
        #pragma unroll
        for (int k = 0; k < 16; k++) {
            unsigned long long ap[4];
            asm volatile("ld.shared.v2.b64 {%0, %1}, [%2];"
                         : "=l"(ap[0]), "=l"(ap[1]) : "r"(abuf + k * (AS_ROW * 4u)));
            asm volatile("ld.shared.v2.b64 {%0, %1}, [%2];"
                         : "=l"(ap[2]), "=l"(ap[3]) : "r"(abuf + k * (AS_ROW * 4u) + 16u));
            float4 b4 = *(const float4*)&Bs[cur][k][n0];
            float bv[4] = {b4.x, b4.y, b4.z, b4.w};
            #pragma unroll
            for (int c = 0; c < 4; c++) {
                unsigned long long bb;
                unsigned int bu = __float_as_uint(bv[c]);
                asm("mov.b64 %0, {%1, %1};" : "=l"(bb) : "r"(bu));
                #pragma unroll
                for (int p = 0; p < 4; p++)
                    asm("fma.rn.f32x2 %0, %1, %2, %3;"
                        : "=l"(acc[p][c]) : "l"(ap[p]), "l"(bb), "l"(acc[p][c]));
            }
        }
        if (has_next) {
            const int nxt = (kt + 1) & 1;
            As[nxt][ac + 0][ar] = ra.x; As[nxt][ac + 1][ar] = ra.y;
            As[nxt][ac + 2][ar] = ra.z; As[nxt][ac + 3][ar] = ra.w;
            *(float4*)&Bs[nxt][br][bc]     = rb[0];
            *(float4*)&Bs[nxt][br + 8][bc] = rb[1];
            __syncthreads();
        }
    }

    float avs[4], avd[4];
    if (MODE == 1) {
        *(float4*)avs = *(const float4*)(asw + cb * 32 + c2 * 4);
        *(float4*)avd = *(const float4*)(adw + cb * 32 + c2 * 4);
    }
    float bss[4], bsq[4];
    if (MODE == 2) {
        #pragma unroll
        for (int c = 0; c < 4; c++) { bss[c] = 0.f; bsq[c] = 0.f; }
    }

    #pragma unroll
    for (int p = 0; p < 4; p++) {
        #pragma unroll
        for (int h = 0; h < 2; h++) {
            int gr = bm + m0 + p * 2 + h;
            float o4[4];
            #pragma unroll
            for (int c = 0; c < 4; c++) {
                float2 f = *(float2*)&acc[p][c];
                o4[c] = (h == 0 ? f.x : f.y) * scale;
            }
            if (MODE == 1) {
                float s = 0.f, d = 0.f;
                #pragma unroll
                for (int c = 0; c < 4; c++) { s += o4[c] * avs[c]; d += o4[c] * avd[c]; }
                s += __shfl_xor_sync(0xffffffffu, s, 1);
                s += __shfl_xor_sync(0xffffffffu, s, 2);
                s += __shfl_xor_sync(0xffffffffu, s, 4);
                d += __shfl_xor_sync(0xffffffffu, d, 1);
                d += __shfl_xor_sync(0xffffffffu, d, 2);
                d += __shfl_xor_sync(0xffffffffu, d, 4);
                if (c2 == 0 && gr < M) {
                    g_as[gr * 4 + cb] = s;
                    g_ad[gr * 4 + cb] = d;
                }
            }
            if (gr < M) {
                if (MODE == 2) {
                    #pragma unroll
                    for (int c = 0; c < 4; c++) { bss[c] += o4[c]; bsq[c] += o4[c] * o4[c]; }
                }
                *(float4*)(Y + (size_t)gr * 128 + n0) = *(float4*)o4;
            }
        }
    }

    if (MODE == 2) {
        __syncthreads();
        float* ssum = &As[0][0][0];
        float* ssq  = &As[0][0][0] + 1024;
        const int idx8 = wb * 4 + r2;
        *(float4*)&ssum[idx8 * 128 + n0] = *(float4*)bss;
        *(float4*)&ssq [idx8 * 128 + n0] = *(float4*)bsq;
        __syncthreads();
        if (tid < 128) {
            float s = 0.f, q = 0.f;
            #pragma unroll
            for (int t = 0; t < 8; t++) { s += ssum[t * 128 + tid]; q += ssq[t * 128 + tid]; }
            atomicAdd(&g_bnsum[tid], s);
            atomicAdd(&g_bnsq[tid], q);
        }
    }
}

// ---------------------------------------------------------------------------
// Layer-2 attention precompute:  u_s[h*128+c] = sum_j W2[c, h*128+j]*as2[h,j]
// ---------------------------------------------------------------------------
__global__ void prep_u_kernel(const float* __restrict__ W2,
                              const float* __restrict__ as2,
                              const float* __restrict__ ad2) {
    int t = blockIdx.x * blockDim.x + threadIdx.x;
    if (t >= 512) return;
    int h = t >> 7, c = t & 127;
    const float* wrow = W2 + (size_t)c * 512 + h * 128;
    const float* av = as2 + h * 128;
    const float* dv = ad2 + h * 128;
    float s = 0.f, d = 0.f;
    for (int j = 0; j < 128; j++) { float w = wrow[j]; s += w * av[j]; d += w * dv[j]; }
    g_us[t] = s; g_ud[t] = d;
}

// Repack W2 [128, 512] -> g_w2r [512, 128]: g_w2r[h*128+c][o] = W2[c][h*128+o]
__global__ void repack_w2_kernel(const float* __restrict__ W2) {
    int i = blockIdx.x * blockDim.x + threadIdx.x;
    if (i >= 512 * 128) return;
    int k = i >> 7, o = i & 127, h = k >> 7, c = k & 127;
    g_w2r[i] = W2[(size_t)c * 512 + h * 128 + o];
}

// ---------------------------------------------------------------------------
// Fused layer-1 BN+ELU apply + layer-2 attention dots. One warp per node:
// single read of ob produces hb AND a_s/a_d (replaces bn_apply + att2).
// ---------------------------------------------------------------------------
__global__ __launch_bounds__(256)
void bn_apply_att_kernel(const float* __restrict__ ob, const float* __restrict__ gamma,
                         const float* __restrict__ beta, float* __restrict__ hb) {
    int gw = (blockIdx.x * blockDim.x + threadIdx.x) >> 5;
    int lane = threadIdx.x & 31;
    if (gw >= NN) return;
    const int c0 = lane * 4;
    const float invN = 1.f / (float)NN;
    float4 v  = *(const float4*)(ob + (size_t)gw * 128 + c0);
    float4 bs = *(const float4*)(g_bnsum + c0);
    float4 bq = *(const float4*)(g_bnsq + c0);
    float4 gm = *(const float4*)(gamma + c0);
    float4 bt = *(const float4*)(beta + c0);
    float y[4];
    {
        float mu, var, sc;
        mu = bs.x * invN; var = bq.x * invN - mu * mu; sc = gm.x * rsqrtf(var + 1e-5f);
        y[0] = (v.x - mu) * sc + bt.x;
        mu = bs.y * invN; var = bq.y * invN - mu * mu; sc = gm.y * rsqrtf(var + 1e-5f);
        y[1] = (v.y - mu) * sc + bt.y;
        mu = bs.z * invN; var = bq.z * invN - mu * mu; sc = gm.z * rsqrtf(var + 1e-5f);
        y[2] = (v.z - mu) * sc + bt.z;
        mu = bs.w * invN; var = bq.w * invN - mu * mu; sc = gm.w * rsqrtf(var + 1e-5f);
        y[3] = (v.w - mu) * sc + bt.w;
    }
    #pragma unroll
    for (int j = 0; j < 4; j++) y[j] = y[j] > 0.f ? y[j] : expm1f(y[j]);
    *(float4*)(hb + (size_t)gw * 128 + c0) = make_float4(y[0], y[1], y[2], y[3]);

    float s[4], d[4];
    #pragma unroll
    for (int h = 0; h < 4; h++) {
        const float4 us = *(const float4*)(g_us + h * 128 + c0);
        const float4 ud = *(const float4*)(g_ud + h * 128 + c0);
        s[h] = y[0] * us.x + y[1] * us.y + y[2] * us.z + y[3] * us.w;
        d[h] = y[0] * ud.x + y[1] * ud.y + y[2] * ud.z + y[3] * ud.w;
    }
    #pragma unroll
    for (int o = 16; o; o >>= 1) {
        #pragma unroll
        for (int h = 0; h < 4; h++) {
            s[h] += __shfl_xor_sync(0xffffffffu, s[h], o);
            d[h] += __shfl_xor_sync(0xffffffffu, d[h], o);
        }
    }
    if (lane == 0) {
        #pragma unroll
        for (int h = 0; h < 4; h++) { g_as[gw * 4 + h] = s[h]; g_ad[gw * 4 + h] = d[h]; }
    }
}

// ---------------------------------------------------------------------------
// Edge weights, fast path (deg <= 32, ~all nodes: mean deg 17)
// ---------------------------------------------------------------------------
struct EdgeW { int s; float w0, w1, w2, w3; };

__device__ __forceinline__ EdgeW edge_weights_fast(int rs, int deg, int n, int lane) {
    const float4 adv = *(const float4*)(g_ad + 4 * n);
    EdgeW r; r.s = 0;
    float e0 = -1e30f, e1 = -1e30f, e2 = -1e30f, e3 = -1e30f;
    if (lane < deg) {
        r.s = g_csrc[rs + lane];
        float4 a = __ldg((const float4*)(g_as + 4 * r.s));
        e0 = lrelu(a.x + adv.x); e1 = lrelu(a.y + adv.y);
        e2 = lrelu(a.z + adv.z); e3 = lrelu(a.w + adv.w);
    }
    float m0 = e0, m1 = e1, m2 = e2, m3 = e3;
    #pragma unroll
    for (int o = 16; o; o >>= 1) {
        m0 = fmaxf(m0, __shfl_xor_sync(0xffffffffu, m0, o));
        m1 = fmaxf(m1, __shfl_xor_sync(0xffffffffu, m1, o));
        m2 = fmaxf(m2, __shfl_xor_sync(0xffffffffu, m2, o));
        m3 = fmaxf(m3, __shfl_xor_sync(0xffffffffu, m3, o));
    }
    float p0 = 0.f, p1 = 0.f, p2 = 0.f, p3 = 0.f;
    if (lane < deg) {
        p0 = __expf(e0 - m0); p1 = __expf(e1 - m1);
        p2 = __expf(e2 - m2); p3 = __expf(e3 - m3);
    }
    float s0 = p0, s1 = p1, s2 = p2, s3 = p3;
    #pragma unroll
    for (int o = 16; o; o >>= 1) {
        s0 += __shfl_xor_sync(0xffffffffu, s0, o);
        s1 += __shfl_xor_sync(0xffffffffu, s1, o);
        s2 += __shfl_xor_sync(0xffffffffu, s2, o);
        s3 += __shfl_xor_sync(0xffffffffu, s3, o);
    }
    r.w0 = p0 * (1.f / (s0 + 1e-16f));
    r.w1 = p1 * (1.f / (s1 + 1e-16f));
    r.w2 = p2 * (1.f / (s2 + 1e-16f));
    r.w3 = p3 * (1.f / (s3 + 1e-16f));
    return r;
}

// Slow-path context (deg > 32; ~3 nodes)
struct SoftCtx { float m0, m1, m2, m3, i0, i1, i2, i3; float4 adv; };

__device__ __forceinline__ SoftCtx softmax_ctx(int rs, int re, int n, int lane) {
    SoftCtx c;
    c.adv = *(const float4*)(g_ad + 4 * n);
    float m0 = -1e30f, m1 = -1e30f, m2 = -1e30f, m3 = -1e30f;
    for (int idx = rs + lane; idx < re; idx += 32) {
        int s = g_csrc[idx];
        float4 a = __ldg((const float4*)(g_as + 4 * s));
        m0 = fmaxf(m0, lrelu(a.x + c.adv.x));
        m1 = fmaxf(m1, lrelu(a.y + c.adv.y));
        m2 = fmaxf(m2, lrelu(a.z + c.adv.z));
        m3 = fmaxf(m3, lrelu(a.w + c.adv.w));
    }
    #pragma unroll
    for (int o = 16; o; o >>= 1) {
        m0 = fmaxf(m0, __shfl_xor_sync(0xffffffffu, m0, o));
        m1 = fmaxf(m1, __shfl_xor_sync(0xffffffffu, m1, o));
        m2 = fmaxf(m2, __shfl_xor_sync(0xffffffffu, m2, o));
        m3 = fmaxf(m3, __shfl_xor_sync(0xffffffffu, m3, o));
    }
    float s0 = 0.f, s1 = 0.f, s2 = 0.f, s3 = 0.f;
    for (int idx = rs + lane; idx < re; idx += 32) {
        int s = g_csrc[idx];
        float4 a = __ldg((const float4*)(g_as + 4 * s));
        s0 += __expf(lrelu(a.x + c.adv.x) - m0);
        s1 += __expf(lrelu(a.y + c.adv.y) - m1);
        s2 += __expf(lrelu(a.z + c.adv.z) - m2);
        s3 += __expf(lrelu(a.w + c.adv.w) - m3);
    }
    #pragma unroll
    for (int o = 16; o; o >>= 1) {
        s0 += __shfl_xor_sync(0xffffffffu, s0, o);
        s1 += __shfl_xor_sync(0xffffffffu, s1, o);
        s2 += __shfl_xor_sync(0xffffffffu, s2, o);
        s3 += __shfl_xor_sync(0xffffffffu, s3, o);
    }
    c.m0 = m0; c.m1 = m1; c.m2 = m2; c.m3 = m3;
    c.i0 = 1.f / (s0 + 1e-16f); c.i1 = 1.f / (s1 + 1e-16f);
    c.i2 = 1.f / (s2 + 1e-16f); c.i3 = 1.f / (s3 + 1e-16f);
    return c;
}

// ---------------------------------------------------------------------------
// Concat aggregation (layers 0/1): persistent warps + fused BN stats.
// Bias omitted: a per-column constant cancels exactly under BatchNorm.
// ---------------------------------------------------------------------------
__global__ __launch_bounds__(256)
void aggregate_kernel(const float* __restrict__ xp, float* __restrict__ ob) {
    const int lane = threadIdx.x & 31, w = threadIdx.x >> 5;
    const int gwarp = blockIdx.x * 8 + w;
    const int nwarps = gridDim.x * 8;
    float bs[4] = {0.f, 0.f, 0.f, 0.f}, bq[4] = {0.f, 0.f, 0.f, 0.f};

    for (int n = gwarp; n < NN; n += nwarps) {
        const int rs = g_rowptr[n], re = g_rowptr[n + 1];
        const int deg = re - rs;
        float acc0 = 0.f, acc1 = 0.f, acc2 = 0.f, acc3 = 0.f;

        if (deg <= 32) {
            EdgeW ew = edge_weights_fast(rs, deg, n, lane);
            for (int j = 0; j < deg; j++) {
                int sj   = __shfl_sync(0xffffffffu, ew.s,  j);
                float b0 = __shfl_sync(0xffffffffu, ew.w0, j);
                float b1 = __shfl_sync(0xffffffffu, ew.w1, j);
                float b2 = __shfl_sync(0xffffffffu, ew.w2, j);
                float b3 = __shfl_sync(0xffffffffu, ew.w3, j);
                float ww = (lane < 16) ? (lane < 8 ? b0 : b1) : (lane < 24 ? b2 : b3);
                float4 v = __ldg((const float4*)(xp + (size_t)sj * 128 + lane * 4));
                acc0 += ww * v.x; acc1 += ww * v.y; acc2 += ww * v.z; acc3 += ww * v.w;
            }
        } else {
            SoftCtx cx = softmax_ctx(rs, re, n, lane);
            for (int idx = rs; idx < re; idx += 32) {
                int myi = idx + lane;
                int s = 0;
                float w0 = 0.f, w1 = 0.f, w2 = 0.f, w3 = 0.f;
                if (myi < re) {
                    s = g_csrc[myi];
                    float4 a = __ldg((const float4*)(g_as + 4 * s));
                    w0 = __expf(lrelu(a.x + cx.adv.x) - cx.m0) * cx.i0;
                    w1 = __expf(lrelu(a.y + cx.adv.y) - cx.m1) * cx.i1;
                    w2 = __expf(lrelu(a.z + cx.adv.z) - cx.m2) * cx.i2;
                    w3 = __expf(lrelu(a.w + cx.adv.w) - cx.m3) * cx.i3;
                }
                int cnt = min(32, re - idx);
                for (int j = 0; j < cnt; j++) {
                    int sj   = __shfl_sync(0xffffffffu, s,  j);
                    float b0 = __shfl_sync(0xffffffffu, w0, j);
                    float b1 = __shfl_sync(0xffffffffu, w1, j);
                    float b2 = __shfl_sync(0xffffffffu, w2, j);
                    float b3 = __shfl_sync(0xffffffffu, w3, j);
                    float ww = (lane < 16) ? (lane < 8 ? b0 : b1) : (lane < 24 ? b2 : b3);
                    float4 v = __ldg((const float4*)(xp + (size_t)sj * 128 + lane * 4));
                    acc0 += ww * v.x; acc1 += ww * v.y; acc2 += ww * v.z; acc3 += ww * v.w;
                }
            }
        }
        float* dst = ob + (size_t)n * 128 + lane * 4;
        dst[0] = acc0; dst[1] = acc1; dst[2] = acc2; dst[3] = acc3;
        bs[0] += acc0; bq[0] += acc0 * acc0;
        bs[1] += acc1; bq[1] += acc1 * acc1;
        bs[2] += acc2; bq[2] += acc2 * acc2;
        bs[3] += acc3; bq[3] += acc3 * acc3;
    }

    __shared__ float ssum[8][128];
    __shared__ float ssq[8][128];
    #pragma unroll
    for (int k = 0; k < 4; k++) { ssum[w][lane * 4 + k] = bs[k]; ssq[w][lane * 4 + k] = bq[k]; }
    __syncthreads();
    if (threadIdx.x < 128) {
        float s = 0.f, q = 0.f;
        #pragma unroll
        for (int j = 0; j < 8; j++) { s += ssum[j][threadIdx.x]; q += ssq[j][threadIdx.x]; }
        atomicAdd(&g_bnsum[threadIdx.x], s);
        atomicAdd(&g_bnsq[threadIdx.x], q);
    }
}

// ---------------------------------------------------------------------------
// Layer-2 aggregation in h-space: agg[n, h*128+c] = sum_e alpha[e,h] * h[src, c]
// ---------------------------------------------------------------------------
__global__ __launch_bounds__(256)
void aggregate2_kernel(const float* __restrict__ hb, float* __restrict__ agg) {
    int n = (blockIdx.x * blockDim.x + threadIdx.x) >> 5;
    int lane = threadIdx.x & 31;
    if (n >= NN) return;
    const int rs = g_rowptr[n], re = g_rowptr[n + 1];
    const int deg = re - rs;

    float acc[4][4];
    #pragma unroll
    for (int h = 0; h < 4; h++)
        #pragma unroll
        for (int k = 0; k < 4; k++) acc[h][k] = 0.f;

    if (deg <= 32) {
        EdgeW ew = edge_weights_fast(rs, deg, n, lane);
        for (int j = 0; j < deg; j++) {
            int sj   = __shfl_sync(0xffffffffu, ew.s,  j);
            float b0 = __shfl_sync(0xffffffffu, ew.w0, j);
            float b1 = __shfl_sync(0xffffffffu, ew.w1, j);
            float b2 = __shfl_sync(0xffffffffu, ew.w2, j);
            float b3 = __shfl_sync(0xffffffffu, ew.w3, j);
            float4 v = __ldg((const float4*)(hb + (size_t)sj * 128 + lane * 4));
            acc[0][0] += b0 * v.x; acc[0][1] += b0 * v.y; acc[0][2] += b0 * v.z; acc[0][3] += b0 * v.w;
            acc[1][0] += b1 * v.x; acc[1][1] += b1 * v.y; acc[1][2] += b1 * v.z; acc[1][3] += b1 * v.w;
            acc[2][0] += b2 * v.x; acc[2][1] += b2 * v.y; acc[2][2] += b2 * v.z; acc[2][3] += b2 * v.w;
            acc[3][0] += b3 * v.x; acc[3][1] += b3 * v.y; acc[3][2] += b3 * v.z; acc[3][3] += b3 * v.w;
        }
    } else {
        SoftCtx cx = softmax_ctx(rs, re, n, lane);
        for (int idx = rs; idx < re; idx += 32) {
            int myi = idx + lane;
            int s = 0;
            float w0 = 0.f, w1 = 0.f, w2 = 0.f, w3 = 0.f;
            if (myi < re) {
                s = g_csrc[myi];
                float4 a = __ldg((const float4*)(g_as + 4 * s));
                w0 = __expf(lrelu(a.x + cx.adv.x) - cx.m0) * cx.i0;
                w1 = __expf(lrelu(a.y + cx.adv.y) - cx.m1) * cx.i1;
                w2 = __expf(lrelu(a.z + cx.adv.z) - cx.m2) * cx.i2;
                w3 = __expf(lrelu(a.w + cx.adv.w) - cx.m3) * cx.i3;
            }
            int cnt = min(32, re - idx);
            for (int j = 0; j < cnt; j++) {
                int sj   = __shfl_sync(0xffffffffu, s,  j);
                float b0 = __shfl_sync(0xffffffffu, w0, j);
                float b1 = __shfl_sync(0xffffffffu, w1, j);
                float b2 = __shfl_sync(0xffffffffu, w2, j);
                float b3 = __shfl_sync(0xffffffffu, w3, j);
                float4 v = __ldg((const float4*)(hb + (size_t)sj * 128 + lane * 4));
                acc[0][0] += b0 * v.x; acc[0][1] += b0 * v.y; acc[0][2] += b0 * v.z; acc[0][3] += b0 * v.w;
                acc[1][0] += b1 * v.x; acc[1][1] += b1 * v.y; acc[1][2] += b1 * v.z; acc[1][3] += b1 * v.w;
                acc[2][0] += b2 * v.x; acc[2][1] += b2 * v.y; acc[2][2] += b2 * v.z; acc[2][3] += b2 * v.w;
                acc[3][0] += b3 * v.x; acc[3][1] += b3 * v.y; acc[3][2] += b3 * v.z; acc[3][3] += b3 * v.w;
            }
        }
    }
    #pragma unroll
    for (int h = 0; h < 4; h++)
        *(float4*)(agg + (size_t)n * 512 + h * 128 + lane * 4) = *(float4*)acc[h];
}

// ---------------------------------------------------------------------------
// BatchNorm
// ---------------------------------------------------------------------------
__global__ void bn_zero_kernel() {
    if (threadIdx.x < 128) { g_bnsum[threadIdx.x] = 0.f; g_bnsq[threadIdx.x] = 0.f; }
}

template <bool ELU>
__global__ __launch_bounds__(256)
void bn_apply_kernel(const float* __restrict__ in, const float* __restrict__ gamma,
                     const float* __restrict__ beta, float* __restrict__ out) {
    int i = blockIdx.x * blockDim.x + threadIdx.x;
    if (i >= NN * 128) return;
    int col = i & 127;
    const float invN = 1.f / (float)NN;
    float mu  = g_bnsum[col] * invN;
    float var = g_bnsq[col] * invN - mu * mu;
    float sc  = gamma[col] * rsqrtf(var + 1e-5f);
    float y   = (in[i] - mu) * sc + beta[col];
    if (ELU) y = (y > 0.f) ? y : expm1f(y);
    out[i] = y;
}

// ---------------------------------------------------------------------------
// Launch: two-stream graph. Side stream runs L0 SGEMM + W2 prep concurrently
// with the CSR build; joined via events before the first aggregate.
// ---------------------------------------------------------------------------
extern "C" void kernel_launch(void* const* d_in, const int* in_sizes, int n_in,
                              void* d_out, int out_size) {
    const float* x   = (const float*)d_in[0];
    const void*  ei  = d_in[1];
    const float* W0  = (const float*)d_in[2];
    const float* as0 = (const float*)d_in[3];
    const float* ad0 = (const float*)d_in[4];
    const float* g0  = (const float*)d_in[6];
    const float* be0 = (const float*)d_in[7];
    const float* W1  = (const float*)d_in[8];
    const float* as1 = (const float*)d_in[9];
    const float* ad1 = (const float*)d_in[10];
    const float* g1  = (const float*)d_in[12];
    const float* be1 = (const float*)d_in[13];
    const float* W2  = (const float*)d_in[14];
    const float* as2 = (const float*)d_in[15];
    const float* ad2 = (const float*)d_in[16];
    const float* g2  = (const float*)d_in[18];
    const float* be2 = (const float*)d_in[19];
    float* out = (float*)d_out;

    float* xp; cudaGetSymbolAddress((void**)&xp, g_xp);
    float* hb; cudaGetSymbolAddress((void**)&hb, g_h);
    float* ob; cudaGetSymbolAddress((void**)&ob, g_ob);
    float* w2r; cudaGetSymbolAddress((void**)&w2r, g_w2r);

    static cudaStream_t s2 = nullptr;
    static cudaEvent_t ev0 = nullptr, ev2 = nullptr;
    if (!s2) {
        cudaStreamCreateWithFlags(&s2, cudaStreamNonBlocking);
        cudaEventCreateWithFlags(&ev0, cudaEventDisableTiming);
        cudaEventCreateWithFlags(&ev2, cudaEventDisableTiming);
    }

    const int nb_n  = (NN + 255) / 256;
    const int nb_e  = (EP + 255) / 256;
    const int nb_n8 = (NN + 7) / 8;           // warp-per-node kernels
    const int nb_el = (NN * 128 + 255) / 256;
    const dim3 gemm((NN + 63) / 64, 1);       // 64-row tiles: 782 CTAs

    // Fork: side stream (L0 SGEMM + W2 prep) runs concurrently with CSR build.
    cudaEventRecord(ev0, 0);

    detect_kernel<<<1, 64>>>(ei);
    zero_deg_kernel<<<nb_n, 256>>>();
    decode_kernel<<<nb_e, 256>>>(ei);

    cudaStreamWaitEvent(s2, ev0, 0);
    sgemm_kernel<128, 1, false><<<gemm, 256, 0, s2>>>(x, W0, xp, NN, 1.f, as0, ad0, nullptr, nullptr);
    prep_u_kernel<<<2, 256, 0, s2>>>(W2, as2, ad2);
    repack_w2_kernel<<<256, 256, 0, s2>>>(W2);
    cudaEventRecord(ev2, s2);

    block_sum_kernel<<<NB, 256>>>();
    scan_bsum_kernel<<<1, 256>>>();
    scan_fill_kernel<<<NB, 256>>>();
    scatter_kernel<<<nb_e, 256>>>();

    cudaStreamWaitEvent(0, ev2, 0);   // join before consuming xp / att dots

    // ---- Layer 0 aggregate (+BN stats) ----
    bn_zero_kernel<<<1, 128>>>();
    aggregate_kernel<<<1480, 256>>>(xp, ob);

    // ---- Layer 1: BN+ELU fused into A-load; att dots in epilogue ----
    sgemm_kernel<128, 1, true><<<gemm, 256>>>(ob, W1, xp, NN, 1.f, as1, ad1, g0, be0);
    bn_zero_kernel<<<1, 128>>>();
    aggregate_kernel<<<1480, 256>>>(xp, ob);

    // ---- Layer 2: fused BN apply + h-space att dots, aggregate, W2 GEMM ----
    bn_apply_att_kernel<<<nb_n8, 256>>>(ob, g1, be1, hb);
    aggregate2_kernel<<<nb_n8, 256>>>(hb, xp);          // xp <- [N,512] agg
    bn_zero_kernel<<<1, 128>>>();
    sgemm_kernel<512, 2, false><<<gemm, 256>>>(xp, w2r, ob, NN, 0.25f, nullptr, nullptr, nullptr, nullptr);
    bn_apply_kernel<false><<<nb_el, 256>>>(ob, g2, be2, out);

    (void)in_sizes; (void)n_in; (void)out_size;
}